// round 6
// baseline (speedup 1.0000x reference)
#include <cuda_runtime.h>
#include <cuda_fp16.h>
#include <math.h>
#include <stdint.h>

#define NN 50000
#define NE 800000
#define SA2 168            // A-tile row stride in fp16 units
#define A_BYTES 43008      // 128 * SA2 * 2 per buffer

// ---------------- scratch (static device globals; no allocation) -----------
__device__ float    g_logits[NE];
__device__ float    g_ex[NE];
__device__ float    g_denom[NN];
__device__ unsigned g_maxb[NN];
__device__ float    g_agg[NN * 64];

// fp16 fragment-packed weights (filled once per launch by prep_kernel)
__device__ unsigned g_W1e[10240];
__device__ unsigned g_W1a[10240];
__device__ unsigned g_W2e[4096];

__device__ __forceinline__ unsigned ordenc(float f) {
    unsigned u = __float_as_uint(f);
    return (u & 0x80000000u) ? ~u : (u | 0x80000000u);
}
__device__ __forceinline__ float orddec(unsigned u) {
    return __uint_as_float((u & 0x80000000u) ? (u ^ 0x80000000u) : ~u);
}
__device__ __forceinline__ unsigned pack_h2(float a, float b) {
    __half2 h = __floats2half2_rn(a, b);
    return *(unsigned*)&h;
}

__device__ __forceinline__ void mma_f16(float c[4], const unsigned a[4], uint2 b) {
    asm volatile(
        "mma.sync.aligned.m16n8k16.row.col.f32.f16.f16.f32 "
        "{%0,%1,%2,%3},{%4,%5,%6,%7},{%8,%9},{%0,%1,%2,%3};\n"
        : "+f"(c[0]), "+f"(c[1]), "+f"(c[2]), "+f"(c[3])
        : "r"(a[0]), "r"(a[1]), "r"(a[2]), "r"(a[3]), "r"(b.x), "r"(b.y));
}

// ---------------- weight prep: fp32 row-major -> fp16 fragment pairs --------
__global__ void prep_kernel(const float* __restrict__ We1,
                            const float* __restrict__ Wa1,
                            const float* __restrict__ We2) {
    int idx = blockIdx.x * blockDim.x + threadIdx.x;
    if (idx < 10240) {                      // W1-type [K=160][N=128]
        int reg = idx & 1, lane = (idx >> 1) & 31, nbt = (idx >> 6) & 15, kk = idx >> 10;
        int g = lane >> 2, t = lane & 3;
        int n = nbt * 8 + g;
        int k0 = kk * 16 + 2 * t + reg * 8;
        g_W1e[idx] = pack_h2(We1[k0 * 128 + n], We1[(k0 + 1) * 128 + n]);
        g_W1a[idx] = pack_h2(Wa1[k0 * 128 + n], Wa1[(k0 + 1) * 128 + n]);
    } else if (idx < 10240 + 4096) {        // W2 [K=128][N=64]
        int i = idx - 10240;
        int reg = i & 1, lane = (i >> 1) & 31, nbt = (i >> 6) & 7, kk = i >> 9;
        int g = lane >> 2, t = lane & 3;
        int n = nbt * 8 + g;
        int k0 = kk * 16 + 2 * t + reg * 8;
        g_W2e[i] = pack_h2(We2[k0 * 64 + n], We2[(k0 + 1) * 64 + n]);
    }
}

// ---------------- producer: gather one 128-edge tile into A buffer ----------
__device__ __forceinline__ void produce_tile(
    int tile, char* Abuf, int* sS, int* sD,
    const float* __restrict__ nf, const float* __restrict__ ef,
    const int* __restrict__ src, const int* __restrict__ dst, int E, int pt)
{
    const int e0 = tile * 128;
    {
        int e = e0 + pt;
        sS[pt] = (e < E) ? src[e] : 0;
        sD[pt] = (e < E) ? dst[e] : 0;
    }
    asm volatile("bar.sync 2, 128;" ::: "memory");
    for (int idx = pt; idx < 128 * 40; idx += 128) {
        int le = idx / 40, q = idx - le * 40;
        int ee = e0 + le;
        int es = (ee < E) ? ee : 0;
        float4 v;
        if (q < 16)      v = __ldg((const float4*)(nf + (size_t)sS[le] * 64) + q);
        else if (q < 32) v = __ldg((const float4*)(nf + (size_t)sD[le] * 64) + (q - 16));
        else             v = __ldg((const float4*)(ef + (size_t)es * 32) + (q - 32));
        uint2 o = make_uint2(pack_h2(v.x, v.y), pack_h2(v.z, v.w));
        *(uint2*)(Abuf + le * (SA2 * 2) + q * 8) = o;
    }
}

// ---------------- persistent edge kernel ------------------------------------
// 384 threads: warps 0-7 compute (warp_m = wid&3, warp_n = wid>>2), warps 8-11 produce
__global__ void __launch_bounds__(384, 1)
edge_kernel(const float* __restrict__ nf, const float* __restrict__ ef,
            const int* __restrict__ src, const int* __restrict__ dst,
            const float* __restrict__ be1, const float* __restrict__ be2,
            const float* __restrict__ ba1, const float* __restrict__ Wa2,
            const float* __restrict__ ba2,
            float* __restrict__ uh_e, int E, int ntiles)
{
    extern __shared__ __align__(16) char dyn[];
    char* Abase = dyn;                                  // [2][128][SA2] fp16
    unsigned* sW1e = (unsigned*)(dyn + 2 * A_BYTES);    // 40 KB
    unsigned* sW1a = sW1e + 10240;                      // 40 KB
    unsigned* sW2v = sW1a + 10240;                      // 16 KB
    __shared__ float sLogit[2][128];
    __shared__ int sSrc[2][128], sDst[2][128];

    const int tid = threadIdx.x;
    const bool isProd = (tid >= 256);
    const int lane = tid & 31, wid = tid >> 5;
    const int g = lane >> 2, t = lane & 3;
    const int warp_m = wid & 3, warp_n = (wid >> 2) & 1;

    // stage all weights once (resident for the whole kernel)
    for (int i = tid; i < 2560; i += 384) ((uint4*)sW1e)[i] = ((const uint4*)g_W1e)[i];
    for (int i = tid; i < 2560; i += 384) ((uint4*)sW1a)[i] = ((const uint4*)g_W1a)[i];
    for (int i = tid; i < 1024; i += 384) ((uint4*)sW2v)[i] = ((const uint4*)g_W2e)[i];

    // prologue: producers fill buffer 0 with the first tile
    if (isProd && (int)blockIdx.x < ntiles)
        produce_tile(blockIdx.x, Abase, sSrc[0], sDst[0], nf, ef, src, dst, E, tid - 256);
    __syncthreads();

    int p = 0;
    for (int tIdx = blockIdx.x; tIdx < ntiles; tIdx += gridDim.x, p ^= 1) {
        if (isProd) {
            int tn = tIdx + gridDim.x;
            if (tn < ntiles)
                produce_tile(tn, Abase + (1 - p) * A_BYTES, sSrc[1 - p], sDst[1 - p],
                             nf, ef, src, dst, E, tid - 256);
            // match compute's named barriers? no: compute uses id 1 (256 thr), producers id 2.
        } else {
            char* pA = Abase + p * A_BYTES;
            const int e0 = tIdx * 128;

            // ---- GEMM1-edge ----
            float accE[2][8][4];
#pragma unroll
            for (int mt = 0; mt < 2; mt++)
#pragma unroll
                for (int nb = 0; nb < 8; nb++)
#pragma unroll
                    for (int q = 0; q < 4; q++) accE[mt][nb][q] = 0.f;
            {
                unsigned a[2][4];
                const uint2* sWu = (const uint2*)sW1e;
#pragma unroll
                for (int kk = 0; kk < 10; kk++) {
#pragma unroll
                    for (int mt = 0; mt < 2; mt++) {
                        int row = warp_m * 32 + mt * 16 + g;
                        const char* base = pA + row * (SA2 * 2) + kk * 32 + 4 * t;
                        a[mt][0] = *(const unsigned*)(base);
                        a[mt][1] = *(const unsigned*)(base + 8 * (SA2 * 2));
                        a[mt][2] = *(const unsigned*)(base + 16);
                        a[mt][3] = *(const unsigned*)(base + 8 * (SA2 * 2) + 16);
                    }
#pragma unroll
                    for (int nb = 0; nb < 8; nb++) {
                        uint2 b = sWu[(kk * 16 + warp_n * 8 + nb) * 32 + lane];
                        mma_f16(accE[0][nb], a[0], b);
                        mma_f16(accE[1][nb], a[1], b);
                    }
                }
            }
            // pack edge-hidden with bias+relu -> 32 regs (frees 32)
            unsigned hpk[2][8][2];
#pragma unroll
            for (int mt = 0; mt < 2; mt++)
#pragma unroll
                for (int nb = 0; nb < 8; nb++) {
                    int c = warp_n * 64 + nb * 8 + 2 * t;
                    float b0 = __ldg(be1 + c), b1 = __ldg(be1 + c + 1);
                    hpk[mt][nb][0] = pack_h2(fmaxf(accE[mt][nb][0] + b0, 0.f),
                                             fmaxf(accE[mt][nb][1] + b1, 0.f));
                    hpk[mt][nb][1] = pack_h2(fmaxf(accE[mt][nb][2] + b0, 0.f),
                                             fmaxf(accE[mt][nb][3] + b1, 0.f));
                }

            // ---- GEMM1-attn ----
            float accA[2][8][4];
#pragma unroll
            for (int mt = 0; mt < 2; mt++)
#pragma unroll
                for (int nb = 0; nb < 8; nb++)
#pragma unroll
                    for (int q = 0; q < 4; q++) accA[mt][nb][q] = 0.f;
            {
                unsigned a[2][4];
                const uint2* sWu = (const uint2*)sW1a;
#pragma unroll
                for (int kk = 0; kk < 10; kk++) {
#pragma unroll
                    for (int mt = 0; mt < 2; mt++) {
                        int row = warp_m * 32 + mt * 16 + g;
                        const char* base = pA + row * (SA2 * 2) + kk * 32 + 4 * t;
                        a[mt][0] = *(const unsigned*)(base);
                        a[mt][1] = *(const unsigned*)(base + 8 * (SA2 * 2));
                        a[mt][2] = *(const unsigned*)(base + 16);
                        a[mt][3] = *(const unsigned*)(base + 8 * (SA2 * 2) + 16);
                    }
#pragma unroll
                    for (int nb = 0; nb < 8; nb++) {
                        uint2 b = sWu[(kk * 16 + warp_n * 8 + nb) * 32 + lane];
                        mma_f16(accA[0][nb], a[0], b);
                        mma_f16(accA[1][nb], a[1], b);
                    }
                }
            }

            // attention epilogue: partial logit per lane-group, reduce over t
            {
                float s00 = 0.f, s01 = 0.f, s10 = 0.f, s11 = 0.f;
#pragma unroll
                for (int nb = 0; nb < 8; nb++) {
                    int c = warp_n * 64 + nb * 8 + 2 * t;
                    float b0 = __ldg(ba1 + c), b1 = __ldg(ba1 + c + 1);
                    float w0 = __ldg(Wa2 + c), w1 = __ldg(Wa2 + c + 1);
                    s00 += fmaxf(accA[0][nb][0] + b0, 0.f) * w0 + fmaxf(accA[0][nb][1] + b1, 0.f) * w1;
                    s01 += fmaxf(accA[0][nb][2] + b0, 0.f) * w0 + fmaxf(accA[0][nb][3] + b1, 0.f) * w1;
                    s10 += fmaxf(accA[1][nb][0] + b0, 0.f) * w0 + fmaxf(accA[1][nb][1] + b1, 0.f) * w1;
                    s11 += fmaxf(accA[1][nb][2] + b0, 0.f) * w0 + fmaxf(accA[1][nb][3] + b1, 0.f) * w1;
                }
#pragma unroll
                for (int off = 1; off <= 2; off <<= 1) {
                    s00 += __shfl_xor_sync(0xffffffffu, s00, off);
                    s01 += __shfl_xor_sync(0xffffffffu, s01, off);
                    s10 += __shfl_xor_sync(0xffffffffu, s10, off);
                    s11 += __shfl_xor_sync(0xffffffffu, s11, off);
                }
                if (t == 0) {
                    sLogit[warp_n][warp_m * 32 + g]      = s00;
                    sLogit[warp_n][warp_m * 32 + 8 + g]  = s01;
                    sLogit[warp_n][warp_m * 32 + 16 + g] = s10;
                    sLogit[warp_n][warp_m * 32 + 24 + g] = s11;
                }
            }
            asm volatile("bar.sync 1, 256;" ::: "memory");   // A reads done, sLogit ready

            if (tid < 128) {
                int e = e0 + tid;
                if (e < E) g_logits[e] = sLogit[0][tid] + sLogit[1][tid] + __ldg(ba2);
            }
            // hidden -> A tile (cols 0..127)
#pragma unroll
            for (int mt = 0; mt < 2; mt++)
#pragma unroll
                for (int nb = 0; nb < 8; nb++) {
                    int c = warp_n * 64 + nb * 8 + 2 * t;
                    int r0 = warp_m * 32 + mt * 16 + g;
                    *(unsigned*)(pA + r0 * (SA2 * 2) + c * 2)       = hpk[mt][nb][0];
                    *(unsigned*)(pA + (r0 + 8) * (SA2 * 2) + c * 2) = hpk[mt][nb][1];
                }
            asm volatile("bar.sync 1, 256;" ::: "memory");   // hidden visible

            // ---- GEMM2 + store uh_e ----
            {
                float accO[2][4][4];
#pragma unroll
                for (int mt = 0; mt < 2; mt++)
#pragma unroll
                    for (int nb = 0; nb < 4; nb++)
#pragma unroll
                        for (int q = 0; q < 4; q++) accO[mt][nb][q] = 0.f;
                unsigned a[2][4];
                const uint2* sWu = (const uint2*)sW2v;
#pragma unroll
                for (int kk = 0; kk < 8; kk++) {
#pragma unroll
                    for (int mt = 0; mt < 2; mt++) {
                        int row = warp_m * 32 + mt * 16 + g;
                        const char* base = pA + row * (SA2 * 2) + kk * 32 + 4 * t;
                        a[mt][0] = *(const unsigned*)(base);
                        a[mt][1] = *(const unsigned*)(base + 8 * (SA2 * 2));
                        a[mt][2] = *(const unsigned*)(base + 16);
                        a[mt][3] = *(const unsigned*)(base + 8 * (SA2 * 2) + 16);
                    }
#pragma unroll
                    for (int nb = 0; nb < 4; nb++) {
                        uint2 b = sWu[(kk * 8 + warp_n * 4 + nb) * 32 + lane];
                        mma_f16(accO[0][nb], a[0], b);
                        mma_f16(accO[1][nb], a[1], b);
                    }
                }
#pragma unroll
                for (int mt = 0; mt < 2; mt++)
#pragma unroll
                    for (int nb = 0; nb < 4; nb++) {
                        int c = warp_n * 32 + nb * 8 + 2 * t;
                        float b0 = __ldg(be2 + c), b1 = __ldg(be2 + c + 1);
                        int r0 = warp_m * 32 + mt * 16 + g;
                        int e = e0 + r0;
                        if (e < E)
                            *(float2*)(uh_e + (size_t)e * 64 + c) =
                                make_float2(accO[mt][nb][0] + b0, accO[mt][nb][1] + b1);
                        if (e + 8 < E)
                            *(float2*)(uh_e + (size_t)(e + 8) * 64 + c) =
                                make_float2(accO[mt][nb][2] + b0, accO[mt][nb][3] + b1);
                    }
            }
        }
        __syncthreads();   // swap buffers: producer fill done, compute reads done
    }
}

// ---------------- node kernel (fp32 SIMT, unchanged) ------------------------
#define TILE 128
#define SWP  132
#define SW2P 68
template <int K>
__device__ __forceinline__ void gemm_8x8(const float* __restrict__ sAm, int lda,
                                         const float* __restrict__ sB, int ldb,
                                         int tx, int ty, float acc[8][8]) {
#pragma unroll
    for (int i = 0; i < 8; i++)
#pragma unroll
        for (int j = 0; j < 8; j++) acc[i][j] = 0.f;
#pragma unroll 2
    for (int k = 0; k < K; k++) {
        float a[8];
#pragma unroll
        for (int i = 0; i < 8; i++) a[i] = sAm[(ty * 8 + i) * lda + k];
        float4 b0 = *(const float4*)(sB + k * ldb + tx * 8);
        float4 b1 = *(const float4*)(sB + k * ldb + tx * 8 + 4);
        float b[8] = {b0.x, b0.y, b0.z, b0.w, b1.x, b1.y, b1.z, b1.w};
#pragma unroll
        for (int i = 0; i < 8; i++)
#pragma unroll
            for (int j = 0; j < 8; j++)
                acc[i][j] = fmaf(a[i], b[j], acc[i][j]);
    }
}

__global__ void __launch_bounds__(256, 1)
node_kernel(const float* __restrict__ nf,
            const float* __restrict__ Wn1, const float* __restrict__ bn1,
            const float* __restrict__ Wn2, const float* __restrict__ bn2,
            float* __restrict__ uh_n, int N)
{
    extern __shared__ float smem[];
    float* sIn  = smem;
    float* sW1  = smem + TILE * SWP;
    float* sHid = sW1;
    float* sW2  = sW1 + TILE * SWP;

    const int tid = threadIdx.x;
    const int tx = tid & 15, ty = tid >> 4;
    const int n0 = blockIdx.x * TILE;

    for (int idx = tid; idx < TILE * 32; idx += 256) {
        int ln = idx >> 5, q = idx & 31;
        int n = n0 + ln;
        float4 v = make_float4(0.f, 0.f, 0.f, 0.f);
        if (n < N)
            v = (q < 16) ? __ldg((const float4*)(g_agg + (size_t)n * 64) + q)
                         : __ldg((const float4*)(nf + (size_t)n * 64) + (q - 16));
        *(float4*)(sIn + ln * SWP + q * 4) = v;
    }
    for (int idx = tid; idx < 128 * 32; idx += 256) {
        int r = idx >> 5, c4 = idx & 31;
        *(float4*)(sW1 + r * SWP + c4 * 4) = __ldg((const float4*)Wn1 + idx);
    }
    __syncthreads();

    float acc[8][8];
    gemm_8x8<128>(sIn, SWP, sW1, SWP, tx, ty, acc);
    __syncthreads();

    {
        float4 bb0 = __ldg((const float4*)bn1 + tx * 2);
        float4 bb1 = __ldg((const float4*)bn1 + tx * 2 + 1);
        float bb[8] = {bb0.x, bb0.y, bb0.z, bb0.w, bb1.x, bb1.y, bb1.z, bb1.w};
#pragma unroll
        for (int i = 0; i < 8; i++)
#pragma unroll
            for (int j = 0; j < 8; j++)
                sHid[(ty * 8 + i) * SWP + tx * 8 + j] = fmaxf(acc[i][j] + bb[j], 0.f);
    }
    for (int idx = tid; idx < 128 * 16; idx += 256) {
        int r = idx >> 4, c4 = idx & 15;
        *(float4*)(sW2 + r * SW2P + c4 * 4) = __ldg((const float4*)Wn2 + idx);
    }
    __syncthreads();

    {
        float acc2[8][4];
#pragma unroll
        for (int i = 0; i < 8; i++)
#pragma unroll
            for (int j = 0; j < 4; j++) acc2[i][j] = 0.f;
#pragma unroll 4
        for (int k = 0; k < 128; k++) {
            float a[8];
#pragma unroll
            for (int i = 0; i < 8; i++) a[i] = sHid[(ty * 8 + i) * SWP + k];
            float4 b = *(const float4*)(sW2 + k * SW2P + tx * 4);
#pragma unroll
            for (int i = 0; i < 8; i++) {
                acc2[i][0] = fmaf(a[i], b.x, acc2[i][0]);
                acc2[i][1] = fmaf(a[i], b.y, acc2[i][1]);
                acc2[i][2] = fmaf(a[i], b.z, acc2[i][2]);
                acc2[i][3] = fmaf(a[i], b.w, acc2[i][3]);
            }
        }
        float4 b2 = __ldg((const float4*)bn2 + tx);
#pragma unroll
        for (int i = 0; i < 8; i++) {
            int n = n0 + ty * 8 + i;
            if (n < N) {
                float4 o = make_float4(acc2[i][0] + b2.x, acc2[i][1] + b2.y,
                                       acc2[i][2] + b2.z, acc2[i][3] + b2.w);
                *(float4*)(uh_n + (size_t)n * 64 + tx * 4) = o;
            }
        }
    }
}

// ---------------- softmax / aggregation kernels -----------------------------
__global__ void init_kernel(int N) {
    int t = blockIdx.x * blockDim.x + threadIdx.x;
    if (t < N * 64) g_agg[t] = 0.f;
    if (t < N) { g_denom[t] = 0.f; g_maxb[t] = 0u; }
}
__global__ void max_kernel(const int* __restrict__ dst, int E) {
    int t = blockIdx.x * blockDim.x + threadIdx.x;
    if (t < E) atomicMax(&g_maxb[dst[t]], ordenc(g_logits[t]));
}
__global__ void ex_kernel(const int* __restrict__ dst, int E) {
    int t = blockIdx.x * blockDim.x + threadIdx.x;
    if (t < E) {
        int d = dst[t];
        float m = orddec(g_maxb[d]);
        if (!isfinite(m)) m = 0.f;
        float ex = expf(g_logits[t] - m);
        g_ex[t] = ex;
        atomicAdd(&g_denom[d], ex);
    }
}
__global__ void agg_kernel(const int* __restrict__ dst, const float* __restrict__ uh_e, int E) {
    int t = blockIdx.x * blockDim.x + threadIdx.x;
    int e = t >> 4, lane = t & 15;
    if (e < E) {
        int d = dst[e];
        float attn = g_ex[e] / fmaxf(g_denom[d], 1e-38f);
        float4 u = __ldg((const float4*)(uh_e + (size_t)e * 64) + lane);
        float* p = g_agg + (size_t)d * 64 + lane * 4;
        atomicAdd(p + 0, u.x * attn);
        atomicAdd(p + 1, u.y * attn);
        atomicAdd(p + 2, u.z * attn);
        atomicAdd(p + 3, u.w * attn);
    }
}

// ---------------- launch -----------------------------------------------------
extern "C" void kernel_launch(void* const* d_in, const int* in_sizes, int n_in,
                              void* d_out, int out_size)
{
    const float* nf  = (const float*)d_in[0];
    const float* ef  = (const float*)d_in[1];
    const int*   src = (const int*)d_in[2];
    const int*   dst = (const int*)d_in[3];
    const float* We1 = (const float*)d_in[4];
    const float* be1 = (const float*)d_in[5];
    const float* We2 = (const float*)d_in[6];
    const float* be2 = (const float*)d_in[7];
    const float* Wa1 = (const float*)d_in[8];
    const float* ba1 = (const float*)d_in[9];
    const float* Wa2 = (const float*)d_in[10];
    const float* ba2 = (const float*)d_in[11];
    const float* Wn1 = (const float*)d_in[12];
    const float* bn1 = (const float*)d_in[13];
    const float* Wn2 = (const float*)d_in[14];
    const float* bn2 = (const float*)d_in[15];

    const int N = in_sizes[0] / 64;
    const int E = in_sizes[2];
    const int ntiles = (E + 127) / 128;

    float* uh_n = (float*)d_out;
    float* uh_e = uh_n + (size_t)N * 64;

    int nsm = 148;
    cudaDeviceGetAttribute(&nsm, cudaDevAttrMultiProcessorCount, 0);
    int grid = (nsm < ntiles) ? nsm : ntiles;

    const int EDGE_SMEM = 2 * A_BYTES + (10240 + 10240 + 4096) * 4;              // 184320
    const int NODE_SMEM = (TILE * SWP * 2 + TILE * SW2P) * (int)sizeof(float);   // 169984

    cudaFuncSetAttribute(edge_kernel, cudaFuncAttributeMaxDynamicSharedMemorySize, EDGE_SMEM);
    cudaFuncSetAttribute(node_kernel, cudaFuncAttributeMaxDynamicSharedMemorySize, NODE_SMEM);

    prep_kernel<<<(10240 + 4096 + 255) / 256, 256>>>(We1, Wa1, We2);
    init_kernel<<<(N * 64 + 255) / 256, 256>>>(N);
    edge_kernel<<<grid, 384, EDGE_SMEM>>>(
        nf, ef, src, dst, be1, be2, ba1, Wa2, ba2, uh_e, E, ntiles);
    max_kernel<<<(E + 255) / 256, 256>>>(dst, E);
    ex_kernel<<<(E + 255) / 256, 256>>>(dst, E);
    agg_kernel<<<(int)(((size_t)E * 16 + 255) / 256), 256>>>(dst, uh_e, E);
    node_kernel<<<(N + TILE - 1) / TILE, 256, NODE_SMEM>>>(
        nf, Wn1, bn1, Wn2, bn2, uh_n, N);
}

// round 7
// speedup vs baseline: 1.1828x; 1.1828x over previous
#include <cuda_runtime.h>
#include <cuda_fp16.h>
#include <math.h>
#include <stdint.h>

#define NN 50000
#define NE 800000

// ---------------- scratch (static device globals; no allocation) -----------
__device__ float    g_logits[NE];
__device__ float    g_ex[NE];
__device__ float    g_denom[NN];
__device__ unsigned g_maxb[NN];
__device__ float    g_agg[NN * 64];

// P/Q tables: [node][256] fp16 (stored as half2 words). P = nf@[We1s|Wa1s], Q = nf@[We1d|Wa1d]
__device__ unsigned g_P[50048 * 128];
__device__ unsigned g_Q[50048 * 128];

// fp16 fragment images (filled once per launch by prep_kernel)
__device__ unsigned g_WPf[8192];   // [K=64][N=256]
__device__ unsigned g_WQf[8192];   // [K=64][N=256]
__device__ unsigned g_Wcf[4096];   // [K=32][N=256]  (ef rows of We1|Wa1)
__device__ unsigned g_W2f[4096];   // [K=128][N=64]

__device__ __forceinline__ unsigned ordenc(float f) {
    unsigned u = __float_as_uint(f);
    return (u & 0x80000000u) ? ~u : (u | 0x80000000u);
}
__device__ __forceinline__ float orddec(unsigned u) {
    return __uint_as_float((u & 0x80000000u) ? (u ^ 0x80000000u) : ~u);
}
__device__ __forceinline__ unsigned pack_h2(float a, float b) {
    __half2 h = __floats2half2_rn(a, b);
    return *(unsigned*)&h;
}

__device__ __forceinline__ void mma_f16(float c[4], const unsigned a[4], uint2 b) {
    asm volatile(
        "mma.sync.aligned.m16n8k16.row.col.f32.f16.f16.f32 "
        "{%0,%1,%2,%3},{%4,%5,%6,%7},{%8,%9},{%0,%1,%2,%3};\n"
        : "+f"(c[0]), "+f"(c[1]), "+f"(c[2]), "+f"(c[3])
        : "r"(a[0]), "r"(a[1]), "r"(a[2]), "r"(a[3]), "r"(b.x), "r"(b.y));
}

// ---------------- weight prep: build all fragment images --------------------
// frag layout for W[K][N]: idx = ((kk*NBT + nbt)*32 + lane)*2 + reg
//   n = nbt*8 + (lane>>2); k0 = kk*16 + 2*(lane&3) + reg*8; val = pack(W[k0][n], W[k0+1][n])
__global__ void prep_kernel(const float* __restrict__ We1,
                            const float* __restrict__ Wa1,
                            const float* __restrict__ We2) {
    int idx = blockIdx.x * blockDim.x + threadIdx.x;
    if (idx < 8192) {                       // WP/WQ: K=64, N=256 (NBT=32)
        int reg = idx & 1, lane = (idx >> 1) & 31, nbt = (idx >> 6) & 31, kk = idx >> 11;
        int g = lane >> 2, t = lane & 3;
        int n = nbt * 8 + g;
        int k0 = kk * 16 + 2 * t + reg * 8;
        const float* W = (n < 128) ? We1 : Wa1;
        int nc = n & 127;
        g_WPf[idx] = pack_h2(W[k0 * 128 + nc], W[(k0 + 1) * 128 + nc]);
        g_WQf[idx] = pack_h2(W[(k0 + 64) * 128 + nc], W[(k0 + 65) * 128 + nc]);
    } else if (idx < 8192 + 4096) {         // Wc: K=32, N=256 (rows 128..159)
        int i = idx - 8192;
        int reg = i & 1, lane = (i >> 1) & 31, nbt = (i >> 6) & 31, kk = i >> 11;  // kk 0..1
        int g = lane >> 2, t = lane & 3;
        int n = nbt * 8 + g;
        int k0 = 128 + kk * 16 + 2 * t + reg * 8;
        const float* W = (n < 128) ? We1 : Wa1;
        int nc = n & 127;
        g_Wcf[i] = pack_h2(W[k0 * 128 + nc], W[(k0 + 1) * 128 + nc]);
    } else if (idx < 8192 + 4096 + 4096) {  // W2: K=128, N=64 (NBT=8)
        int i = idx - 12288;
        int reg = i & 1, lane = (i >> 1) & 31, nbt = (i >> 6) & 7, kk = i >> 9;
        int g = lane >> 2, t = lane & 3;
        int n = nbt * 8 + g;
        int k0 = kk * 16 + 2 * t + reg * 8;
        g_W2f[i] = pack_h2(We2[k0 * 64 + n], We2[(k0 + 1) * 64 + n]);
    }
}

// ---------------- per-node precompute: P = nf@WP, Q = nf@WQ (fp16 out) ------
// block = 128 nodes, 256 threads
__global__ void __launch_bounds__(256, 1)
pq_kernel(const float* __restrict__ nf, int N)
{
    extern __shared__ __align__(16) char dyn[];
    char* sNf = dyn;                              // [128][72] fp16 (stride 144B)
    unsigned* sWP = (unsigned*)(dyn + 18432);     // 32 KB
    unsigned* sWQ = sWP + 8192;                   // 32 KB

    const int tid = threadIdx.x;
    const int lane = tid & 31, wid = tid >> 5;
    const int g = lane >> 2, t = lane & 3;
    const int warp_m = wid & 3, warp_n = wid >> 2;
    const int n0 = blockIdx.x * 128;

    for (int i = tid; i < 2048; i += 256) ((uint4*)sWP)[i] = ((const uint4*)g_WPf)[i];
    for (int i = tid; i < 2048; i += 256) ((uint4*)sWQ)[i] = ((const uint4*)g_WQf)[i];
    for (int idx = tid; idx < 128 * 16; idx += 256) {
        int le = idx >> 4, q = idx & 15;
        int n = n0 + le;
        float4 v = make_float4(0.f, 0.f, 0.f, 0.f);
        if (n < N) v = __ldg((const float4*)(nf + (size_t)n * 64) + q);
        *(uint2*)(sNf + le * 144 + q * 8) = make_uint2(pack_h2(v.x, v.y), pack_h2(v.z, v.w));
    }
    __syncthreads();

    for (int tab = 0; tab < 2; tab++) {
        const uint2* sWu = (const uint2*)(tab ? sWQ : sWP);
        unsigned* gOut = tab ? g_Q : g_P;
        float acc[2][16][4];
#pragma unroll
        for (int mt = 0; mt < 2; mt++)
#pragma unroll
            for (int nb = 0; nb < 16; nb++)
#pragma unroll
                for (int q = 0; q < 4; q++) acc[mt][nb][q] = 0.f;
        unsigned a[2][4];
#pragma unroll
        for (int kk = 0; kk < 4; kk++) {
#pragma unroll
            for (int mt = 0; mt < 2; mt++) {
                int row = warp_m * 32 + mt * 16 + g;
                const char* base = sNf + row * 144 + kk * 32 + 4 * t;
                a[mt][0] = *(const unsigned*)(base);
                a[mt][1] = *(const unsigned*)(base + 8 * 144);
                a[mt][2] = *(const unsigned*)(base + 16);
                a[mt][3] = *(const unsigned*)(base + 8 * 144 + 16);
            }
#pragma unroll
            for (int nb = 0; nb < 16; nb++) {
                uint2 b = sWu[(kk * 32 + warp_n * 16 + nb) * 32 + lane];
                mma_f16(acc[0][nb], a[0], b);
                mma_f16(acc[1][nb], a[1], b);
            }
        }
#pragma unroll
        for (int mt = 0; mt < 2; mt++)
#pragma unroll
            for (int nb = 0; nb < 16; nb++) {
                int c = warp_n * 128 + nb * 8 + 2 * t;        // 0..255, even
                int r0 = warp_m * 32 + mt * 16 + g;
                if (n0 + r0 < N)
                    gOut[(size_t)(n0 + r0) * 128 + (c >> 1)] = pack_h2(acc[mt][nb][0], acc[mt][nb][1]);
                if (n0 + r0 + 8 < N)
                    gOut[(size_t)(n0 + r0 + 8) * 128 + (c >> 1)] = pack_h2(acc[mt][nb][2], acc[mt][nb][3]);
            }
    }
}

// ---------------- edge kernel: factored MLPs --------------------------------
// smem byte offsets
#define oEf 0          // [128][40] fp16  (10240 B, row stride 80)
#define oP  10240      // [128][264] fp16 (67584 B, row stride 528)
#define oQ  77824      // [128][264] fp16
#define oH  145408     // [128][136] fp16 (34816 B, row stride 272)
#define oW1 180224     // Wc frags 16384 B
#define oW2 196608     // W2 frags 16384 B
#define EDGE_SMEM 212992

__global__ void __launch_bounds__(256, 1)
edge_kernel(const float* __restrict__ ef_,
            const int* __restrict__ src, const int* __restrict__ dst,
            const float* __restrict__ be1, const float* __restrict__ be2,
            const float* __restrict__ ba1, const float* __restrict__ Wa2,
            const float* __restrict__ ba2,
            float* __restrict__ uh_e, int E)
{
    extern __shared__ __align__(16) char dyn[];
    __shared__ float sLogit[128];
    __shared__ int sSrc[128], sDst[128];

    const int tid = threadIdx.x;
    const int lane = tid & 31, wid = tid >> 5;
    const int g = lane >> 2, t = lane & 3;
    const int warp_m = wid & 3, warp_n = wid >> 2;
    const int e0 = blockIdx.x * 128;

    if (tid < 128)      { int e = e0 + tid;       sSrc[tid]       = (e < E) ? src[e] : 0; }
    else                { int e = e0 + tid - 128; sDst[tid - 128] = (e < E) ? dst[e] : 0; }
    __syncthreads();

    // stage weight frags (32 KB) + gather ef tile + gather P/Q rows
    for (int i = tid; i < 1024; i += 256) ((uint4*)(dyn + oW1))[i] = ((const uint4*)g_Wcf)[i];
    for (int i = tid; i < 1024; i += 256) ((uint4*)(dyn + oW2))[i] = ((const uint4*)g_W2f)[i];
    for (int idx = tid; idx < 1024; idx += 256) {   // ef: 128 x 8 float4
        int le = idx >> 3, q = idx & 7;
        int e = e0 + le;
        float4 v = make_float4(0.f, 0.f, 0.f, 0.f);
        if (e < E) v = __ldg((const float4*)(ef_ + (size_t)e * 32) + q);
        *(uint2*)(dyn + oEf + le * 80 + q * 8) = make_uint2(pack_h2(v.x, v.y), pack_h2(v.z, v.w));
    }
    for (int idx = tid; idx < 8192; idx += 256) {   // P then Q: 128 rows x 32 uint4
        int tab = idx >> 12;
        int i = idx & 4095;
        int le = i >> 5, q = i & 31;
        int r = tab ? sDst[le] : sSrc[le];
        uint4 v = __ldg((const uint4*)(tab ? g_Q : g_P) + (size_t)r * 32 + q);
        *(uint4*)(dyn + (tab ? oQ : oP) + le * 528 + q * 16) = v;
    }
    __syncthreads();

    // ---- GEMM_ef: [128x32] x Wc[32x256] ----
    float acc[2][16][4];
#pragma unroll
    for (int mt = 0; mt < 2; mt++)
#pragma unroll
        for (int nb = 0; nb < 16; nb++)
#pragma unroll
            for (int q = 0; q < 4; q++) acc[mt][nb][q] = 0.f;
    {
        unsigned a[2][4];
        const uint2* sWu = (const uint2*)(dyn + oW1);
#pragma unroll
        for (int kk = 0; kk < 2; kk++) {
#pragma unroll
            for (int mt = 0; mt < 2; mt++) {
                int row = warp_m * 32 + mt * 16 + g;
                const char* base = dyn + oEf + row * 80 + kk * 32 + 4 * t;
                a[mt][0] = *(const unsigned*)(base);
                a[mt][1] = *(const unsigned*)(base + 8 * 80);
                a[mt][2] = *(const unsigned*)(base + 16);
                a[mt][3] = *(const unsigned*)(base + 8 * 80 + 16);
            }
#pragma unroll
            for (int nb = 0; nb < 16; nb++) {
                uint2 b = sWu[(kk * 32 + warp_n * 16 + nb) * 32 + lane];
                mma_f16(acc[0][nb], a[0], b);
                mma_f16(acc[1][nb], a[1], b);
            }
        }
    }

    // ---- epilogue: h = acc + P[src] + Q[dst] + bias ----
    if (warp_n == 0) {
        // edge-MLP hidden -> sH (fp16)
#pragma unroll
        for (int mt = 0; mt < 2; mt++)
#pragma unroll
            for (int nb = 0; nb < 16; nb++) {
                int c = nb * 8 + 2 * t;
                float b0 = __ldg(be1 + c), b1 = __ldg(be1 + c + 1);
                int r0 = warp_m * 32 + mt * 16 + g, r1 = r0 + 8;
                __half2 p0 = *(const __half2*)(dyn + oP + r0 * 528 + c * 2);
                __half2 q0 = *(const __half2*)(dyn + oQ + r0 * 528 + c * 2);
                __half2 p1 = *(const __half2*)(dyn + oP + r1 * 528 + c * 2);
                __half2 q1 = *(const __half2*)(dyn + oQ + r1 * 528 + c * 2);
                float h00 = acc[mt][nb][0] + __low2float(p0) + __low2float(q0) + b0;
                float h01 = acc[mt][nb][1] + __high2float(p0) + __high2float(q0) + b1;
                float h10 = acc[mt][nb][2] + __low2float(p1) + __low2float(q1) + b0;
                float h11 = acc[mt][nb][3] + __high2float(p1) + __high2float(q1) + b1;
                *(unsigned*)(dyn + oH + r0 * 272 + c * 2) = pack_h2(fmaxf(h00, 0.f), fmaxf(h01, 0.f));
                *(unsigned*)(dyn + oH + r1 * 272 + c * 2) = pack_h2(fmaxf(h10, 0.f), fmaxf(h11, 0.f));
            }
    } else {
        // attention logit partials
        float s[4] = {0.f, 0.f, 0.f, 0.f};
#pragma unroll
        for (int nb = 0; nb < 16; nb++) {
            int c = nb * 8 + 2 * t;           // attn-hidden col 0..127
            int ct = (128 + c) * 2;           // byte offset in P/Q rows
            float b0 = __ldg(ba1 + c), b1 = __ldg(ba1 + c + 1);
            float w0 = __ldg(Wa2 + c), w1 = __ldg(Wa2 + c + 1);
#pragma unroll
            for (int mt = 0; mt < 2; mt++) {
                int r0 = warp_m * 32 + mt * 16 + g, r1 = r0 + 8;
                __half2 p0 = *(const __half2*)(dyn + oP + r0 * 528 + ct);
                __half2 q0 = *(const __half2*)(dyn + oQ + r0 * 528 + ct);
                __half2 p1 = *(const __half2*)(dyn + oP + r1 * 528 + ct);
                __half2 q1 = *(const __half2*)(dyn + oQ + r1 * 528 + ct);
                s[mt * 2 + 0] += fmaxf(acc[mt][nb][0] + __low2float(p0) + __low2float(q0) + b0, 0.f) * w0
                               + fmaxf(acc[mt][nb][1] + __high2float(p0) + __high2float(q0) + b1, 0.f) * w1;
                s[mt * 2 + 1] += fmaxf(acc[mt][nb][2] + __low2float(p1) + __low2float(q1) + b0, 0.f) * w0
                               + fmaxf(acc[mt][nb][3] + __high2float(p1) + __high2float(q1) + b1, 0.f) * w1;
            }
        }
#pragma unroll
        for (int off = 1; off <= 2; off <<= 1) {
            s[0] += __shfl_xor_sync(0xffffffffu, s[0], off);
            s[1] += __shfl_xor_sync(0xffffffffu, s[1], off);
            s[2] += __shfl_xor_sync(0xffffffffu, s[2], off);
            s[3] += __shfl_xor_sync(0xffffffffu, s[3], off);
        }
        if (t == 0) {
            sLogit[warp_m * 32 + g]      = s[0];
            sLogit[warp_m * 32 + 8 + g]  = s[1];
            sLogit[warp_m * 32 + 16 + g] = s[2];
            sLogit[warp_m * 32 + 24 + g] = s[3];
        }
    }
    __syncthreads();

    if (tid < 128) {
        int e = e0 + tid;
        if (e < E) g_logits[e] = sLogit[tid] + __ldg(ba2);
    }

    // ---- GEMM2: hidden[128x128] x W2[128x64] -> uh_e ----
    {
        float accO[2][4][4];
#pragma unroll
        for (int mt = 0; mt < 2; mt++)
#pragma unroll
            for (int nb = 0; nb < 4; nb++)
#pragma unroll
                for (int q = 0; q < 4; q++) accO[mt][nb][q] = 0.f;
        unsigned a[2][4];
        const uint2* sWu = (const uint2*)(dyn + oW2);
#pragma unroll
        for (int kk = 0; kk < 8; kk++) {
#pragma unroll
            for (int mt = 0; mt < 2; mt++) {
                int row = warp_m * 32 + mt * 16 + g;
                const char* base = dyn + oH + row * 272 + kk * 32 + 4 * t;
                a[mt][0] = *(const unsigned*)(base);
                a[mt][1] = *(const unsigned*)(base + 8 * 272);
                a[mt][2] = *(const unsigned*)(base + 16);
                a[mt][3] = *(const unsigned*)(base + 8 * 272 + 16);
            }
#pragma unroll
            for (int nb = 0; nb < 4; nb++) {
                uint2 b = sWu[(kk * 8 + warp_n * 4 + nb) * 32 + lane];
                mma_f16(accO[0][nb], a[0], b);
                mma_f16(accO[1][nb], a[1], b);
            }
        }
#pragma unroll
        for (int mt = 0; mt < 2; mt++)
#pragma unroll
            for (int nb = 0; nb < 4; nb++) {
                int c = warp_n * 32 + nb * 8 + 2 * t;
                float b0 = __ldg(be2 + c), b1 = __ldg(be2 + c + 1);
                int r0 = warp_m * 32 + mt * 16 + g;
                int e = e0 + r0;
                if (e < E)
                    *(float2*)(uh_e + (size_t)e * 64 + c) =
                        make_float2(accO[mt][nb][0] + b0, accO[mt][nb][1] + b1);
                if (e + 8 < E)
                    *(float2*)(uh_e + (size_t)(e + 8) * 64 + c) =
                        make_float2(accO[mt][nb][2] + b0, accO[mt][nb][3] + b1);
            }
    }
}

// ---------------- node kernel (fp32 SIMT, unchanged) ------------------------
#define TILE 128
#define SWP  132
#define SW2P 68
template <int K>
__device__ __forceinline__ void gemm_8x8(const float* __restrict__ sAm, int lda,
                                         const float* __restrict__ sB, int ldb,
                                         int tx, int ty, float acc[8][8]) {
#pragma unroll
    for (int i = 0; i < 8; i++)
#pragma unroll
        for (int j = 0; j < 8; j++) acc[i][j] = 0.f;
#pragma unroll 2
    for (int k = 0; k < K; k++) {
        float a[8];
#pragma unroll
        for (int i = 0; i < 8; i++) a[i] = sAm[(ty * 8 + i) * lda + k];
        float4 b0 = *(const float4*)(sB + k * ldb + tx * 8);
        float4 b1 = *(const float4*)(sB + k * ldb + tx * 8 + 4);
        float b[8] = {b0.x, b0.y, b0.z, b0.w, b1.x, b1.y, b1.z, b1.w};
#pragma unroll
        for (int i = 0; i < 8; i++)
#pragma unroll
            for (int j = 0; j < 8; j++)
                acc[i][j] = fmaf(a[i], b[j], acc[i][j]);
    }
}

__global__ void __launch_bounds__(256, 1)
node_kernel(const float* __restrict__ nf,
            const float* __restrict__ Wn1, const float* __restrict__ bn1,
            const float* __restrict__ Wn2, const float* __restrict__ bn2,
            float* __restrict__ uh_n, int N)
{
    extern __shared__ float smem[];
    float* sIn  = smem;
    float* sW1  = smem + TILE * SWP;
    float* sHid = sW1;
    float* sW2  = sW1 + TILE * SWP;

    const int tid = threadIdx.x;
    const int tx = tid & 15, ty = tid >> 4;
    const int n0 = blockIdx.x * TILE;

    for (int idx = tid; idx < TILE * 32; idx += 256) {
        int ln = idx >> 5, q = idx & 31;
        int n = n0 + ln;
        float4 v = make_float4(0.f, 0.f, 0.f, 0.f);
        if (n < N)
            v = (q < 16) ? __ldg((const float4*)(g_agg + (size_t)n * 64) + q)
                         : __ldg((const float4*)(nf + (size_t)n * 64) + (q - 16));
        *(float4*)(sIn + ln * SWP + q * 4) = v;
    }
    for (int idx = tid; idx < 128 * 32; idx += 256) {
        int r = idx >> 5, c4 = idx & 31;
        *(float4*)(sW1 + r * SWP + c4 * 4) = __ldg((const float4*)Wn1 + idx);
    }
    __syncthreads();

    float acc[8][8];
    gemm_8x8<128>(sIn, SWP, sW1, SWP, tx, ty, acc);
    __syncthreads();

    {
        float4 bb0 = __ldg((const float4*)bn1 + tx * 2);
        float4 bb1 = __ldg((const float4*)bn1 + tx * 2 + 1);
        float bb[8] = {bb0.x, bb0.y, bb0.z, bb0.w, bb1.x, bb1.y, bb1.z, bb1.w};
#pragma unroll
        for (int i = 0; i < 8; i++)
#pragma unroll
            for (int j = 0; j < 8; j++)
                sHid[(ty * 8 + i) * SWP + tx * 8 + j] = fmaxf(acc[i][j] + bb[j], 0.f);
    }
    for (int idx = tid; idx < 128 * 16; idx += 256) {
        int r = idx >> 4, c4 = idx & 15;
        *(float4*)(sW2 + r * SW2P + c4 * 4) = __ldg((const float4*)Wn2 + idx);
    }
    __syncthreads();

    {
        float acc2[8][4];
#pragma unroll
        for (int i = 0; i < 8; i++)
#pragma unroll
            for (int j = 0; j < 4; j++) acc2[i][j] = 0.f;
#pragma unroll 4
        for (int k = 0; k < 128; k++) {
            float a[8];
#pragma unroll
            for (int i = 0; i < 8; i++) a[i] = sHid[(ty * 8 + i) * SWP + k];
            float4 b = *(const float4*)(sW2 + k * SW2P + tx * 4);
#pragma unroll
            for (int i = 0; i < 8; i++) {
                acc2[i][0] = fmaf(a[i], b.x, acc2[i][0]);
                acc2[i][1] = fmaf(a[i], b.y, acc2[i][1]);
                acc2[i][2] = fmaf(a[i], b.z, acc2[i][2]);
                acc2[i][3] = fmaf(a[i], b.w, acc2[i][3]);
            }
        }
        float4 b2 = __ldg((const float4*)bn2 + tx);
#pragma unroll
        for (int i = 0; i < 8; i++) {
            int n = n0 + ty * 8 + i;
            if (n < N) {
                float4 o = make_float4(acc2[i][0] + b2.x, acc2[i][1] + b2.y,
                                       acc2[i][2] + b2.z, acc2[i][3] + b2.w);
                *(float4*)(uh_n + (size_t)n * 64 + tx * 4) = o;
            }
        }
    }
}

// ---------------- softmax / aggregation kernels -----------------------------
__global__ void init_kernel(int N) {
    int t = blockIdx.x * blockDim.x + threadIdx.x;
    if (t < N * 64) g_agg[t] = 0.f;
    if (t < N) { g_denom[t] = 0.f; g_maxb[t] = 0u; }
}
__global__ void max_kernel(const int* __restrict__ dst, int E) {
    int t = blockIdx.x * blockDim.x + threadIdx.x;
    if (t < E) atomicMax(&g_maxb[dst[t]], ordenc(g_logits[t]));
}
__global__ void ex_kernel(const int* __restrict__ dst, int E) {
    int t = blockIdx.x * blockDim.x + threadIdx.x;
    if (t < E) {
        int d = dst[t];
        float m = orddec(g_maxb[d]);
        if (!isfinite(m)) m = 0.f;
        float ex = expf(g_logits[t] - m);
        g_ex[t] = ex;
        atomicAdd(&g_denom[d], ex);
    }
}
__global__ void agg_kernel(const int* __restrict__ dst, const float* __restrict__ uh_e, int E) {
    int t = blockIdx.x * blockDim.x + threadIdx.x;
    int e = t >> 4, lane = t & 15;
    if (e < E) {
        int d = dst[e];
        float attn = g_ex[e] / fmaxf(g_denom[d], 1e-38f);
        float4 u = __ldg((const float4*)(uh_e + (size_t)e * 64) + lane);
        float* p = g_agg + (size_t)d * 64 + lane * 4;
        atomicAdd(p + 0, u.x * attn);
        atomicAdd(p + 1, u.y * attn);
        atomicAdd(p + 2, u.z * attn);
        atomicAdd(p + 3, u.w * attn);
    }
}

// ---------------- launch -----------------------------------------------------
extern "C" void kernel_launch(void* const* d_in, const int* in_sizes, int n_in,
                              void* d_out, int out_size)
{
    const float* nf  = (const float*)d_in[0];
    const float* ef  = (const float*)d_in[1];
    const int*   src = (const int*)d_in[2];
    const int*   dst = (const int*)d_in[3];
    const float* We1 = (const float*)d_in[4];
    const float* be1 = (const float*)d_in[5];
    const float* We2 = (const float*)d_in[6];
    const float* be2 = (const float*)d_in[7];
    const float* Wa1 = (const float*)d_in[8];
    const float* ba1 = (const float*)d_in[9];
    const float* Wa2 = (const float*)d_in[10];
    const float* ba2 = (const float*)d_in[11];
    const float* Wn1 = (const float*)d_in[12];
    const float* bn1 = (const float*)d_in[13];
    const float* Wn2 = (const float*)d_in[14];
    const float* bn2 = (const float*)d_in[15];

    const int N = in_sizes[0] / 64;
    const int E = in_sizes[2];

    float* uh_n = (float*)d_out;
    float* uh_e = uh_n + (size_t)N * 64;

    const int PQ_SMEM   = 18432 + 32768 + 32768;                                 // 83968
    const int NODE_SMEM = (TILE * SWP * 2 + TILE * SW2P) * (int)sizeof(float);   // 169984

    cudaFuncSetAttribute(pq_kernel,   cudaFuncAttributeMaxDynamicSharedMemorySize, PQ_SMEM);
    cudaFuncSetAttribute(edge_kernel, cudaFuncAttributeMaxDynamicSharedMemorySize, EDGE_SMEM);
    cudaFuncSetAttribute(node_kernel, cudaFuncAttributeMaxDynamicSharedMemorySize, NODE_SMEM);

    prep_kernel<<<(16384 + 255) / 256, 256>>>(We1, Wa1, We2);
    init_kernel<<<(N * 64 + 255) / 256, 256>>>(N);
    pq_kernel<<<(N + 127) / 128, 256, PQ_SMEM>>>(nf, N);
    edge_kernel<<<(E + 127) / 128, 256, EDGE_SMEM>>>(
        ef, src, dst, be1, be2, ba1, Wa2, ba2, uh_e, E);
    max_kernel<<<(E + 255) / 256, 256>>>(dst, E);
    ex_kernel<<<(E + 255) / 256, 256>>>(dst, E);
    agg_kernel<<<(int)(((size_t)E * 16 + 255) / 256), 256>>>(dst, uh_e, E);
    node_kernel<<<(N + TILE - 1) / TILE, 256, NODE_SMEM>>>(
        nf, Wn1, bn1, Wn2, bn2, uh_n, N);
}

// round 8
// speedup vs baseline: 1.9216x; 1.6246x over previous
#include <cuda_runtime.h>
#include <cuda_fp16.h>
#include <math.h>
#include <stdint.h>

#define NN 50000
#define NE 800000

// ---------------- scratch (static device globals; no allocation) -----------
__device__ float    g_logits[NE];
__device__ float    g_ex[NE];
__device__ float    g_denom[NN];
__device__ unsigned g_maxb[NN];
__device__ float    g_agg[NN * 64];

// P/Q tables: [node][256] fp16. P = nf@[We1s|Wa1s], Q = nf@[We1d|Wa1d]
__device__ unsigned g_P[50048 * 128];
__device__ unsigned g_Q[50048 * 128];

// fp16 fragment images
__device__ unsigned g_WPf[8192];   // [K=64][N=256]
__device__ unsigned g_WQf[8192];   // [K=64][N=256]
__device__ unsigned g_Wcf[4096];   // [K=32][N=256]  (ef rows of We1|Wa1)
__device__ unsigned g_W2f[4096];   // [K=128][N=64]

__device__ __forceinline__ unsigned ordenc(float f) {
    unsigned u = __float_as_uint(f);
    return (u & 0x80000000u) ? ~u : (u | 0x80000000u);
}
__device__ __forceinline__ float orddec(unsigned u) {
    return __uint_as_float((u & 0x80000000u) ? (u ^ 0x80000000u) : ~u);
}
__device__ __forceinline__ unsigned pack_h2(float a, float b) {
    __half2 h = __floats2half2_rn(a, b);
    return *(unsigned*)&h;
}
__device__ __forceinline__ unsigned addh2_f32(unsigned a, unsigned b) {
    float2 fa = __half22float2(*(__half2*)&a);
    float2 fb = __half22float2(*(__half2*)&b);
    return pack_h2(fa.x + fb.x, fa.y + fb.y);
}

__device__ __forceinline__ void mma_f16(float c[4], const unsigned a[4], uint2 b) {
    asm volatile(
        "mma.sync.aligned.m16n8k16.row.col.f32.f16.f16.f32 "
        "{%0,%1,%2,%3},{%4,%5,%6,%7},{%8,%9},{%0,%1,%2,%3};\n"
        : "+f"(c[0]), "+f"(c[1]), "+f"(c[2]), "+f"(c[3])
        : "r"(a[0]), "r"(a[1]), "r"(a[2]), "r"(a[3]), "r"(b.x), "r"(b.y));
}

// ---------------- weight prep -----------------------------------------------
__global__ void prep_kernel(const float* __restrict__ We1,
                            const float* __restrict__ Wa1,
                            const float* __restrict__ We2) {
    int idx = blockIdx.x * blockDim.x + threadIdx.x;
    if (idx < 8192) {                       // WP/WQ: K=64, N=256 (NBT=32)
        int reg = idx & 1, lane = (idx >> 1) & 31, nbt = (idx >> 6) & 31, kk = idx >> 11;
        int g = lane >> 2, t = lane & 3;
        int n = nbt * 8 + g;
        int k0 = kk * 16 + 2 * t + reg * 8;
        const float* W = (n < 128) ? We1 : Wa1;
        int nc = n & 127;
        g_WPf[idx] = pack_h2(W[k0 * 128 + nc], W[(k0 + 1) * 128 + nc]);
        g_WQf[idx] = pack_h2(W[(k0 + 64) * 128 + nc], W[(k0 + 65) * 128 + nc]);
    } else if (idx < 8192 + 4096) {         // Wc: K=32, N=256 (rows 128..159)
        int i = idx - 8192;
        int reg = i & 1, lane = (i >> 1) & 31, nbt = (i >> 6) & 31, kk = i >> 11;
        int g = lane >> 2, t = lane & 3;
        int n = nbt * 8 + g;
        int k0 = 128 + kk * 16 + 2 * t + reg * 8;
        const float* W = (n < 128) ? We1 : Wa1;
        int nc = n & 127;
        g_Wcf[i] = pack_h2(W[k0 * 128 + nc], W[(k0 + 1) * 128 + nc]);
    } else if (idx < 8192 + 4096 + 4096) {  // W2: K=128, N=64
        int i = idx - 12288;
        int reg = i & 1, lane = (i >> 1) & 31, nbt = (i >> 6) & 7, kk = i >> 9;
        int g = lane >> 2, t = lane & 3;
        int n = nbt * 8 + g;
        int k0 = kk * 16 + 2 * t + reg * 8;
        g_W2f[i] = pack_h2(We2[k0 * 64 + n], We2[(k0 + 1) * 64 + n]);
    }
}

// ---------------- per-node precompute: P = nf@WP, Q = nf@WQ -----------------
__global__ void __launch_bounds__(256, 1)
pq_kernel(const float* __restrict__ nf, int N)
{
    extern __shared__ __align__(16) char dyn[];
    char* sNf = dyn;                              // [128][72] fp16 (stride 144B)
    unsigned* sWP = (unsigned*)(dyn + 18432);     // 32 KB
    unsigned* sWQ = sWP + 8192;                   // 32 KB

    const int tid = threadIdx.x;
    const int lane = tid & 31, wid = tid >> 5;
    const int g = lane >> 2, t = lane & 3;
    const int warp_m = wid & 3, warp_n = wid >> 2;
    const int n0 = blockIdx.x * 128;

    for (int i = tid; i < 2048; i += 256) ((uint4*)sWP)[i] = ((const uint4*)g_WPf)[i];
    for (int i = tid; i < 2048; i += 256) ((uint4*)sWQ)[i] = ((const uint4*)g_WQf)[i];
    for (int idx = tid; idx < 128 * 16; idx += 256) {
        int le = idx >> 4, q = idx & 15;
        int n = n0 + le;
        float4 v = make_float4(0.f, 0.f, 0.f, 0.f);
        if (n < N) v = __ldg((const float4*)(nf + (size_t)n * 64) + q);
        *(uint2*)(sNf + le * 144 + q * 8) = make_uint2(pack_h2(v.x, v.y), pack_h2(v.z, v.w));
    }
    __syncthreads();

    for (int tab = 0; tab < 2; tab++) {
        const uint2* sWu = (const uint2*)(tab ? sWQ : sWP);
        unsigned* gOut = tab ? g_Q : g_P;
        float acc[2][16][4];
#pragma unroll
        for (int mt = 0; mt < 2; mt++)
#pragma unroll
            for (int nb = 0; nb < 16; nb++)
#pragma unroll
                for (int q = 0; q < 4; q++) acc[mt][nb][q] = 0.f;
        unsigned a[2][4];
#pragma unroll
        for (int kk = 0; kk < 4; kk++) {
#pragma unroll
            for (int mt = 0; mt < 2; mt++) {
                int row = warp_m * 32 + mt * 16 + g;
                const char* base = sNf + row * 144 + kk * 32 + 4 * t;
                a[mt][0] = *(const unsigned*)(base);
                a[mt][1] = *(const unsigned*)(base + 8 * 144);
                a[mt][2] = *(const unsigned*)(base + 16);
                a[mt][3] = *(const unsigned*)(base + 8 * 144 + 16);
            }
#pragma unroll
            for (int nb = 0; nb < 16; nb++) {
                uint2 b = sWu[(kk * 32 + warp_n * 16 + nb) * 32 + lane];
                mma_f16(acc[0][nb], a[0], b);
                mma_f16(acc[1][nb], a[1], b);
            }
        }
#pragma unroll
        for (int mt = 0; mt < 2; mt++)
#pragma unroll
            for (int nb = 0; nb < 16; nb++) {
                int c = warp_n * 128 + nb * 8 + 2 * t;
                int r0 = warp_m * 32 + mt * 16 + g;
                if (n0 + r0 < N)
                    gOut[(size_t)(n0 + r0) * 128 + (c >> 1)] = pack_h2(acc[mt][nb][0], acc[mt][nb][1]);
                if (n0 + r0 + 8 < N)
                    gOut[(size_t)(n0 + r0 + 8) * 128 + (c >> 1)] = pack_h2(acc[mt][nb][2], acc[mt][nb][3]);
            }
    }
}

// ---------------- edge kernel: factored, 2 CTAs/SM ---------------------------
// smem: ef [128][40]h stride 80 ; S [128][264]h stride 528 (edge cols get
// overwritten in-place by hidden H) ; W frags
#define oEf 0
#define oS  10240
#define oW1 77824
#define oW2 94208
#define EDGE_SMEM 110592

__global__ void __launch_bounds__(256, 2)
edge_kernel(const float* __restrict__ ef_,
            const int* __restrict__ src, const int* __restrict__ dst,
            const float* __restrict__ be1, const float* __restrict__ be2,
            const float* __restrict__ ba1, const float* __restrict__ Wa2,
            const float* __restrict__ ba2,
            float* __restrict__ uh_e, int E)
{
    extern __shared__ __align__(16) char dyn[];
    __shared__ int sSrc[128], sDst[128];

    const int tid = threadIdx.x;
    const int lane = tid & 31, wid = tid >> 5;
    const int g = lane >> 2, t = lane & 3;
    const int e0 = blockIdx.x * 128;

    if (tid < 128)      { int e = e0 + tid;       sSrc[tid]       = (e < E) ? src[e] : 0; }
    else                { int e = e0 + tid - 128; sDst[tid - 128] = (e < E) ? dst[e] : 0; }
    __syncthreads();

    // stage weight frags + ef tile + combined S = P[src] + Q[dst]
    for (int i = tid; i < 1024; i += 256) ((uint4*)(dyn + oW1))[i] = ((const uint4*)g_Wcf)[i];
    for (int i = tid; i < 1024; i += 256) ((uint4*)(dyn + oW2))[i] = ((const uint4*)g_W2f)[i];
    for (int idx = tid; idx < 1024; idx += 256) {
        int le = idx >> 3, q = idx & 7;
        int e = e0 + le;
        float4 v = make_float4(0.f, 0.f, 0.f, 0.f);
        if (e < E) v = __ldg((const float4*)(ef_ + (size_t)e * 32) + q);
        *(uint2*)(dyn + oEf + le * 80 + q * 8) = make_uint2(pack_h2(v.x, v.y), pack_h2(v.z, v.w));
    }
    for (int idx = tid; idx < 4096; idx += 256) {
        int le = idx >> 5, q = idx & 31;
        uint4 p = __ldg((const uint4*)g_P + (size_t)sSrc[le] * 32 + q);
        uint4 qv = __ldg((const uint4*)g_Q + (size_t)sDst[le] * 32 + q);
        uint4 s;
        s.x = addh2_f32(p.x, qv.x); s.y = addh2_f32(p.y, qv.y);
        s.z = addh2_f32(p.z, qv.z); s.w = addh2_f32(p.w, qv.w);
        *(uint4*)(dyn + oS + le * 528 + q * 16) = s;
    }
    __syncthreads();

    const int row0 = wid * 16 + g, row1 = row0 + 8;

    // ---- Pass E: edge-hidden cols [0,128). Each warp: 16 rows x 128 cols ----
    {
        float acc[16][4];
#pragma unroll
        for (int nb = 0; nb < 16; nb++)
#pragma unroll
            for (int q = 0; q < 4; q++) acc[nb][q] = 0.f;
        unsigned a[4];
        const uint2* sWu = (const uint2*)(dyn + oW1);
#pragma unroll
        for (int kk = 0; kk < 2; kk++) {
            const char* base = dyn + oEf + row0 * 80 + kk * 32 + 4 * t;
            a[0] = *(const unsigned*)(base);
            a[1] = *(const unsigned*)(base + 8 * 80);
            a[2] = *(const unsigned*)(base + 16);
            a[3] = *(const unsigned*)(base + 8 * 80 + 16);
#pragma unroll
            for (int nb = 0; nb < 16; nb++) {
                uint2 b = sWu[(kk * 32 + nb) * 32 + lane];
                mma_f16(acc[nb], a, b);
            }
        }
        // epilogue: h = acc + S + be1, relu -> fp16, in-place into S cols 0..127
#pragma unroll
        for (int nb = 0; nb < 16; nb++) {
            int c = nb * 8 + 2 * t;
            float b0 = __ldg(be1 + c), b1 = __ldg(be1 + c + 1);
            float2 s0 = __half22float2(*(const __half2*)(dyn + oS + row0 * 528 + c * 2));
            float2 s1 = __half22float2(*(const __half2*)(dyn + oS + row1 * 528 + c * 2));
            *(unsigned*)(dyn + oS + row0 * 528 + c * 2) =
                pack_h2(fmaxf(acc[nb][0] + s0.x + b0, 0.f), fmaxf(acc[nb][1] + s0.y + b1, 0.f));
            *(unsigned*)(dyn + oS + row1 * 528 + c * 2) =
                pack_h2(fmaxf(acc[nb][2] + s1.x + b0, 0.f), fmaxf(acc[nb][3] + s1.y + b1, 0.f));
        }
    }

    // ---- Pass A: attn cols [128,256) + logit reduction ----
    {
        float acc[16][4];
#pragma unroll
        for (int nb = 0; nb < 16; nb++)
#pragma unroll
            for (int q = 0; q < 4; q++) acc[nb][q] = 0.f;
        unsigned a[4];
        const uint2* sWu = (const uint2*)(dyn + oW1);
#pragma unroll
        for (int kk = 0; kk < 2; kk++) {
            const char* base = dyn + oEf + row0 * 80 + kk * 32 + 4 * t;
            a[0] = *(const unsigned*)(base);
            a[1] = *(const unsigned*)(base + 8 * 80);
            a[2] = *(const unsigned*)(base + 16);
            a[3] = *(const unsigned*)(base + 8 * 80 + 16);
#pragma unroll
            for (int nb = 0; nb < 16; nb++) {
                uint2 b = sWu[(kk * 32 + 16 + nb) * 32 + lane];
                mma_f16(acc[nb], a, b);
            }
        }
        float l0 = 0.f, l1 = 0.f;
#pragma unroll
        for (int nb = 0; nb < 16; nb++) {
            int c = nb * 8 + 2 * t;
            int off = (128 + c) * 2;
            float b0 = __ldg(ba1 + c), b1 = __ldg(ba1 + c + 1);
            float w0 = __ldg(Wa2 + c), w1 = __ldg(Wa2 + c + 1);
            float2 s0 = __half22float2(*(const __half2*)(dyn + oS + row0 * 528 + off));
            float2 s1 = __half22float2(*(const __half2*)(dyn + oS + row1 * 528 + off));
            l0 += fmaxf(acc[nb][0] + s0.x + b0, 0.f) * w0 + fmaxf(acc[nb][1] + s0.y + b1, 0.f) * w1;
            l1 += fmaxf(acc[nb][2] + s1.x + b0, 0.f) * w0 + fmaxf(acc[nb][3] + s1.y + b1, 0.f) * w1;
        }
#pragma unroll
        for (int off = 1; off <= 2; off <<= 1) {
            l0 += __shfl_xor_sync(0xffffffffu, l0, off);
            l1 += __shfl_xor_sync(0xffffffffu, l1, off);
        }
        if (t == 0) {
            float b2 = __ldg(ba2);
            if (e0 + row0 < E) g_logits[e0 + row0] = l0 + b2;
            if (e0 + row1 < E) g_logits[e0 + row1] = l1 + b2;
        }
    }
    __syncthreads();   // hidden H (in S region) visible to all warps

    // ---- GEMM2: H[128x128] x W2[128x64] -> uh_e ----
    {
        const int warp_m = wid & 3, warp_n = wid >> 2;
        float accO[2][4][4];
#pragma unroll
        for (int mt = 0; mt < 2; mt++)
#pragma unroll
            for (int nb = 0; nb < 4; nb++)
#pragma unroll
                for (int q = 0; q < 4; q++) accO[mt][nb][q] = 0.f;
        unsigned a[2][4];
        const uint2* sWu = (const uint2*)(dyn + oW2);
#pragma unroll
        for (int kk = 0; kk < 8; kk++) {
#pragma unroll
            for (int mt = 0; mt < 2; mt++) {
                int row = warp_m * 32 + mt * 16 + g;
                const char* base = dyn + oS + row * 528 + kk * 32 + 4 * t;
                a[mt][0] = *(const unsigned*)(base);
                a[mt][1] = *(const unsigned*)(base + 8 * 528);
                a[mt][2] = *(const unsigned*)(base + 16);
                a[mt][3] = *(const unsigned*)(base + 8 * 528 + 16);
            }
#pragma unroll
            for (int nb = 0; nb < 4; nb++) {
                uint2 b = sWu[(kk * 8 + warp_n * 4 + nb) * 32 + lane];
                mma_f16(accO[0][nb], a[0], b);
                mma_f16(accO[1][nb], a[1], b);
            }
        }
#pragma unroll
        for (int mt = 0; mt < 2; mt++)
#pragma unroll
            for (int nb = 0; nb < 4; nb++) {
                int c = warp_n * 32 + nb * 8 + 2 * t;
                float b0 = __ldg(be2 + c), b1 = __ldg(be2 + c + 1);
                int r0 = warp_m * 32 + mt * 16 + g;
                int e = e0 + r0;
                if (e < E)
                    *(float2*)(uh_e + (size_t)e * 64 + c) =
                        make_float2(accO[mt][nb][0] + b0, accO[mt][nb][1] + b1);
                if (e + 8 < E)
                    *(float2*)(uh_e + (size_t)(e + 8) * 64 + c) =
                        make_float2(accO[mt][nb][2] + b0, accO[mt][nb][3] + b1);
            }
    }
}

// ---------------- node kernel (fp32 SIMT, unchanged) ------------------------
#define TILE 128
#define SWP  132
#define SW2P 68
template <int K>
__device__ __forceinline__ void gemm_8x8(const float* __restrict__ sAm, int lda,
                                         const float* __restrict__ sB, int ldb,
                                         int tx, int ty, float acc[8][8]) {
#pragma unroll
    for (int i = 0; i < 8; i++)
#pragma unroll
        for (int j = 0; j < 8; j++) acc[i][j] = 0.f;
#pragma unroll 2
    for (int k = 0; k < K; k++) {
        float a[8];
#pragma unroll
        for (int i = 0; i < 8; i++) a[i] = sAm[(ty * 8 + i) * lda + k];
        float4 b0 = *(const float4*)(sB + k * ldb + tx * 8);
        float4 b1 = *(const float4*)(sB + k * ldb + tx * 8 + 4);
        float b[8] = {b0.x, b0.y, b0.z, b0.w, b1.x, b1.y, b1.z, b1.w};
#pragma unroll
        for (int i = 0; i < 8; i++)
#pragma unroll
            for (int j = 0; j < 8; j++)
                acc[i][j] = fmaf(a[i], b[j], acc[i][j]);
    }
}

__global__ void __launch_bounds__(256, 1)
node_kernel(const float* __restrict__ nf,
            const float* __restrict__ Wn1, const float* __restrict__ bn1,
            const float* __restrict__ Wn2, const float* __restrict__ bn2,
            float* __restrict__ uh_n, int N)
{
    extern __shared__ float smem[];
    float* sIn  = smem;
    float* sW1  = smem + TILE * SWP;
    float* sHid = sW1;
    float* sW2  = sW1 + TILE * SWP;

    const int tid = threadIdx.x;
    const int tx = tid & 15, ty = tid >> 4;
    const int n0 = blockIdx.x * TILE;

    for (int idx = tid; idx < TILE * 32; idx += 256) {
        int ln = idx >> 5, q = idx & 31;
        int n = n0 + ln;
        float4 v = make_float4(0.f, 0.f, 0.f, 0.f);
        if (n < N)
            v = (q < 16) ? __ldg((const float4*)(g_agg + (size_t)n * 64) + q)
                         : __ldg((const float4*)(nf + (size_t)n * 64) + (q - 16));
        *(float4*)(sIn + ln * SWP + q * 4) = v;
    }
    for (int idx = tid; idx < 128 * 32; idx += 256) {
        int r = idx >> 5, c4 = idx & 31;
        *(float4*)(sW1 + r * SWP + c4 * 4) = __ldg((const float4*)Wn1 + idx);
    }
    __syncthreads();

    float acc[8][8];
    gemm_8x8<128>(sIn, SWP, sW1, SWP, tx, ty, acc);
    __syncthreads();

    {
        float4 bb0 = __ldg((const float4*)bn1 + tx * 2);
        float4 bb1 = __ldg((const float4*)bn1 + tx * 2 + 1);
        float bb[8] = {bb0.x, bb0.y, bb0.z, bb0.w, bb1.x, bb1.y, bb1.z, bb1.w};
#pragma unroll
        for (int i = 0; i < 8; i++)
#pragma unroll
            for (int j = 0; j < 8; j++)
                sHid[(ty * 8 + i) * SWP + tx * 8 + j] = fmaxf(acc[i][j] + bb[j], 0.f);
    }
    for (int idx = tid; idx < 128 * 16; idx += 256) {
        int r = idx >> 4, c4 = idx & 15;
        *(float4*)(sW2 + r * SW2P + c4 * 4) = __ldg((const float4*)Wn2 + idx);
    }
    __syncthreads();

    {
        float acc2[8][4];
#pragma unroll
        for (int i = 0; i < 8; i++)
#pragma unroll
            for (int j = 0; j < 4; j++) acc2[i][j] = 0.f;
#pragma unroll 4
        for (int k = 0; k < 128; k++) {
            float a[8];
#pragma unroll
            for (int i = 0; i < 8; i++) a[i] = sHid[(ty * 8 + i) * SWP + k];
            float4 b = *(const float4*)(sW2 + k * SW2P + tx * 4);
#pragma unroll
            for (int i = 0; i < 8; i++) {
                acc2[i][0] = fmaf(a[i], b.x, acc2[i][0]);
                acc2[i][1] = fmaf(a[i], b.y, acc2[i][1]);
                acc2[i][2] = fmaf(a[i], b.z, acc2[i][2]);
                acc2[i][3] = fmaf(a[i], b.w, acc2[i][3]);
            }
        }
        float4 b2 = __ldg((const float4*)bn2 + tx);
#pragma unroll
        for (int i = 0; i < 8; i++) {
            int n = n0 + ty * 8 + i;
            if (n < N) {
                float4 o = make_float4(acc2[i][0] + b2.x, acc2[i][1] + b2.y,
                                       acc2[i][2] + b2.z, acc2[i][3] + b2.w);
                *(float4*)(uh_n + (size_t)n * 64 + tx * 4) = o;
            }
        }
    }
}

// ---------------- softmax / aggregation kernels -----------------------------
__global__ void init_kernel(int N) {
    int t = blockIdx.x * blockDim.x + threadIdx.x;
    if (t < N * 64) g_agg[t] = 0.f;
    if (t < N) { g_denom[t] = 0.f; g_maxb[t] = 0u; }
}
__global__ void max_kernel(const int* __restrict__ dst, int E) {
    int t = blockIdx.x * blockDim.x + threadIdx.x;
    if (t < E) atomicMax(&g_maxb[dst[t]], ordenc(g_logits[t]));
}
__global__ void ex_kernel(const int* __restrict__ dst, int E) {
    int t = blockIdx.x * blockDim.x + threadIdx.x;
    if (t < E) {
        int d = dst[t];
        float m = orddec(g_maxb[d]);
        if (!isfinite(m)) m = 0.f;
        float ex = expf(g_logits[t] - m);
        g_ex[t] = ex;
        atomicAdd(&g_denom[d], ex);
    }
}
__global__ void agg_kernel(const int* __restrict__ dst, const float* __restrict__ uh_e, int E) {
    int t = blockIdx.x * blockDim.x + threadIdx.x;
    int e = t >> 4, lane = t & 15;
    if (e < E) {
        int d = dst[e];
        float attn = g_ex[e] / fmaxf(g_denom[d], 1e-38f);
        float4 u = __ldg((const float4*)(uh_e + (size_t)e * 64) + lane);
        float* p = g_agg + (size_t)d * 64 + lane * 4;
        atomicAdd(p + 0, u.x * attn);
        atomicAdd(p + 1, u.y * attn);
        atomicAdd(p + 2, u.z * attn);
        atomicAdd(p + 3, u.w * attn);
    }
}

// ---------------- launch -----------------------------------------------------
extern "C" void kernel_launch(void* const* d_in, const int* in_sizes, int n_in,
                              void* d_out, int out_size)
{
    const float* nf  = (const float*)d_in[0];
    const float* ef  = (const float*)d_in[1];
    const int*   src = (const int*)d_in[2];
    const int*   dst = (const int*)d_in[3];
    const float* We1 = (const float*)d_in[4];
    const float* be1 = (const float*)d_in[5];
    const float* We2 = (const float*)d_in[6];
    const float* be2 = (const float*)d_in[7];
    const float* Wa1 = (const float*)d_in[8];
    const float* ba1 = (const float*)d_in[9];
    const float* Wa2 = (const float*)d_in[10];
    const float* ba2 = (const float*)d_in[11];
    const float* Wn1 = (const float*)d_in[12];
    const float* bn1 = (const float*)d_in[13];
    const float* Wn2 = (const float*)d_in[14];
    const float* bn2 = (const float*)d_in[15];

    const int N = in_sizes[0] / 64;
    const int E = in_sizes[2];

    float* uh_n = (float*)d_out;
    float* uh_e = uh_n + (size_t)N * 64;

    const int PQ_SMEM   = 18432 + 32768 + 32768;                                 // 83968
    const int NODE_SMEM = (TILE * SWP * 2 + TILE * SW2P) * (int)sizeof(float);   // 169984

    cudaFuncSetAttribute(pq_kernel,   cudaFuncAttributeMaxDynamicSharedMemorySize, PQ_SMEM);
    cudaFuncSetAttribute(edge_kernel, cudaFuncAttributeMaxDynamicSharedMemorySize, EDGE_SMEM);
    cudaFuncSetAttribute(node_kernel, cudaFuncAttributeMaxDynamicSharedMemorySize, NODE_SMEM);

    prep_kernel<<<(16384 + 255) / 256, 256>>>(We1, Wa1, We2);
    init_kernel<<<(N * 64 + 255) / 256, 256>>>(N);
    pq_kernel<<<(N + 127) / 128, 256, PQ_SMEM>>>(nf, N);
    edge_kernel<<<(E + 127) / 128, 256, EDGE_SMEM>>>(
        ef, src, dst, be1, be2, ba1, Wa2, ba2, uh_e, E);
    max_kernel<<<(E + 255) / 256, 256>>>(dst, E);
    ex_kernel<<<(E + 255) / 256, 256>>>(dst, E);
    agg_kernel<<<(int)(((size_t)E * 16 + 255) / 256), 256>>>(dst, uh_e, E);
    node_kernel<<<(N + TILE - 1) / TILE, 256, NODE_SMEM>>>(
        nf, Wn1, bn1, Wn2, bn2, uh_n, N);
}

// round 9
// speedup vs baseline: 1.9899x; 1.0355x over previous
#include <cuda_runtime.h>
#include <cuda_fp16.h>
#include <math.h>
#include <stdint.h>

#define NN 50000
#define NE 800000

// ---------------- scratch (static device globals; no allocation) -----------
__device__ float    g_logits[NE];
__device__ float    g_ex[NE];
__device__ float    g_denom[NN];
__device__ unsigned g_maxb[NN];
__device__ float    g_agg[NN * 64];

// P/Q tables: [node][256] fp16. P = nf@[We1s|Wa1s], Q = nf@[We1d|Wa1d]
__device__ unsigned g_P[50048 * 128];
__device__ unsigned g_Q[50048 * 128];

// fp16 fragment images
__device__ unsigned g_WPf[8192];   // [K=64][N=256]
__device__ unsigned g_WQf[8192];   // [K=64][N=256]
__device__ unsigned g_Wcf[4096];   // [K=32][N=256]  (ef rows of We1|Wa1)
__device__ unsigned g_W2f[4096];   // [K=128][N=64]

__device__ __forceinline__ unsigned ordenc(float f) {
    unsigned u = __float_as_uint(f);
    return (u & 0x80000000u) ? ~u : (u | 0x80000000u);
}
__device__ __forceinline__ float orddec(unsigned u) {
    return __uint_as_float((u & 0x80000000u) ? (u ^ 0x80000000u) : ~u);
}
__device__ __forceinline__ unsigned pack_h2(float a, float b) {
    __half2 h = __floats2half2_rn(a, b);
    return *(unsigned*)&h;
}
__device__ __forceinline__ unsigned addh2_f32(unsigned a, unsigned b) {
    float2 fa = __half22float2(*(__half2*)&a);
    float2 fb = __half22float2(*(__half2*)&b);
    return pack_h2(fa.x + fb.x, fa.y + fb.y);
}

__device__ __forceinline__ void mma_f16(float c[4], const unsigned a[4], uint2 b) {
    asm volatile(
        "mma.sync.aligned.m16n8k16.row.col.f32.f16.f16.f32 "
        "{%0,%1,%2,%3},{%4,%5,%6,%7},{%8,%9},{%0,%1,%2,%3};\n"
        : "+f"(c[0]), "+f"(c[1]), "+f"(c[2]), "+f"(c[3])
        : "r"(a[0]), "r"(a[1]), "r"(a[2]), "r"(a[3]), "r"(b.x), "r"(b.y));
}

// ---------------- weight prep -----------------------------------------------
__global__ void prep_kernel(const float* __restrict__ We1,
                            const float* __restrict__ Wa1,
                            const float* __restrict__ We2) {
    int idx = blockIdx.x * blockDim.x + threadIdx.x;
    if (idx < 8192) {                       // WP/WQ: K=64, N=256 (NBT=32)
        int reg = idx & 1, lane = (idx >> 1) & 31, nbt = (idx >> 6) & 31, kk = idx >> 11;
        int g = lane >> 2, t = lane & 3;
        int n = nbt * 8 + g;
        int k0 = kk * 16 + 2 * t + reg * 8;
        const float* W = (n < 128) ? We1 : Wa1;
        int nc = n & 127;
        g_WPf[idx] = pack_h2(W[k0 * 128 + nc], W[(k0 + 1) * 128 + nc]);
        g_WQf[idx] = pack_h2(W[(k0 + 64) * 128 + nc], W[(k0 + 65) * 128 + nc]);
    } else if (idx < 8192 + 4096) {         // Wc: K=32, N=256 (rows 128..159)
        int i = idx - 8192;
        int reg = i & 1, lane = (i >> 1) & 31, nbt = (i >> 6) & 31, kk = i >> 11;
        int g = lane >> 2, t = lane & 3;
        int n = nbt * 8 + g;
        int k0 = 128 + kk * 16 + 2 * t + reg * 8;
        const float* W = (n < 128) ? We1 : Wa1;
        int nc = n & 127;
        g_Wcf[i] = pack_h2(W[k0 * 128 + nc], W[(k0 + 1) * 128 + nc]);
    } else if (idx < 8192 + 4096 + 4096) {  // W2: K=128, N=64
        int i = idx - 12288;
        int reg = i & 1, lane = (i >> 1) & 31, nbt = (i >> 6) & 7, kk = i >> 9;
        int g = lane >> 2, t = lane & 3;
        int n = nbt * 8 + g;
        int k0 = kk * 16 + 2 * t + reg * 8;
        g_W2f[i] = pack_h2(We2[k0 * 64 + n], We2[(k0 + 1) * 64 + n]);
    }
}

// ---------------- per-node precompute: P = nf@WP, Q = nf@WQ -----------------
__global__ void __launch_bounds__(256, 1)
pq_kernel(const float* __restrict__ nf, int N)
{
    extern __shared__ __align__(16) char dyn[];
    char* sNf = dyn;                              // [128][72] fp16 (stride 144B)
    unsigned* sWP = (unsigned*)(dyn + 18432);     // 32 KB
    unsigned* sWQ = sWP + 8192;                   // 32 KB

    const int tid = threadIdx.x;
    const int lane = tid & 31, wid = tid >> 5;
    const int g = lane >> 2, t = lane & 3;
    const int warp_m = wid & 3, warp_n = wid >> 2;
    const int n0 = blockIdx.x * 128;

    for (int i = tid; i < 2048; i += 256) ((uint4*)sWP)[i] = ((const uint4*)g_WPf)[i];
    for (int i = tid; i < 2048; i += 256) ((uint4*)sWQ)[i] = ((const uint4*)g_WQf)[i];
    for (int idx = tid; idx < 128 * 16; idx += 256) {
        int le = idx >> 4, q = idx & 15;
        int n = n0 + le;
        float4 v = make_float4(0.f, 0.f, 0.f, 0.f);
        if (n < N) v = __ldg((const float4*)(nf + (size_t)n * 64) + q);
        *(uint2*)(sNf + le * 144 + q * 8) = make_uint2(pack_h2(v.x, v.y), pack_h2(v.z, v.w));
    }
    __syncthreads();

    for (int tab = 0; tab < 2; tab++) {
        const uint2* sWu = (const uint2*)(tab ? sWQ : sWP);
        unsigned* gOut = tab ? g_Q : g_P;
        float acc[2][16][4];
#pragma unroll
        for (int mt = 0; mt < 2; mt++)
#pragma unroll
            for (int nb = 0; nb < 16; nb++)
#pragma unroll
                for (int q = 0; q < 4; q++) acc[mt][nb][q] = 0.f;
        unsigned a[2][4];
#pragma unroll
        for (int kk = 0; kk < 4; kk++) {
#pragma unroll
            for (int mt = 0; mt < 2; mt++) {
                int row = warp_m * 32 + mt * 16 + g;
                const char* base = sNf + row * 144 + kk * 32 + 4 * t;
                a[mt][0] = *(const unsigned*)(base);
                a[mt][1] = *(const unsigned*)(base + 8 * 144);
                a[mt][2] = *(const unsigned*)(base + 16);
                a[mt][3] = *(const unsigned*)(base + 8 * 144 + 16);
            }
#pragma unroll
            for (int nb = 0; nb < 16; nb++) {
                uint2 b = sWu[(kk * 32 + warp_n * 16 + nb) * 32 + lane];
                mma_f16(acc[0][nb], a[0], b);
                mma_f16(acc[1][nb], a[1], b);
            }
        }
#pragma unroll
        for (int mt = 0; mt < 2; mt++)
#pragma unroll
            for (int nb = 0; nb < 16; nb++) {
                int c = warp_n * 128 + nb * 8 + 2 * t;
                int r0 = warp_m * 32 + mt * 16 + g;
                if (n0 + r0 < N)
                    gOut[(size_t)(n0 + r0) * 128 + (c >> 1)] = pack_h2(acc[mt][nb][0], acc[mt][nb][1]);
                if (n0 + r0 + 8 < N)
                    gOut[(size_t)(n0 + r0 + 8) * 128 + (c >> 1)] = pack_h2(acc[mt][nb][2], acc[mt][nb][3]);
            }
    }
}

// ---------------- edge kernel: factored, hidden kept in registers ------------
#define oEf 0          // ef tile [128][40]h, stride 80
#define oS  10240      // S tile [128][264]h, stride 528 (64KB data + pad)
#define oW1 77824      // Wc frags 16KB
#define oW2 94208      // W2 frags 16KB
#define EDGE_SMEM 110592

__global__ void __launch_bounds__(256, 2)
edge_kernel(const float* __restrict__ ef_,
            const int* __restrict__ src, const int* __restrict__ dst,
            const float* __restrict__ be1, const float* __restrict__ be2,
            const float* __restrict__ ba1, const float* __restrict__ Wa2,
            const float* __restrict__ ba2,
            float* __restrict__ uh_e, int E)
{
    extern __shared__ __align__(16) char dyn[];
    __shared__ int sSrc[128], sDst[128];

    const int tid = threadIdx.x;
    const int lane = tid & 31, wid = tid >> 5;
    const int g = lane >> 2, t = lane & 3;
    const int e0 = blockIdx.x * 128;

    if (tid < 128)      { int e = e0 + tid;       sSrc[tid]       = (e < E) ? src[e] : 0; }
    else                { int e = e0 + tid - 128; sDst[tid - 128] = (e < E) ? dst[e] : 0; }
    __syncthreads();

    // stage weight frags + ef tile + combined S = P[src] + Q[dst]
    for (int i = tid; i < 1024; i += 256) ((uint4*)(dyn + oW1))[i] = ((const uint4*)g_Wcf)[i];
    for (int i = tid; i < 1024; i += 256) ((uint4*)(dyn + oW2))[i] = ((const uint4*)g_W2f)[i];
    for (int idx = tid; idx < 1024; idx += 256) {
        int le = idx >> 3, q = idx & 7;
        int e = e0 + le;
        float4 v = make_float4(0.f, 0.f, 0.f, 0.f);
        if (e < E) v = __ldg((const float4*)(ef_ + (size_t)e * 32) + q);
        *(uint2*)(dyn + oEf + le * 80 + q * 8) = make_uint2(pack_h2(v.x, v.y), pack_h2(v.z, v.w));
    }
    for (int idx = tid; idx < 4096; idx += 256) {
        int le = idx >> 5, q = idx & 31;
        uint4 p = __ldg((const uint4*)g_P + (size_t)sSrc[le] * 32 + q);
        uint4 qv = __ldg((const uint4*)g_Q + (size_t)sDst[le] * 32 + q);
        uint4 s;
        s.x = addh2_f32(p.x, qv.x); s.y = addh2_f32(p.y, qv.y);
        s.z = addh2_f32(p.z, qv.z); s.w = addh2_f32(p.w, qv.w);
        *(uint4*)(dyn + oS + le * 528 + q * 16) = s;
    }
    __syncthreads();

    const int row0 = wid * 16 + g, row1 = row0 + 8;
    unsigned hpk[16][2];   // packed hidden (A operand for GEMM2)

    // ---- Pass E: edge-hidden cols [0,128) -> registers ----
    {
        float acc[16][4];
#pragma unroll
        for (int nb = 0; nb < 16; nb++)
#pragma unroll
            for (int q = 0; q < 4; q++) acc[nb][q] = 0.f;
        unsigned a[4];
        const uint2* sWu = (const uint2*)(dyn + oW1);
#pragma unroll
        for (int kk = 0; kk < 2; kk++) {
            const char* base = dyn + oEf + row0 * 80 + kk * 32 + 4 * t;
            a[0] = *(const unsigned*)(base);
            a[1] = *(const unsigned*)(base + 8 * 80);
            a[2] = *(const unsigned*)(base + 16);
            a[3] = *(const unsigned*)(base + 8 * 80 + 16);
#pragma unroll
            for (int nb = 0; nb < 16; nb++) {
                uint2 b = sWu[(kk * 32 + nb) * 32 + lane];
                mma_f16(acc[nb], a, b);
            }
        }
#pragma unroll
        for (int nb = 0; nb < 16; nb++) {
            int c = nb * 8 + 2 * t;
            float b0 = __ldg(be1 + c), b1 = __ldg(be1 + c + 1);
            float2 s0 = __half22float2(*(const __half2*)(dyn + oS + row0 * 528 + c * 2));
            float2 s1 = __half22float2(*(const __half2*)(dyn + oS + row1 * 528 + c * 2));
            hpk[nb][0] = pack_h2(fmaxf(acc[nb][0] + s0.x + b0, 0.f),
                                 fmaxf(acc[nb][1] + s0.y + b1, 0.f));
            hpk[nb][1] = pack_h2(fmaxf(acc[nb][2] + s1.x + b0, 0.f),
                                 fmaxf(acc[nb][3] + s1.y + b1, 0.f));
        }
    }

    // ---- Pass A: attn cols [128,256) + logit ----
    {
        float acc[16][4];
#pragma unroll
        for (int nb = 0; nb < 16; nb++)
#pragma unroll
            for (int q = 0; q < 4; q++) acc[nb][q] = 0.f;
        unsigned a[4];
        const uint2* sWu = (const uint2*)(dyn + oW1);
#pragma unroll
        for (int kk = 0; kk < 2; kk++) {
            const char* base = dyn + oEf + row0 * 80 + kk * 32 + 4 * t;
            a[0] = *(const unsigned*)(base);
            a[1] = *(const unsigned*)(base + 8 * 80);
            a[2] = *(const unsigned*)(base + 16);
            a[3] = *(const unsigned*)(base + 8 * 80 + 16);
#pragma unroll
            for (int nb = 0; nb < 16; nb++) {
                uint2 b = sWu[(kk * 32 + 16 + nb) * 32 + lane];
                mma_f16(acc[nb], a, b);
            }
        }
        float l0 = 0.f, l1 = 0.f;
#pragma unroll
        for (int nb = 0; nb < 16; nb++) {
            int c = nb * 8 + 2 * t;
            int off = (128 + c) * 2;
            float b0 = __ldg(ba1 + c), b1 = __ldg(ba1 + c + 1);
            float w0 = __ldg(Wa2 + c), w1 = __ldg(Wa2 + c + 1);
            float2 s0 = __half22float2(*(const __half2*)(dyn + oS + row0 * 528 + off));
            float2 s1 = __half22float2(*(const __half2*)(dyn + oS + row1 * 528 + off));
            l0 += fmaxf(acc[nb][0] + s0.x + b0, 0.f) * w0 + fmaxf(acc[nb][1] + s0.y + b1, 0.f) * w1;
            l1 += fmaxf(acc[nb][2] + s1.x + b0, 0.f) * w0 + fmaxf(acc[nb][3] + s1.y + b1, 0.f) * w1;
        }
#pragma unroll
        for (int off = 1; off <= 2; off <<= 1) {
            l0 += __shfl_xor_sync(0xffffffffu, l0, off);
            l1 += __shfl_xor_sync(0xffffffffu, l1, off);
        }
        if (t == 0) {
            float b2 = __ldg(ba2);
            if (e0 + row0 < E) g_logits[e0 + row0] = l0 + b2;
            if (e0 + row1 < E) g_logits[e0 + row1] = l1 + b2;
        }
    }

    // ---- GEMM2: warp computes rows [wid*16, wid*16+16) x 64 cols; A = hpk ----
    {
        float accO[8][4];
#pragma unroll
        for (int nb = 0; nb < 8; nb++)
#pragma unroll
            for (int q = 0; q < 4; q++) accO[nb][q] = 0.f;
        const uint2* sWu = (const uint2*)(dyn + oW2);
#pragma unroll
        for (int kk = 0; kk < 8; kk++) {
            unsigned a[4] = { hpk[2 * kk][0], hpk[2 * kk][1],
                              hpk[2 * kk + 1][0], hpk[2 * kk + 1][1] };
#pragma unroll
            for (int nb = 0; nb < 8; nb++) {
                uint2 b = sWu[(kk * 8 + nb) * 32 + lane];
                mma_f16(accO[nb], a, b);
            }
        }
#pragma unroll
        for (int nb = 0; nb < 8; nb++) {
            int c = nb * 8 + 2 * t;
            float b0 = __ldg(be2 + c), b1 = __ldg(be2 + c + 1);
            if (e0 + row0 < E)
                *(float2*)(uh_e + (size_t)(e0 + row0) * 64 + c) =
                    make_float2(accO[nb][0] + b0, accO[nb][1] + b1);
            if (e0 + row1 < E)
                *(float2*)(uh_e + (size_t)(e0 + row1) * 64 + c) =
                    make_float2(accO[nb][2] + b0, accO[nb][3] + b1);
        }
    }
}

// ---------------- node kernel (fp32 SIMT, unchanged) ------------------------
#define TILE 128
#define SWP  132
#define SW2P 68
template <int K>
__device__ __forceinline__ void gemm_8x8(const float* __restrict__ sAm, int lda,
                                         const float* __restrict__ sB, int ldb,
                                         int tx, int ty, float acc[8][8]) {
#pragma unroll
    for (int i = 0; i < 8; i++)
#pragma unroll
        for (int j = 0; j < 8; j++) acc[i][j] = 0.f;
#pragma unroll 2
    for (int k = 0; k < K; k++) {
        float a[8];
#pragma unroll
        for (int i = 0; i < 8; i++) a[i] = sAm[(ty * 8 + i) * lda + k];
        float4 b0 = *(const float4*)(sB + k * ldb + tx * 8);
        float4 b1 = *(const float4*)(sB + k * ldb + tx * 8 + 4);
        float b[8] = {b0.x, b0.y, b0.z, b0.w, b1.x, b1.y, b1.z, b1.w};
#pragma unroll
        for (int i = 0; i < 8; i++)
#pragma unroll
            for (int j = 0; j < 8; j++)
                acc[i][j] = fmaf(a[i], b[j], acc[i][j]);
    }
}

__global__ void __launch_bounds__(256, 1)
node_kernel(const float* __restrict__ nf,
            const float* __restrict__ Wn1, const float* __restrict__ bn1,
            const float* __restrict__ Wn2, const float* __restrict__ bn2,
            float* __restrict__ uh_n, int N)
{
    extern __shared__ float smem[];
    float* sIn  = smem;
    float* sW1  = smem + TILE * SWP;
    float* sHid = sW1;
    float* sW2  = sW1 + TILE * SWP;

    const int tid = threadIdx.x;
    const int tx = tid & 15, ty = tid >> 4;
    const int n0 = blockIdx.x * TILE;

    for (int idx = tid; idx < TILE * 32; idx += 256) {
        int ln = idx >> 5, q = idx & 31;
        int n = n0 + ln;
        float4 v = make_float4(0.f, 0.f, 0.f, 0.f);
        if (n < N)
            v = (q < 16) ? __ldg((const float4*)(g_agg + (size_t)n * 64) + q)
                         : __ldg((const float4*)(nf + (size_t)n * 64) + (q - 16));
        *(float4*)(sIn + ln * SWP + q * 4) = v;
    }
    for (int idx = tid; idx < 128 * 32; idx += 256) {
        int r = idx >> 5, c4 = idx & 31;
        *(float4*)(sW1 + r * SWP + c4 * 4) = __ldg((const float4*)Wn1 + idx);
    }
    __syncthreads();

    float acc[8][8];
    gemm_8x8<128>(sIn, SWP, sW1, SWP, tx, ty, acc);
    __syncthreads();

    {
        float4 bb0 = __ldg((const float4*)bn1 + tx * 2);
        float4 bb1 = __ldg((const float4*)bn1 + tx * 2 + 1);
        float bb[8] = {bb0.x, bb0.y, bb0.z, bb0.w, bb1.x, bb1.y, bb1.z, bb1.w};
#pragma unroll
        for (int i = 0; i < 8; i++)
#pragma unroll
            for (int j = 0; j < 8; j++)
                sHid[(ty * 8 + i) * SWP + tx * 8 + j] = fmaxf(acc[i][j] + bb[j], 0.f);
    }
    for (int idx = tid; idx < 128 * 16; idx += 256) {
        int r = idx >> 4, c4 = idx & 15;
        *(float4*)(sW2 + r * SW2P + c4 * 4) = __ldg((const float4*)Wn2 + idx);
    }
    __syncthreads();

    {
        float acc2[8][4];
#pragma unroll
        for (int i = 0; i < 8; i++)
#pragma unroll
            for (int j = 0; j < 4; j++) acc2[i][j] = 0.f;
#pragma unroll 4
        for (int k = 0; k < 128; k++) {
            float a[8];
#pragma unroll
            for (int i = 0; i < 8; i++) a[i] = sHid[(ty * 8 + i) * SWP + k];
            float4 b = *(const float4*)(sW2 + k * SW2P + tx * 4);
#pragma unroll
            for (int i = 0; i < 8; i++) {
                acc2[i][0] = fmaf(a[i], b.x, acc2[i][0]);
                acc2[i][1] = fmaf(a[i], b.y, acc2[i][1]);
                acc2[i][2] = fmaf(a[i], b.z, acc2[i][2]);
                acc2[i][3] = fmaf(a[i], b.w, acc2[i][3]);
            }
        }
        float4 b2 = __ldg((const float4*)bn2 + tx);
#pragma unroll
        for (int i = 0; i < 8; i++) {
            int n = n0 + ty * 8 + i;
            if (n < N) {
                float4 o = make_float4(acc2[i][0] + b2.x, acc2[i][1] + b2.y,
                                       acc2[i][2] + b2.z, acc2[i][3] + b2.w);
                *(float4*)(uh_n + (size_t)n * 64 + tx * 4) = o;
            }
        }
    }
}

// ---------------- softmax / aggregation kernels -----------------------------
__global__ void init_kernel(int N) {
    int t = blockIdx.x * blockDim.x + threadIdx.x;
    if (t < N * 64) g_agg[t] = 0.f;
    if (t < N) { g_denom[t] = 0.f; g_maxb[t] = 0u; }
}
__global__ void max_kernel(const int* __restrict__ dst, int E) {
    int t = blockIdx.x * blockDim.x + threadIdx.x;
    if (t < E) atomicMax(&g_maxb[dst[t]], ordenc(g_logits[t]));
}
__global__ void ex_kernel(const int* __restrict__ dst, int E) {
    int t = blockIdx.x * blockDim.x + threadIdx.x;
    if (t < E) {
        int d = dst[t];
        float m = orddec(g_maxb[d]);
        if (!isfinite(m)) m = 0.f;
        float ex = expf(g_logits[t] - m);
        g_ex[t] = ex;
        atomicAdd(&g_denom[d], ex);
    }
}
__global__ void agg_kernel(const int* __restrict__ dst, const float* __restrict__ uh_e, int E) {
    int t = blockIdx.x * blockDim.x + threadIdx.x;
    int e = t >> 4, lane = t & 15;
    if (e < E) {
        int d = dst[e];
        float attn = g_ex[e] / fmaxf(g_denom[d], 1e-38f);
        float4 u = __ldg((const float4*)(uh_e + (size_t)e * 64) + lane);
        float* p = g_agg + (size_t)d * 64 + lane * 4;
        asm volatile("red.global.add.v4.f32 [%0], {%1,%2,%3,%4};"
                     :: "l"(p), "f"(u.x * attn), "f"(u.y * attn),
                        "f"(u.z * attn), "f"(u.w * attn) : "memory");
    }
}

// ---------------- launch -----------------------------------------------------
extern "C" void kernel_launch(void* const* d_in, const int* in_sizes, int n_in,
                              void* d_out, int out_size)
{
    const float* nf  = (const float*)d_in[0];
    const float* ef  = (const float*)d_in[1];
    const int*   src = (const int*)d_in[2];
    const int*   dst = (const int*)d_in[3];
    const float* We1 = (const float*)d_in[4];
    const float* be1 = (const float*)d_in[5];
    const float* We2 = (const float*)d_in[6];
    const float* be2 = (const float*)d_in[7];
    const float* Wa1 = (const float*)d_in[8];
    const float* ba1 = (const float*)d_in[9];
    const float* Wa2 = (const float*)d_in[10];
    const float* ba2 = (const float*)d_in[11];
    const float* Wn1 = (const float*)d_in[12];
    const float* bn1 = (const float*)d_in[13];
    const float* Wn2 = (const float*)d_in[14];
    const float* bn2 = (const float*)d_in[15];

    const int N = in_sizes[0] / 64;
    const int E = in_sizes[2];

    float* uh_n = (float*)d_out;
    float* uh_e = uh_n + (size_t)N * 64;

    const int PQ_SMEM   = 18432 + 32768 + 32768;                                 // 83968
    const int NODE_SMEM = (TILE * SWP * 2 + TILE * SW2P) * (int)sizeof(float);   // 169984

    cudaFuncSetAttribute(pq_kernel,   cudaFuncAttributeMaxDynamicSharedMemorySize, PQ_SMEM);
    cudaFuncSetAttribute(edge_kernel, cudaFuncAttributeMaxDynamicSharedMemorySize, EDGE_SMEM);
    cudaFuncSetAttribute(node_kernel, cudaFuncAttributeMaxDynamicSharedMemorySize, NODE_SMEM);

    prep_kernel<<<(16384 + 255) / 256, 256>>>(We1, Wa1, We2);
    init_kernel<<<(N * 64 + 255) / 256, 256>>>(N);
    pq_kernel<<<(N + 127) / 128, 256, PQ_SMEM>>>(nf, N);
    edge_kernel<<<(E + 127) / 128, 256, EDGE_SMEM>>>(
        ef, src, dst, be1, be2, ba1, Wa2, ba2, uh_e, E);
    max_kernel<<<(E + 255) / 256, 256>>>(dst, E);
    ex_kernel<<<(E + 255) / 256, 256>>>(dst, E);
    agg_kernel<<<(int)(((size_t)E * 16 + 255) / 256), 256>>>(dst, uh_e, E);
    node_kernel<<<(N + TILE - 1) / TILE, 256, NODE_SMEM>>>(
        nf, Wn1, bn1, Wn2, bn2, uh_n, N);
}

// round 10
// speedup vs baseline: 2.4257x; 1.2190x over previous
#include <cuda_runtime.h>
#include <cuda_fp16.h>
#include <math.h>
#include <stdint.h>

#define NN 50000
#define NE 800000

// ---------------- scratch (static device globals; no allocation) -----------
__device__ float    g_logits[NE];
__device__ float    g_ex[NE];
__device__ float    g_denom[NN];
__device__ unsigned g_maxb[NN];
__device__ float    g_agg[NN * 64];

// P/Q tables: [node][256] fp16. P = nf@[We1s|Wa1s], Q = nf@[We1d|Wa1d]
__device__ unsigned g_P[50048 * 128];
__device__ unsigned g_Q[50048 * 128];

// fp16 fragment images
__device__ unsigned g_WPf[8192];    // [K=64][N=256]
__device__ unsigned g_WQf[8192];    // [K=64][N=256]
__device__ unsigned g_Wcf[4096];    // [K=32][N=256]  (ef rows of We1|Wa1)
__device__ unsigned g_W2f[4096];    // [K=128][N=64]
__device__ unsigned g_Wn1f[8192];   // [K=128][N=128]
__device__ unsigned g_Wn2f[4096];   // [K=128][N=64]

__device__ __forceinline__ unsigned ordenc(float f) {
    unsigned u = __float_as_uint(f);
    return (u & 0x80000000u) ? ~u : (u | 0x80000000u);
}
__device__ __forceinline__ float orddec(unsigned u) {
    return __uint_as_float((u & 0x80000000u) ? (u ^ 0x80000000u) : ~u);
}
__device__ __forceinline__ unsigned pack_h2(float a, float b) {
    __half2 h = __floats2half2_rn(a, b);
    return *(unsigned*)&h;
}
__device__ __forceinline__ unsigned addh2_f32(unsigned a, unsigned b) {
    float2 fa = __half22float2(*(__half2*)&a);
    float2 fb = __half22float2(*(__half2*)&b);
    return pack_h2(fa.x + fb.x, fa.y + fb.y);
}

__device__ __forceinline__ void mma_f16(float c[4], const unsigned a[4], uint2 b) {
    asm volatile(
        "mma.sync.aligned.m16n8k16.row.col.f32.f16.f16.f32 "
        "{%0,%1,%2,%3},{%4,%5,%6,%7},{%8,%9},{%0,%1,%2,%3};\n"
        : "+f"(c[0]), "+f"(c[1]), "+f"(c[2]), "+f"(c[3])
        : "r"(a[0]), "r"(a[1]), "r"(a[2]), "r"(a[3]), "r"(b.x), "r"(b.y));
}

// ---------------- weight prep -----------------------------------------------
__global__ void prep_kernel(const float* __restrict__ We1,
                            const float* __restrict__ Wa1,
                            const float* __restrict__ We2,
                            const float* __restrict__ Wn1,
                            const float* __restrict__ Wn2) {
    int idx = blockIdx.x * blockDim.x + threadIdx.x;
    if (idx < 8192) {                       // WP/WQ: K=64, N=256 (NBT=32)
        int reg = idx & 1, lane = (idx >> 1) & 31, nbt = (idx >> 6) & 31, kk = idx >> 11;
        int g = lane >> 2, t = lane & 3;
        int n = nbt * 8 + g;
        int k0 = kk * 16 + 2 * t + reg * 8;
        const float* W = (n < 128) ? We1 : Wa1;
        int nc = n & 127;
        g_WPf[idx] = pack_h2(W[k0 * 128 + nc], W[(k0 + 1) * 128 + nc]);
        g_WQf[idx] = pack_h2(W[(k0 + 64) * 128 + nc], W[(k0 + 65) * 128 + nc]);
    } else if (idx < 12288) {               // Wc: K=32, N=256 (rows 128..159)
        int i = idx - 8192;
        int reg = i & 1, lane = (i >> 1) & 31, nbt = (i >> 6) & 31, kk = i >> 11;
        int g = lane >> 2, t = lane & 3;
        int n = nbt * 8 + g;
        int k0 = 128 + kk * 16 + 2 * t + reg * 8;
        const float* W = (n < 128) ? We1 : Wa1;
        int nc = n & 127;
        g_Wcf[i] = pack_h2(W[k0 * 128 + nc], W[(k0 + 1) * 128 + nc]);
    } else if (idx < 16384) {               // W2e: K=128, N=64
        int i = idx - 12288;
        int reg = i & 1, lane = (i >> 1) & 31, nbt = (i >> 6) & 7, kk = i >> 9;
        int g = lane >> 2, t = lane & 3;
        int n = nbt * 8 + g;
        int k0 = kk * 16 + 2 * t + reg * 8;
        g_W2f[i] = pack_h2(We2[k0 * 64 + n], We2[(k0 + 1) * 64 + n]);
    } else if (idx < 24576) {               // Wn1: K=128, N=128 (NBT=16)
        int i = idx - 16384;
        int reg = i & 1, lane = (i >> 1) & 31, nbt = (i >> 6) & 15, kk = i >> 10;
        int g = lane >> 2, t = lane & 3;
        int n = nbt * 8 + g;
        int k0 = kk * 16 + 2 * t + reg * 8;
        g_Wn1f[i] = pack_h2(Wn1[k0 * 128 + n], Wn1[(k0 + 1) * 128 + n]);
    } else if (idx < 28672) {               // Wn2: K=128, N=64
        int i = idx - 24576;
        int reg = i & 1, lane = (i >> 1) & 31, nbt = (i >> 6) & 7, kk = i >> 9;
        int g = lane >> 2, t = lane & 3;
        int n = nbt * 8 + g;
        int k0 = kk * 16 + 2 * t + reg * 8;
        g_Wn2f[i] = pack_h2(Wn2[k0 * 64 + n], Wn2[(k0 + 1) * 64 + n]);
    }
}

// ---------------- per-node precompute: P = nf@WP, Q = nf@WQ -----------------
__global__ void __launch_bounds__(256, 1)
pq_kernel(const float* __restrict__ nf, int N)
{
    extern __shared__ __align__(16) char dyn[];
    char* sNf = dyn;                              // [128][72] fp16 (stride 144B)
    unsigned* sWP = (unsigned*)(dyn + 18432);     // 32 KB
    unsigned* sWQ = sWP + 8192;                   // 32 KB

    const int tid = threadIdx.x;
    const int lane = tid & 31, wid = tid >> 5;
    const int g = lane >> 2, t = lane & 3;
    const int warp_m = wid & 3, warp_n = wid >> 2;
    const int n0 = blockIdx.x * 128;

    for (int i = tid; i < 2048; i += 256) ((uint4*)sWP)[i] = ((const uint4*)g_WPf)[i];
    for (int i = tid; i < 2048; i += 256) ((uint4*)sWQ)[i] = ((const uint4*)g_WQf)[i];
    for (int idx = tid; idx < 128 * 16; idx += 256) {
        int le = idx >> 4, q = idx & 15;
        int n = n0 + le;
        float4 v = make_float4(0.f, 0.f, 0.f, 0.f);
        if (n < N) v = __ldg((const float4*)(nf + (size_t)n * 64) + q);
        *(uint2*)(sNf + le * 144 + q * 8) = make_uint2(pack_h2(v.x, v.y), pack_h2(v.z, v.w));
    }
    __syncthreads();

    for (int tab = 0; tab < 2; tab++) {
        const uint2* sWu = (const uint2*)(tab ? sWQ : sWP);
        unsigned* gOut = tab ? g_Q : g_P;
        float acc[2][16][4];
#pragma unroll
        for (int mt = 0; mt < 2; mt++)
#pragma unroll
            for (int nb = 0; nb < 16; nb++)
#pragma unroll
                for (int q = 0; q < 4; q++) acc[mt][nb][q] = 0.f;
        unsigned a[2][4];
#pragma unroll
        for (int kk = 0; kk < 4; kk++) {
#pragma unroll
            for (int mt = 0; mt < 2; mt++) {
                int row = warp_m * 32 + mt * 16 + g;
                const char* base = sNf + row * 144 + kk * 32 + 4 * t;
                a[mt][0] = *(const unsigned*)(base);
                a[mt][1] = *(const unsigned*)(base + 8 * 144);
                a[mt][2] = *(const unsigned*)(base + 16);
                a[mt][3] = *(const unsigned*)(base + 8 * 144 + 16);
            }
#pragma unroll
            for (int nb = 0; nb < 16; nb++) {
                uint2 b = sWu[(kk * 32 + warp_n * 16 + nb) * 32 + lane];
                mma_f16(acc[0][nb], a[0], b);
                mma_f16(acc[1][nb], a[1], b);
            }
        }
#pragma unroll
        for (int mt = 0; mt < 2; mt++)
#pragma unroll
            for (int nb = 0; nb < 16; nb++) {
                int c = warp_n * 128 + nb * 8 + 2 * t;
                int r0 = warp_m * 32 + mt * 16 + g;
                if (n0 + r0 < N)
                    gOut[(size_t)(n0 + r0) * 128 + (c >> 1)] = pack_h2(acc[mt][nb][0], acc[mt][nb][1]);
                if (n0 + r0 + 8 < N)
                    gOut[(size_t)(n0 + r0 + 8) * 128 + (c >> 1)] = pack_h2(acc[mt][nb][2], acc[mt][nb][3]);
            }
    }
}

// ---------------- edge kernel (R8 structure: hidden via smem, 2 CTAs/SM) ----
#define oEf 0          // ef tile [128][40]h, stride 80
#define oS  10240      // S tile [128][264]h, stride 528
#define oW1 77824      // Wc frags 16KB
#define oW2 94208      // W2 frags 16KB
#define EDGE_SMEM 110592

__global__ void __launch_bounds__(256, 2)
edge_kernel(const float* __restrict__ ef_,
            const int* __restrict__ src, const int* __restrict__ dst,
            const float* __restrict__ be1, const float* __restrict__ be2,
            const float* __restrict__ ba1, const float* __restrict__ Wa2,
            const float* __restrict__ ba2,
            float* __restrict__ uh_e, int E)
{
    extern __shared__ __align__(16) char dyn[];
    __shared__ int sSrc[128], sDst[128];

    const int tid = threadIdx.x;
    const int lane = tid & 31, wid = tid >> 5;
    const int g = lane >> 2, t = lane & 3;
    const int e0 = blockIdx.x * 128;

    if (tid < 128)      { int e = e0 + tid;       sSrc[tid]       = (e < E) ? src[e] : 0; }
    else                { int e = e0 + tid - 128; sDst[tid - 128] = (e < E) ? dst[e] : 0; }
    __syncthreads();

    for (int i = tid; i < 1024; i += 256) ((uint4*)(dyn + oW1))[i] = ((const uint4*)g_Wcf)[i];
    for (int i = tid; i < 1024; i += 256) ((uint4*)(dyn + oW2))[i] = ((const uint4*)g_W2f)[i];
    for (int idx = tid; idx < 1024; idx += 256) {
        int le = idx >> 3, q = idx & 7;
        int e = e0 + le;
        float4 v = make_float4(0.f, 0.f, 0.f, 0.f);
        if (e < E) v = __ldg((const float4*)(ef_ + (size_t)e * 32) + q);
        *(uint2*)(dyn + oEf + le * 80 + q * 8) = make_uint2(pack_h2(v.x, v.y), pack_h2(v.z, v.w));
    }
    for (int idx = tid; idx < 4096; idx += 256) {
        int le = idx >> 5, q = idx & 31;
        uint4 p = __ldg((const uint4*)g_P + (size_t)sSrc[le] * 32 + q);
        uint4 qv = __ldg((const uint4*)g_Q + (size_t)sDst[le] * 32 + q);
        uint4 s;
        s.x = addh2_f32(p.x, qv.x); s.y = addh2_f32(p.y, qv.y);
        s.z = addh2_f32(p.z, qv.z); s.w = addh2_f32(p.w, qv.w);
        *(uint4*)(dyn + oS + le * 528 + q * 16) = s;
    }
    __syncthreads();

    const int row0 = wid * 16 + g, row1 = row0 + 8;

    // ---- Pass E: edge-hidden cols [0,128), written in place into S ----
    {
        float acc[16][4];
#pragma unroll
        for (int nb = 0; nb < 16; nb++)
#pragma unroll
            for (int q = 0; q < 4; q++) acc[nb][q] = 0.f;
        unsigned a[4];
        const uint2* sWu = (const uint2*)(dyn + oW1);
#pragma unroll
        for (int kk = 0; kk < 2; kk++) {
            const char* base = dyn + oEf + row0 * 80 + kk * 32 + 4 * t;
            a[0] = *(const unsigned*)(base);
            a[1] = *(const unsigned*)(base + 8 * 80);
            a[2] = *(const unsigned*)(base + 16);
            a[3] = *(const unsigned*)(base + 8 * 80 + 16);
#pragma unroll
            for (int nb = 0; nb < 16; nb++) {
                uint2 b = sWu[(kk * 32 + nb) * 32 + lane];
                mma_f16(acc[nb], a, b);
            }
        }
#pragma unroll
        for (int nb = 0; nb < 16; nb++) {
            int c = nb * 8 + 2 * t;
            float b0 = __ldg(be1 + c), b1 = __ldg(be1 + c + 1);
            float2 s0 = __half22float2(*(const __half2*)(dyn + oS + row0 * 528 + c * 2));
            float2 s1 = __half22float2(*(const __half2*)(dyn + oS + row1 * 528 + c * 2));
            *(unsigned*)(dyn + oS + row0 * 528 + c * 2) =
                pack_h2(fmaxf(acc[nb][0] + s0.x + b0, 0.f), fmaxf(acc[nb][1] + s0.y + b1, 0.f));
            *(unsigned*)(dyn + oS + row1 * 528 + c * 2) =
                pack_h2(fmaxf(acc[nb][2] + s1.x + b0, 0.f), fmaxf(acc[nb][3] + s1.y + b1, 0.f));
        }
    }

    // ---- Pass A: attn cols [128,256) + logit ----
    {
        float acc[16][4];
#pragma unroll
        for (int nb = 0; nb < 16; nb++)
#pragma unroll
            for (int q = 0; q < 4; q++) acc[nb][q] = 0.f;
        unsigned a[4];
        const uint2* sWu = (const uint2*)(dyn + oW1);
#pragma unroll
        for (int kk = 0; kk < 2; kk++) {
            const char* base = dyn + oEf + row0 * 80 + kk * 32 + 4 * t;
            a[0] = *(const unsigned*)(base);
            a[1] = *(const unsigned*)(base + 8 * 80);
            a[2] = *(const unsigned*)(base + 16);
            a[3] = *(const unsigned*)(base + 8 * 80 + 16);
#pragma unroll
            for (int nb = 0; nb < 16; nb++) {
                uint2 b = sWu[(kk * 32 + 16 + nb) * 32 + lane];
                mma_f16(acc[nb], a, b);
            }
        }
        float l0 = 0.f, l1 = 0.f;
#pragma unroll
        for (int nb = 0; nb < 16; nb++) {
            int c = nb * 8 + 2 * t;
            int off = (128 + c) * 2;
            float b0 = __ldg(ba1 + c), b1 = __ldg(ba1 + c + 1);
            float w0 = __ldg(Wa2 + c), w1 = __ldg(Wa2 + c + 1);
            float2 s0 = __half22float2(*(const __half2*)(dyn + oS + row0 * 528 + off));
            float2 s1 = __half22float2(*(const __half2*)(dyn + oS + row1 * 528 + off));
            l0 += fmaxf(acc[nb][0] + s0.x + b0, 0.f) * w0 + fmaxf(acc[nb][1] + s0.y + b1, 0.f) * w1;
            l1 += fmaxf(acc[nb][2] + s1.x + b0, 0.f) * w0 + fmaxf(acc[nb][3] + s1.y + b1, 0.f) * w1;
        }
#pragma unroll
        for (int off = 1; off <= 2; off <<= 1) {
            l0 += __shfl_xor_sync(0xffffffffu, l0, off);
            l1 += __shfl_xor_sync(0xffffffffu, l1, off);
        }
        if (t == 0) {
            float b2 = __ldg(ba2);
            if (e0 + row0 < E) g_logits[e0 + row0] = l0 + b2;
            if (e0 + row1 < E) g_logits[e0 + row1] = l1 + b2;
        }
    }
    __syncthreads();   // hidden H (in S region) visible to all warps

    // ---- GEMM2: H[128x128] x W2[128x64] -> uh_e ----
    {
        const int warp_m = wid & 3, warp_n = wid >> 2;
        float accO[2][4][4];
#pragma unroll
        for (int mt = 0; mt < 2; mt++)
#pragma unroll
            for (int nb = 0; nb < 4; nb++)
#pragma unroll
                for (int q = 0; q < 4; q++) accO[mt][nb][q] = 0.f;
        unsigned a[2][4];
        const uint2* sWu = (const uint2*)(dyn + oW2);
#pragma unroll
        for (int kk = 0; kk < 8; kk++) {
#pragma unroll
            for (int mt = 0; mt < 2; mt++) {
                int row = warp_m * 32 + mt * 16 + g;
                const char* base = dyn + oS + row * 528 + kk * 32 + 4 * t;
                a[mt][0] = *(const unsigned*)(base);
                a[mt][1] = *(const unsigned*)(base + 8 * 528);
                a[mt][2] = *(const unsigned*)(base + 16);
                a[mt][3] = *(const unsigned*)(base + 8 * 528 + 16);
            }
#pragma unroll
            for (int nb = 0; nb < 4; nb++) {
                uint2 b = sWu[(kk * 8 + warp_n * 4 + nb) * 32 + lane];
                mma_f16(accO[0][nb], a[0], b);
                mma_f16(accO[1][nb], a[1], b);
            }
        }
#pragma unroll
        for (int mt = 0; mt < 2; mt++)
#pragma unroll
            for (int nb = 0; nb < 4; nb++) {
                int c = warp_n * 32 + nb * 8 + 2 * t;
                float b0 = __ldg(be2 + c), b1 = __ldg(be2 + c + 1);
                int r0 = warp_m * 32 + mt * 16 + g;
                int e = e0 + r0;
                if (e < E)
                    *(float2*)(uh_e + (size_t)e * 64 + c) =
                        make_float2(accO[mt][nb][0] + b0, accO[mt][nb][1] + b1);
                if (e + 8 < E)
                    *(float2*)(uh_e + (size_t)(e + 8) * 64 + c) =
                        make_float2(accO[mt][nb][2] + b0, accO[mt][nb][3] + b1);
            }
    }
}

// ---------------- node kernel: fp16 HMMA, 2 CTAs/SM --------------------------
#define oNi  0          // in/hidden tile [128][136]h, stride 272 (34816 B)
#define oNW1 34816      // Wn1 frags 32 KB
#define oNW2 67584      // Wn2 frags 16 KB
#define NODE_SMEM 83968

__global__ void __launch_bounds__(256, 2)
node_kernel(const float* __restrict__ nf,
            const float* __restrict__ bn1, const float* __restrict__ bn2,
            float* __restrict__ uh_n, int N)
{
    extern __shared__ __align__(16) char dyn[];

    const int tid = threadIdx.x;
    const int lane = tid & 31, wid = tid >> 5;
    const int g = lane >> 2, t = lane & 3;
    const int warp_m = wid & 3, warp_n = wid >> 2;
    const int n0 = blockIdx.x * 128;

    for (int i = tid; i < 2048; i += 256) ((uint4*)(dyn + oNW1))[i] = ((const uint4*)g_Wn1f)[i];
    for (int i = tid; i < 1024; i += 256) ((uint4*)(dyn + oNW2))[i] = ((const uint4*)g_Wn2f)[i];
    // gather in = [agg | nf] -> fp16
    for (int idx = tid; idx < 4096; idx += 256) {
        int le = idx >> 5, q = idx & 31;
        int n = n0 + le;
        float4 v = make_float4(0.f, 0.f, 0.f, 0.f);
        if (n < N)
            v = (q < 16) ? __ldg((const float4*)(g_agg + (size_t)n * 64) + q)
                         : __ldg((const float4*)(nf + (size_t)n * 64) + (q - 16));
        *(uint2*)(dyn + oNi + le * 272 + q * 8) = make_uint2(pack_h2(v.x, v.y), pack_h2(v.z, v.w));
    }
    __syncthreads();

    // ---- GEMM1: in[128x128] x Wn1[128x128] ----
    float acc[2][8][4];
#pragma unroll
    for (int mt = 0; mt < 2; mt++)
#pragma unroll
        for (int nb = 0; nb < 8; nb++)
#pragma unroll
            for (int q = 0; q < 4; q++) acc[mt][nb][q] = 0.f;
    {
        unsigned a[2][4];
        const uint2* sWu = (const uint2*)(dyn + oNW1);
#pragma unroll
        for (int kk = 0; kk < 8; kk++) {
#pragma unroll
            for (int mt = 0; mt < 2; mt++) {
                int row = warp_m * 32 + mt * 16 + g;
                const char* base = dyn + oNi + row * 272 + kk * 32 + 4 * t;
                a[mt][0] = *(const unsigned*)(base);
                a[mt][1] = *(const unsigned*)(base + 8 * 272);
                a[mt][2] = *(const unsigned*)(base + 16);
                a[mt][3] = *(const unsigned*)(base + 8 * 272 + 16);
            }
#pragma unroll
            for (int nb = 0; nb < 8; nb++) {
                uint2 b = sWu[(kk * 16 + warp_n * 8 + nb) * 32 + lane];
                mma_f16(acc[0][nb], a[0], b);
                mma_f16(acc[1][nb], a[1], b);
            }
        }
    }
    __syncthreads();   // all GEMM1 reads of sIn done before in-place overwrite

    // hidden = relu(acc + bn1) -> fp16, in place (cols 0..127)
#pragma unroll
    for (int mt = 0; mt < 2; mt++)
#pragma unroll
        for (int nb = 0; nb < 8; nb++) {
            int c = warp_n * 64 + nb * 8 + 2 * t;
            float b0 = __ldg(bn1 + c), b1 = __ldg(bn1 + c + 1);
            int r0 = warp_m * 32 + mt * 16 + g;
            *(unsigned*)(dyn + oNi + r0 * 272 + c * 2) =
                pack_h2(fmaxf(acc[mt][nb][0] + b0, 0.f), fmaxf(acc[mt][nb][1] + b1, 0.f));
            *(unsigned*)(dyn + oNi + (r0 + 8) * 272 + c * 2) =
                pack_h2(fmaxf(acc[mt][nb][2] + b0, 0.f), fmaxf(acc[mt][nb][3] + b1, 0.f));
        }
    __syncthreads();

    // ---- GEMM2: hidden[128x128] x Wn2[128x64] -> uh_n ----
    {
        float accO[2][4][4];
#pragma unroll
        for (int mt = 0; mt < 2; mt++)
#pragma unroll
            for (int nb = 0; nb < 4; nb++)
#pragma unroll
                for (int q = 0; q < 4; q++) accO[mt][nb][q] = 0.f;
        unsigned a[2][4];
        const uint2* sWu = (const uint2*)(dyn + oNW2);
#pragma unroll
        for (int kk = 0; kk < 8; kk++) {
#pragma unroll
            for (int mt = 0; mt < 2; mt++) {
                int row = warp_m * 32 + mt * 16 + g;
                const char* base = dyn + oNi + row * 272 + kk * 32 + 4 * t;
                a[mt][0] = *(const unsigned*)(base);
                a[mt][1] = *(const unsigned*)(base + 8 * 272);
                a[mt][2] = *(const unsigned*)(base + 16);
                a[mt][3] = *(const unsigned*)(base + 8 * 272 + 16);
            }
#pragma unroll
            for (int nb = 0; nb < 4; nb++) {
                uint2 b = sWu[(kk * 8 + warp_n * 4 + nb) * 32 + lane];
                mma_f16(accO[0][nb], a[0], b);
                mma_f16(accO[1][nb], a[1], b);
            }
        }
#pragma unroll
        for (int mt = 0; mt < 2; mt++)
#pragma unroll
            for (int nb = 0; nb < 4; nb++) {
                int c = warp_n * 32 + nb * 8 + 2 * t;
                float b0 = __ldg(bn2 + c), b1 = __ldg(bn2 + c + 1);
                int r0 = warp_m * 32 + mt * 16 + g;
                int n = n0 + r0;
                if (n < N)
                    *(float2*)(uh_n + (size_t)n * 64 + c) =
                        make_float2(accO[mt][nb][0] + b0, accO[mt][nb][1] + b1);
                if (n + 8 < N)
                    *(float2*)(uh_n + (size_t)(n + 8) * 64 + c) =
                        make_float2(accO[mt][nb][2] + b0, accO[mt][nb][3] + b1);
            }
    }
}

// ---------------- softmax / aggregation kernels -----------------------------
__global__ void init_kernel(int N) {
    int t = blockIdx.x * blockDim.x + threadIdx.x;
    if (t < N * 16) ((float4*)g_agg)[t] = make_float4(0.f, 0.f, 0.f, 0.f);
    if (t < N) { g_denom[t] = 0.f; g_maxb[t] = 0u; }
}
__global__ void max_kernel(const int* __restrict__ dst, int E) {
    int t = blockIdx.x * blockDim.x + threadIdx.x;
    if (t < E) atomicMax(&g_maxb[dst[t]], ordenc(g_logits[t]));
}
__global__ void ex_kernel(const int* __restrict__ dst, int E) {
    int t = blockIdx.x * blockDim.x + threadIdx.x;
    if (t < E) {
        int d = dst[t];
        float m = orddec(g_maxb[d]);
        if (!isfinite(m)) m = 0.f;
        float ex = expf(g_logits[t] - m);
        g_ex[t] = ex;
        atomicAdd(&g_denom[d], ex);
    }
}
__global__ void agg_kernel(const int* __restrict__ dst, const float* __restrict__ uh_e, int E) {
    int t = blockIdx.x * blockDim.x + threadIdx.x;
    int e = t >> 4, lane = t & 15;
    if (e < E) {
        int d = dst[e];
        float attn = g_ex[e] / fmaxf(g_denom[d], 1e-38f);
        float4 u = __ldg((const float4*)(uh_e + (size_t)e * 64) + lane);
        float* p = g_agg + (size_t)d * 64 + lane * 4;
        asm volatile("red.global.add.v4.f32 [%0], {%1,%2,%3,%4};"
                     :: "l"(p), "f"(u.x * attn), "f"(u.y * attn),
                        "f"(u.z * attn), "f"(u.w * attn) : "memory");
    }
}

// ---------------- launch -----------------------------------------------------
extern "C" void kernel_launch(void* const* d_in, const int* in_sizes, int n_in,
                              void* d_out, int out_size)
{
    const float* nf  = (const float*)d_in[0];
    const float* ef  = (const float*)d_in[1];
    const int*   src = (const int*)d_in[2];
    const int*   dst = (const int*)d_in[3];
    const float* We1 = (const float*)d_in[4];
    const float* be1 = (const float*)d_in[5];
    const float* We2 = (const float*)d_in[6];
    const float* be2 = (const float*)d_in[7];
    const float* Wa1 = (const float*)d_in[8];
    const float* ba1 = (const float*)d_in[9];
    const float* Wa2 = (const float*)d_in[10];
    const float* ba2 = (const float*)d_in[11];
    const float* Wn1 = (const float*)d_in[12];
    const float* bn1 = (const float*)d_in[13];
    const float* Wn2 = (const float*)d_in[14];
    const float* bn2 = (const float*)d_in[15];

    const int N = in_sizes[0] / 64;
    const int E = in_sizes[2];

    float* uh_n = (float*)d_out;
    float* uh_e = uh_n + (size_t)N * 64;

    const int PQ_SMEM = 18432 + 32768 + 32768;   // 83968

    cudaFuncSetAttribute(pq_kernel,   cudaFuncAttributeMaxDynamicSharedMemorySize, PQ_SMEM);
    cudaFuncSetAttribute(edge_kernel, cudaFuncAttributeMaxDynamicSharedMemorySize, EDGE_SMEM);
    cudaFuncSetAttribute(node_kernel, cudaFuncAttributeMaxDynamicSharedMemorySize, NODE_SMEM);

    prep_kernel<<<(28672 + 255) / 256, 256>>>(We1, Wa1, We2, Wn1, Wn2);
    init_kernel<<<(N * 16 + 255) / 256, 256>>>(N);
    pq_kernel<<<(N + 127) / 128, 256, PQ_SMEM>>>(nf, N);
    edge_kernel<<<(E + 127) / 128, 256, EDGE_SMEM>>>(
        ef, src, dst, be1, be2, ba1, Wa2, ba2, uh_e, E);
    max_kernel<<<(E + 255) / 256, 256>>>(dst, E);
    ex_kernel<<<(E + 255) / 256, 256>>>(dst, E);
    agg_kernel<<<(int)(((size_t)E * 16 + 255) / 256), 256>>>(dst, uh_e, E);
    node_kernel<<<(N + 127) / 128, 256, NODE_SMEM>>>(nf, bn1, bn2, uh_n, N);
}

// round 12
// speedup vs baseline: 2.8463x; 1.1734x over previous
#include <cuda_runtime.h>
#include <cuda_fp16.h>
#include <math.h>
#include <stdint.h>

#define NN 50000
#define NE 800000

// ---------------- scratch (static device globals; no allocation) -----------
__device__ float    g_ex[NE];
__device__ float    g_denom[NN];
__device__ float    g_agg[NN * 64];

// P/Q tables: [node][256] fp16. P = nf@[We1s|Wa1s], Q = nf@[We1d|Wa1d]
__device__ unsigned g_P[50048 * 128];
__device__ unsigned g_Q[50048 * 128];

// fp16 fragment images
__device__ unsigned g_WPf[8192];    // [K=64][N=256]
__device__ unsigned g_WQf[8192];    // [K=64][N=256]
__device__ unsigned g_Wcf[4096];    // [K=32][N=256]  (ef rows of We1|Wa1)
__device__ unsigned g_W2f[4096];    // [K=128][N=64]
__device__ unsigned g_Wn1f[8192];   // [K=128][N=128]
__device__ unsigned g_Wn2f[4096];   // [K=128][N=64]

__device__ __forceinline__ unsigned pack_h2(float a, float b) {
    __half2 h = __floats2half2_rn(a, b);
    return *(unsigned*)&h;
}
__device__ __forceinline__ unsigned addh2_f32(unsigned a, unsigned b) {
    float2 fa = __half22float2(*(__half2*)&a);
    float2 fb = __half22float2(*(__half2*)&b);
    return pack_h2(fa.x + fb.x, fa.y + fb.y);
}

__device__ __forceinline__ void mma_f16(float c[4], const unsigned a[4], uint2 b) {
    asm volatile(
        "mma.sync.aligned.m16n8k16.row.col.f32.f16.f16.f32 "
        "{%0,%1,%2,%3},{%4,%5,%6,%7},{%8,%9},{%0,%1,%2,%3};\n"
        : "+f"(c[0]), "+f"(c[1]), "+f"(c[2]), "+f"(c[3])
        : "r"(a[0]), "r"(a[1]), "r"(a[2]), "r"(a[3]), "r"(b.x), "r"(b.y));
}

// ---------------- weight prep -----------------------------------------------
__global__ void prep_kernel(const float* __restrict__ We1,
                            const float* __restrict__ Wa1,
                            const float* __restrict__ We2,
                            const float* __restrict__ Wn1,
                            const float* __restrict__ Wn2) {
    int idx = blockIdx.x * blockDim.x + threadIdx.x;
    if (idx < 8192) {                       // WP/WQ: K=64, N=256 (NBT=32)
        int reg = idx & 1, lane = (idx >> 1) & 31, nbt = (idx >> 6) & 31, kk = idx >> 11;
        int g = lane >> 2, t = lane & 3;
        int n = nbt * 8 + g;
        int k0 = kk * 16 + 2 * t + reg * 8;
        const float* W = (n < 128) ? We1 : Wa1;
        int nc = n & 127;
        g_WPf[idx] = pack_h2(W[k0 * 128 + nc], W[(k0 + 1) * 128 + nc]);
        g_WQf[idx] = pack_h2(W[(k0 + 64) * 128 + nc], W[(k0 + 65) * 128 + nc]);
    } else if (idx < 12288) {               // Wc: K=32, N=256 (rows 128..159)
        int i = idx - 8192;
        int reg = i & 1, lane = (i >> 1) & 31, nbt = (i >> 6) & 31, kk = i >> 11;
        int g = lane >> 2, t = lane & 3;
        int n = nbt * 8 + g;
        int k0 = 128 + kk * 16 + 2 * t + reg * 8;
        const float* W = (n < 128) ? We1 : Wa1;
        int nc = n & 127;
        g_Wcf[i] = pack_h2(W[k0 * 128 + nc], W[(k0 + 1) * 128 + nc]);
    } else if (idx < 16384) {               // W2e: K=128, N=64
        int i = idx - 12288;
        int reg = i & 1, lane = (i >> 1) & 31, nbt = (i >> 6) & 7, kk = i >> 9;
        int g = lane >> 2, t = lane & 3;
        int n = nbt * 8 + g;
        int k0 = kk * 16 + 2 * t + reg * 8;
        g_W2f[i] = pack_h2(We2[k0 * 64 + n], We2[(k0 + 1) * 64 + n]);
    } else if (idx < 24576) {               // Wn1: K=128, N=128 (NBT=16)
        int i = idx - 16384;
        int reg = i & 1, lane = (i >> 1) & 31, nbt = (i >> 6) & 15, kk = i >> 10;
        int g = lane >> 2, t = lane & 3;
        int n = nbt * 8 + g;
        int k0 = kk * 16 + 2 * t + reg * 8;
        g_Wn1f[i] = pack_h2(Wn1[k0 * 128 + n], Wn1[(k0 + 1) * 128 + n]);
    } else if (idx < 28672) {               // Wn2: K=128, N=64
        int i = idx - 24576;
        int reg = i & 1, lane = (i >> 1) & 31, nbt = (i >> 6) & 7, kk = i >> 9;
        int g = lane >> 2, t = lane & 3;
        int n = nbt * 8 + g;
        int k0 = kk * 16 + 2 * t + reg * 8;
        g_Wn2f[i] = pack_h2(Wn2[k0 * 64 + n], Wn2[(k0 + 1) * 64 + n]);
    }
}

// ---------------- per-node precompute: P = nf@WP, Q = nf@WQ -----------------
__global__ void __launch_bounds__(256, 1)
pq_kernel(const float* __restrict__ nf, int N)
{
    extern __shared__ __align__(16) char dyn[];
    char* sNf = dyn;                              // [128][72] fp16 (stride 144B)
    unsigned* sWP = (unsigned*)(dyn + 18432);     // 32 KB
    unsigned* sWQ = sWP + 8192;                   // 32 KB

    const int tid = threadIdx.x;
    const int lane = tid & 31, wid = tid >> 5;
    const int g = lane >> 2, t = lane & 3;
    const int warp_m = wid & 3, warp_n = wid >> 2;
    const int n0 = blockIdx.x * 128;

    for (int i = tid; i < 2048; i += 256) ((uint4*)sWP)[i] = ((const uint4*)g_WPf)[i];
    for (int i = tid; i < 2048; i += 256) ((uint4*)sWQ)[i] = ((const uint4*)g_WQf)[i];
    for (int idx = tid; idx < 128 * 16; idx += 256) {
        int le = idx >> 4, q = idx & 15;
        int n = n0 + le;
        float4 v = make_float4(0.f, 0.f, 0.f, 0.f);
        if (n < N) v = __ldg((const float4*)(nf + (size_t)n * 64) + q);
        *(uint2*)(sNf + le * 144 + q * 8) = make_uint2(pack_h2(v.x, v.y), pack_h2(v.z, v.w));
    }
    __syncthreads();

    for (int tab = 0; tab < 2; tab++) {
        const uint2* sWu = (const uint2*)(tab ? sWQ : sWP);
        unsigned* gOut = tab ? g_Q : g_P;
        float acc[2][16][4];
#pragma unroll
        for (int mt = 0; mt < 2; mt++)
#pragma unroll
            for (int nb = 0; nb < 16; nb++)
#pragma unroll
                for (int q = 0; q < 4; q++) acc[mt][nb][q] = 0.f;
        unsigned a[2][4];
#pragma unroll
        for (int kk = 0; kk < 4; kk++) {
#pragma unroll
            for (int mt = 0; mt < 2; mt++) {
                int row = warp_m * 32 + mt * 16 + g;
                const char* base = sNf + row * 144 + kk * 32 + 4 * t;
                a[mt][0] = *(const unsigned*)(base);
                a[mt][1] = *(const unsigned*)(base + 8 * 144);
                a[mt][2] = *(const unsigned*)(base + 16);
                a[mt][3] = *(const unsigned*)(base + 8 * 144 + 16);
            }
#pragma unroll
            for (int nb = 0; nb < 16; nb++) {
                uint2 b = sWu[(kk * 32 + warp_n * 16 + nb) * 32 + lane];
                mma_f16(acc[0][nb], a[0], b);
                mma_f16(acc[1][nb], a[1], b);
            }
        }
#pragma unroll
        for (int mt = 0; mt < 2; mt++)
#pragma unroll
            for (int nb = 0; nb < 16; nb++) {
                int c = warp_n * 128 + nb * 8 + 2 * t;
                int r0 = warp_m * 32 + mt * 16 + g;
                if (n0 + r0 < N)
                    gOut[(size_t)(n0 + r0) * 128 + (c >> 1)] = pack_h2(acc[mt][nb][0], acc[mt][nb][1]);
                if (n0 + r0 + 8 < N)
                    gOut[(size_t)(n0 + r0 + 8) * 128 + (c >> 1)] = pack_h2(acc[mt][nb][2], acc[mt][nb][3]);
            }
    }
}

// ---------------- edge kernel: 3 CTAs/SM, fused softmax ----------------------
// dyn smem = S tile [128][264]h, stride 528 (67584 B). ef + weights via LDG.
#define EDGE_SMEM 67584

__global__ void __launch_bounds__(256, 3)
edge_kernel(const float* __restrict__ ef_,
            const int* __restrict__ src, const int* __restrict__ dst,
            const float* __restrict__ be1, const float* __restrict__ be2,
            const float* __restrict__ ba1, const float* __restrict__ Wa2,
            const float* __restrict__ ba2,
            float* __restrict__ uh_e, int E)
{
    extern __shared__ __align__(16) char dyn[];
    __shared__ int sSrc[128], sDst[128];

    const int tid = threadIdx.x;
    const int lane = tid & 31, wid = tid >> 5;
    const int g = lane >> 2, t = lane & 3;
    const int e0 = blockIdx.x * 128;

    if (tid < 128)      { int e = e0 + tid;       sSrc[tid]       = (e < E) ? src[e] : 0; }
    else                { int e = e0 + tid - 128; sDst[tid - 128] = (e < E) ? dst[e] : 0; }
    __syncthreads();

    // stage S = P[src] + Q[dst]
    for (int idx = tid; idx < 4096; idx += 256) {
        int le = idx >> 5, q = idx & 31;
        uint4 p = __ldg((const uint4*)g_P + (size_t)sSrc[le] * 32 + q);
        uint4 qv = __ldg((const uint4*)g_Q + (size_t)sDst[le] * 32 + q);
        uint4 s;
        s.x = addh2_f32(p.x, qv.x); s.y = addh2_f32(p.y, qv.y);
        s.z = addh2_f32(p.z, qv.z); s.w = addh2_f32(p.w, qv.w);
        *(uint4*)(dyn + le * 528 + q * 16) = s;
    }

    const int row0 = wid * 16 + g, row1 = row0 + 8;
    const int er0 = e0 + row0, er1 = e0 + row1;

    // ef A-fragments straight from global (warp-exclusive rows)
    unsigned aef[2][4];
#pragma unroll
    for (int kk = 0; kk < 2; kk++) {
        int c = kk * 16 + 2 * t;
        if (er0 < E) {
            float2 v0 = *(const float2*)(ef_ + (size_t)er0 * 32 + c);
            float2 v2 = *(const float2*)(ef_ + (size_t)er0 * 32 + c + 8);
            aef[kk][0] = pack_h2(v0.x, v0.y);
            aef[kk][2] = pack_h2(v2.x, v2.y);
        } else aef[kk][0] = aef[kk][2] = 0u;
        if (er1 < E) {
            float2 v1 = *(const float2*)(ef_ + (size_t)er1 * 32 + c);
            float2 v3 = *(const float2*)(ef_ + (size_t)er1 * 32 + c + 8);
            aef[kk][1] = pack_h2(v1.x, v1.y);
            aef[kk][3] = pack_h2(v3.x, v3.y);
        } else aef[kk][1] = aef[kk][3] = 0u;
    }
    __syncthreads();   // S ready

    // ---- Pass E: edge-hidden cols [0,128) in two 64-col halves ----
#pragma unroll
    for (int half = 0; half < 2; half++) {
        float acc[8][4];
#pragma unroll
        for (int nb = 0; nb < 8; nb++)
#pragma unroll
            for (int q = 0; q < 4; q++) acc[nb][q] = 0.f;
#pragma unroll
        for (int kk = 0; kk < 2; kk++)
#pragma unroll
            for (int nb = 0; nb < 8; nb++) {
                uint2 b = __ldg((const uint2*)g_Wcf + (kk * 32 + half * 8 + nb) * 32 + lane);
                mma_f16(acc[nb], aef[kk], b);
            }
#pragma unroll
        for (int nb = 0; nb < 8; nb++) {
            int c = half * 64 + nb * 8 + 2 * t;
            float b0 = __ldg(be1 + c), b1 = __ldg(be1 + c + 1);
            float2 s0 = __half22float2(*(const __half2*)(dyn + row0 * 528 + c * 2));
            float2 s1 = __half22float2(*(const __half2*)(dyn + row1 * 528 + c * 2));
            *(unsigned*)(dyn + row0 * 528 + c * 2) =
                pack_h2(fmaxf(acc[nb][0] + s0.x + b0, 0.f), fmaxf(acc[nb][1] + s0.y + b1, 0.f));
            *(unsigned*)(dyn + row1 * 528 + c * 2) =
                pack_h2(fmaxf(acc[nb][2] + s1.x + b0, 0.f), fmaxf(acc[nb][3] + s1.y + b1, 0.f));
        }
    }

    // ---- Pass A: attn cols [128,256) in two halves; accumulate logits ----
    float l0 = 0.f, l1 = 0.f;
#pragma unroll
    for (int half = 0; half < 2; half++) {
        float acc[8][4];
#pragma unroll
        for (int nb = 0; nb < 8; nb++)
#pragma unroll
            for (int q = 0; q < 4; q++) acc[nb][q] = 0.f;
#pragma unroll
        for (int kk = 0; kk < 2; kk++)
#pragma unroll
            for (int nb = 0; nb < 8; nb++) {
                uint2 b = __ldg((const uint2*)g_Wcf + (kk * 32 + 16 + half * 8 + nb) * 32 + lane);
                mma_f16(acc[nb], aef[kk], b);
            }
#pragma unroll
        for (int nb = 0; nb < 8; nb++) {
            int c = half * 64 + nb * 8 + 2 * t;
            int off = (128 + c) * 2;
            float b0 = __ldg(ba1 + c), b1 = __ldg(ba1 + c + 1);
            float w0 = __ldg(Wa2 + c), w1 = __ldg(Wa2 + c + 1);
            float2 s0 = __half22float2(*(const __half2*)(dyn + row0 * 528 + off));
            float2 s1 = __half22float2(*(const __half2*)(dyn + row1 * 528 + off));
            l0 += fmaxf(acc[nb][0] + s0.x + b0, 0.f) * w0 + fmaxf(acc[nb][1] + s0.y + b1, 0.f) * w1;
            l1 += fmaxf(acc[nb][2] + s1.x + b0, 0.f) * w0 + fmaxf(acc[nb][3] + s1.y + b1, 0.f) * w1;
        }
    }
#pragma unroll
    for (int off = 1; off <= 2; off <<= 1) {
        l0 += __shfl_xor_sync(0xffffffffu, l0, off);
        l1 += __shfl_xor_sync(0xffffffffu, l1, off);
    }
    if (t == 0) {
        float b2 = __ldg(ba2);
        if (er0 < E) {
            float ex = expf(l0 + b2);
            g_ex[er0] = ex;
            asm volatile("red.global.add.f32 [%0], %1;" :: "l"(g_denom + sDst[row0]), "f"(ex) : "memory");
        }
        if (er1 < E) {
            float ex = expf(l1 + b2);
            g_ex[er1] = ex;
            asm volatile("red.global.add.f32 [%0], %1;" :: "l"(g_denom + sDst[row1]), "f"(ex) : "memory");
        }
    }
    __syncthreads();   // hidden H (in S region) visible to all warps

    // ---- GEMM2: H[128x128] x W2[128x64] -> uh_e ----
    {
        const int warp_m = wid & 3, warp_n = wid >> 2;
        float accO[2][4][4];
#pragma unroll
        for (int mt = 0; mt < 2; mt++)
#pragma unroll
            for (int nb = 0; nb < 4; nb++)
#pragma unroll
                for (int q = 0; q < 4; q++) accO[mt][nb][q] = 0.f;
        unsigned a[2][4];
#pragma unroll
        for (int kk = 0; kk < 8; kk++) {
#pragma unroll
            for (int mt = 0; mt < 2; mt++) {
                int row = warp_m * 32 + mt * 16 + g;
                const char* base = dyn + row * 528 + kk * 32 + 4 * t;
                a[mt][0] = *(const unsigned*)(base);
                a[mt][1] = *(const unsigned*)(base + 8 * 528);
                a[mt][2] = *(const unsigned*)(base + 16);
                a[mt][3] = *(const unsigned*)(base + 8 * 528 + 16);
            }
#pragma unroll
            for (int nb = 0; nb < 4; nb++) {
                uint2 b = __ldg((const uint2*)g_W2f + (kk * 8 + warp_n * 4 + nb) * 32 + lane);
                mma_f16(accO[0][nb], a[0], b);
                mma_f16(accO[1][nb], a[1], b);
            }
        }
#pragma unroll
        for (int mt = 0; mt < 2; mt++)
#pragma unroll
            for (int nb = 0; nb < 4; nb++) {
                int c = warp_n * 32 + nb * 8 + 2 * t;
                float b0 = __ldg(be2 + c), b1 = __ldg(be2 + c + 1);
                int r0 = warp_m * 32 + mt * 16 + g;
                int e = e0 + r0;
                if (e < E)
                    *(float2*)(uh_e + (size_t)e * 64 + c) =
                        make_float2(accO[mt][nb][0] + b0, accO[mt][nb][1] + b1);
                if (e + 8 < E)
                    *(float2*)(uh_e + (size_t)(e + 8) * 64 + c) =
                        make_float2(accO[mt][nb][2] + b0, accO[mt][nb][3] + b1);
            }
    }
}

// ---------------- node kernel: fp16 HMMA, 2 CTAs/SM --------------------------
#define oNi  0          // in/hidden tile [128][136]h, stride 272 (34816 B)
#define oNW1 34816      // Wn1 frags 32 KB
#define oNW2 67584      // Wn2 frags 16 KB
#define NODE_SMEM 83968

__global__ void __launch_bounds__(256, 2)
node_kernel(const float* __restrict__ nf,
            const float* __restrict__ bn1, const float* __restrict__ bn2,
            float* __restrict__ uh_n, int N)
{
    extern __shared__ __align__(16) char dyn[];

    const int tid = threadIdx.x;
    const int lane = tid & 31, wid = tid >> 5;
    const int g = lane >> 2, t = lane & 3;
    const int warp_m = wid & 3, warp_n = wid >> 2;
    const int n0 = blockIdx.x * 128;

    for (int i = tid; i < 2048; i += 256) ((uint4*)(dyn + oNW1))[i] = ((const uint4*)g_Wn1f)[i];
    for (int i = tid; i < 1024; i += 256) ((uint4*)(dyn + oNW2))[i] = ((const uint4*)g_Wn2f)[i];
    for (int idx = tid; idx < 4096; idx += 256) {
        int le = idx >> 5, q = idx & 31;
        int n = n0 + le;
        float4 v = make_float4(0.f, 0.f, 0.f, 0.f);
        if (n < N)
            v = (q < 16) ? __ldg((const float4*)(g_agg + (size_t)n * 64) + q)
                         : __ldg((const float4*)(nf + (size_t)n * 64) + (q - 16));
        *(uint2*)(dyn + oNi + le * 272 + q * 8) = make_uint2(pack_h2(v.x, v.y), pack_h2(v.z, v.w));
    }
    __syncthreads();

    float acc[2][8][4];
#pragma unroll
    for (int mt = 0; mt < 2; mt++)
#pragma unroll
        for (int nb = 0; nb < 8; nb++)
#pragma unroll
            for (int q = 0; q < 4; q++) acc[mt][nb][q] = 0.f;
    {
        unsigned a[2][4];
        const uint2* sWu = (const uint2*)(dyn + oNW1);
#pragma unroll
        for (int kk = 0; kk < 8; kk++) {
#pragma unroll
            for (int mt = 0; mt < 2; mt++) {
                int row = warp_m * 32 + mt * 16 + g;
                const char* base = dyn + oNi + row * 272 + kk * 32 + 4 * t;
                a[mt][0] = *(const unsigned*)(base);
                a[mt][1] = *(const unsigned*)(base + 8 * 272);
                a[mt][2] = *(const unsigned*)(base + 16);
                a[mt][3] = *(const unsigned*)(base + 8 * 272 + 16);
            }
#pragma unroll
            for (int nb = 0; nb < 8; nb++) {
                uint2 b = sWu[(kk * 16 + warp_n * 8 + nb) * 32 + lane];
                mma_f16(acc[0][nb], a[0], b);
                mma_f16(acc[1][nb], a[1], b);
            }
        }
    }
    __syncthreads();

#pragma unroll
    for (int mt = 0; mt < 2; mt++)
#pragma unroll
        for (int nb = 0; nb < 8; nb++) {
            int c = warp_n * 64 + nb * 8 + 2 * t;
            float b0 = __ldg(bn1 + c), b1 = __ldg(bn1 + c + 1);
            int r0 = warp_m * 32 + mt * 16 + g;
            *(unsigned*)(dyn + oNi + r0 * 272 + c * 2) =
                pack_h2(fmaxf(acc[mt][nb][0] + b0, 0.f), fmaxf(acc[mt][nb][1] + b1, 0.f));
            *(unsigned*)(dyn + oNi + (r0 + 8) * 272 + c * 2) =
                pack_h2(fmaxf(acc[mt][nb][2] + b0, 0.f), fmaxf(acc[mt][nb][3] + b1, 0.f));
        }
    __syncthreads();

    {
        float accO[2][4][4];
#pragma unroll
        for (int mt = 0; mt < 2; mt++)
#pragma unroll
            for (int nb = 0; nb < 4; nb++)
#pragma unroll
                for (int q = 0; q < 4; q++) accO[mt][nb][q] = 0.f;
        unsigned a[2][4];
        const uint2* sWu = (const uint2*)(dyn + oNW2);
#pragma unroll
        for (int kk = 0; kk < 8; kk++) {
#pragma unroll
            for (int mt = 0; mt < 2; mt++) {
                int row = warp_m * 32 + mt * 16 + g;
                const char* base = dyn + oNi + row * 272 + kk * 32 + 4 * t;
                a[mt][0] = *(const unsigned*)(base);
                a[mt][1] = *(const unsigned*)(base + 8 * 272);
                a[mt][2] = *(const unsigned*)(base + 16);
                a[mt][3] = *(const unsigned*)(base + 8 * 272 + 16);
            }
#pragma unroll
            for (int nb = 0; nb < 4; nb++) {
                uint2 b = sWu[(kk * 8 + warp_n * 4 + nb) * 32 + lane];
                mma_f16(accO[0][nb], a[0], b);
                mma_f16(accO[1][nb], a[1], b);
            }
        }
#pragma unroll
        for (int mt = 0; mt < 2; mt++)
#pragma unroll
            for (int nb = 0; nb < 4; nb++) {
                int c = warp_n * 32 + nb * 8 + 2 * t;
                float b0 = __ldg(bn2 + c), b1 = __ldg(bn2 + c + 1);
                int r0 = warp_m * 32 + mt * 16 + g;
                int n = n0 + r0;
                if (n < N)
                    *(float2*)(uh_n + (size_t)n * 64 + c) =
                        make_float2(accO[mt][nb][0] + b0, accO[mt][nb][1] + b1);
                if (n + 8 < N)
                    *(float2*)(uh_n + (size_t)(n + 8) * 64 + c) =
                        make_float2(accO[mt][nb][2] + b0, accO[mt][nb][3] + b1);
            }
    }
}

// ---------------- init / aggregation -----------------------------------------
__global__ void init_kernel(int N) {
    int t = blockIdx.x * blockDim.x + threadIdx.x;
    if (t < N * 16) ((float4*)g_agg)[t] = make_float4(0.f, 0.f, 0.f, 0.f);
    if (t < N) g_denom[t] = 0.f;
}
__global__ void agg_kernel(const int* __restrict__ dst, const float* __restrict__ uh_e, int E) {
    int t = blockIdx.x * blockDim.x + threadIdx.x;
    int e = t >> 4, lane = t & 15;
    if (e < E) {
        int d = dst[e];
        float attn = g_ex[e] / fmaxf(g_denom[d], 1e-38f);
        float4 u = __ldg((const float4*)(uh_e + (size_t)e * 64) + lane);
        float* p = g_agg + (size_t)d * 64 + lane * 4;
        asm volatile("red.global.add.v4.f32 [%0], {%1,%2,%3,%4};"
                     :: "l"(p), "f"(u.x * attn), "f"(u.y * attn),
                        "f"(u.z * attn), "f"(u.w * attn) : "memory");
    }
}

// ---------------- launch -----------------------------------------------------
extern "C" void kernel_launch(void* const* d_in, const int* in_sizes, int n_in,
                              void* d_out, int out_size)
{
    const float* nf  = (const float*)d_in[0];
    const float* ef  = (const float*)d_in[1];
    const int*   src = (const int*)d_in[2];
    const int*   dst = (const int*)d_in[3];
    const float* We1 = (const float*)d_in[4];
    const float* be1 = (const float*)d_in[5];
    const float* We2 = (const float*)d_in[6];
    const float* be2 = (const float*)d_in[7];
    const float* Wa1 = (const float*)d_in[8];
    const float* ba1 = (const float*)d_in[9];
    const float* Wa2 = (const float*)d_in[10];
    const float* ba2 = (const float*)d_in[11];
    const float* Wn1 = (const float*)d_in[12];
    const float* bn1 = (const float*)d_in[13];
    const float* Wn2 = (const float*)d_in[14];
    const float* bn2 = (const float*)d_in[15];

    const int N = in_sizes[0] / 64;
    const int E = in_sizes[2];

    float* uh_n = (float*)d_out;
    float* uh_e = uh_n + (size_t)N * 64;

    const int PQ_SMEM = 18432 + 32768 + 32768;   // 83968

    cudaFuncSetAttribute(pq_kernel,   cudaFuncAttributeMaxDynamicSharedMemorySize, PQ_SMEM);
    cudaFuncSetAttribute(edge_kernel, cudaFuncAttributeMaxDynamicSharedMemorySize, EDGE_SMEM);
    cudaFuncSetAttribute(node_kernel, cudaFuncAttributeMaxDynamicSharedMemorySize, NODE_SMEM);

    prep_kernel<<<(28672 + 255) / 256, 256>>>(We1, Wa1, We2, Wn1, Wn2);
    init_kernel<<<(N * 16 + 255) / 256, 256>>>(N);
    pq_kernel<<<(N + 127) / 128, 256, PQ_SMEM>>>(nf, N);
    edge_kernel<<<(E + 127) / 128, 256, EDGE_SMEM>>>(
        ef, src, dst, be1, be2, ba1, Wa2, ba2, uh_e, E);
    agg_kernel<<<(int)(((size_t)E * 16 + 255) / 256), 256>>>(dst, uh_e, E);
    node_kernel<<<(N + 127) / 128, 256, NODE_SMEM>>>(nf, bn1, bn2, uh_n, N);
}

// round 13
// speedup vs baseline: 2.9368x; 1.0318x over previous
#include <cuda_runtime.h>
#include <cuda_fp16.h>
#include <math.h>
#include <stdint.h>

#define NN 50000
#define NE 800000

// ---------------- scratch (static device globals; no allocation) -----------
__device__ float    g_denom[NN];
__device__ float    g_agg[NN * 64];    // numerator: sum ex*uh_e

// P/Q tables: [node][256] fp16. P = nf@[We1s|Wa1s], Q = nf@[We1d|Wa1d]
__device__ unsigned g_P[50048 * 128];
__device__ unsigned g_Q[50048 * 128];

// fp16 fragment images
__device__ unsigned g_WPf[8192];    // [K=64][N=256]
__device__ unsigned g_WQf[8192];    // [K=64][N=256]
__device__ unsigned g_Wcf[4096];    // [K=32][N=256]  (ef rows of We1|Wa1)
__device__ unsigned g_W2f[4096];    // [K=128][N=64]
__device__ unsigned g_Wn1f[8192];   // [K=128][N=128]
__device__ unsigned g_Wn2f[4096];   // [K=128][N=64]

__device__ __forceinline__ unsigned pack_h2(float a, float b) {
    __half2 h = __floats2half2_rn(a, b);
    return *(unsigned*)&h;
}
__device__ __forceinline__ unsigned addh2_f32(unsigned a, unsigned b) {
    float2 fa = __half22float2(*(__half2*)&a);
    float2 fb = __half22float2(*(__half2*)&b);
    return pack_h2(fa.x + fb.x, fa.y + fb.y);
}

__device__ __forceinline__ void mma_f16(float c[4], const unsigned a[4], uint2 b) {
    asm volatile(
        "mma.sync.aligned.m16n8k16.row.col.f32.f16.f16.f32 "
        "{%0,%1,%2,%3},{%4,%5,%6,%7},{%8,%9},{%0,%1,%2,%3};\n"
        : "+f"(c[0]), "+f"(c[1]), "+f"(c[2]), "+f"(c[3])
        : "r"(a[0]), "r"(a[1]), "r"(a[2]), "r"(a[3]), "r"(b.x), "r"(b.y));
}

// ---------------- weight prep -----------------------------------------------
__global__ void prep_kernel(const float* __restrict__ We1,
                            const float* __restrict__ Wa1,
                            const float* __restrict__ We2,
                            const float* __restrict__ Wn1,
                            const float* __restrict__ Wn2) {
    int idx = blockIdx.x * blockDim.x + threadIdx.x;
    if (idx < 8192) {                       // WP/WQ: K=64, N=256 (NBT=32)
        int reg = idx & 1, lane = (idx >> 1) & 31, nbt = (idx >> 6) & 31, kk = idx >> 11;
        int g = lane >> 2, t = lane & 3;
        int n = nbt * 8 + g;
        int k0 = kk * 16 + 2 * t + reg * 8;
        const float* W = (n < 128) ? We1 : Wa1;
        int nc = n & 127;
        g_WPf[idx] = pack_h2(W[k0 * 128 + nc], W[(k0 + 1) * 128 + nc]);
        g_WQf[idx] = pack_h2(W[(k0 + 64) * 128 + nc], W[(k0 + 65) * 128 + nc]);
    } else if (idx < 12288) {               // Wc: K=32, N=256 (rows 128..159)
        int i = idx - 8192;
        int reg = i & 1, lane = (i >> 1) & 31, nbt = (i >> 6) & 31, kk = i >> 11;
        int g = lane >> 2, t = lane & 3;
        int n = nbt * 8 + g;
        int k0 = 128 + kk * 16 + 2 * t + reg * 8;
        const float* W = (n < 128) ? We1 : Wa1;
        int nc = n & 127;
        g_Wcf[i] = pack_h2(W[k0 * 128 + nc], W[(k0 + 1) * 128 + nc]);
    } else if (idx < 16384) {               // W2e: K=128, N=64
        int i = idx - 12288;
        int reg = i & 1, lane = (i >> 1) & 31, nbt = (i >> 6) & 7, kk = i >> 9;
        int g = lane >> 2, t = lane & 3;
        int n = nbt * 8 + g;
        int k0 = kk * 16 + 2 * t + reg * 8;
        g_W2f[i] = pack_h2(We2[k0 * 64 + n], We2[(k0 + 1) * 64 + n]);
    } else if (idx < 24576) {               // Wn1: K=128, N=128 (NBT=16)
        int i = idx - 16384;
        int reg = i & 1, lane = (i >> 1) & 31, nbt = (i >> 6) & 15, kk = i >> 10;
        int g = lane >> 2, t = lane & 3;
        int n = nbt * 8 + g;
        int k0 = kk * 16 + 2 * t + reg * 8;
        g_Wn1f[i] = pack_h2(Wn1[k0 * 128 + n], Wn1[(k0 + 1) * 128 + n]);
    } else if (idx < 28672) {               // Wn2: K=128, N=64
        int i = idx - 24576;
        int reg = i & 1, lane = (i >> 1) & 31, nbt = (i >> 6) & 7, kk = i >> 9;
        int g = lane >> 2, t = lane & 3;
        int n = nbt * 8 + g;
        int k0 = kk * 16 + 2 * t + reg * 8;
        g_Wn2f[i] = pack_h2(Wn2[k0 * 64 + n], Wn2[(k0 + 1) * 64 + n]);
    }
}

// ---------------- per-node precompute: P = nf@WP, Q = nf@WQ -----------------
// 3 CTAs/SM: smem = nf tile only; weights via __ldg; A frags shared for P & Q
#define PQ_SMEM 18432

__global__ void __launch_bounds__(256, 3)
pq_kernel(const float* __restrict__ nf, int N)
{
    extern __shared__ __align__(16) char dyn[];
    char* sNf = dyn;                              // [128][72] fp16 (stride 144B)

    const int tid = threadIdx.x;
    const int lane = tid & 31, wid = tid >> 5;
    const int g = lane >> 2, t = lane & 3;
    const int n0 = blockIdx.x * 128;

    for (int idx = tid; idx < 128 * 16; idx += 256) {
        int le = idx >> 4, q = idx & 15;
        int n = n0 + le;
        float4 v = make_float4(0.f, 0.f, 0.f, 0.f);
        if (n < N) v = __ldg((const float4*)(nf + (size_t)n * 64) + q);
        *(uint2*)(sNf + le * 144 + q * 8) = make_uint2(pack_h2(v.x, v.y), pack_h2(v.z, v.w));
    }
    __syncthreads();

    const int row0 = wid * 16 + g, row1 = row0 + 8;

    // A fragments (K=64: 4 kk steps) loaded once, reused for P and Q
    unsigned a[4][4];
#pragma unroll
    for (int kk = 0; kk < 4; kk++) {
        const char* base = sNf + row0 * 144 + kk * 32 + 4 * t;
        a[kk][0] = *(const unsigned*)(base);
        a[kk][1] = *(const unsigned*)(base + 8 * 144);
        a[kk][2] = *(const unsigned*)(base + 16);
        a[kk][3] = *(const unsigned*)(base + 8 * 144 + 16);
    }

#pragma unroll
    for (int tab = 0; tab < 2; tab++) {
        const uint2* Wf = (const uint2*)(tab ? g_WQf : g_WPf);
        unsigned* gOut = tab ? g_Q : g_P;
#pragma unroll
        for (int chunk = 0; chunk < 4; chunk++) {
            float acc[8][4];
#pragma unroll
            for (int nb = 0; nb < 8; nb++)
#pragma unroll
                for (int q = 0; q < 4; q++) acc[nb][q] = 0.f;
#pragma unroll
            for (int kk = 0; kk < 4; kk++)
#pragma unroll
                for (int nb = 0; nb < 8; nb++) {
                    uint2 b = __ldg(Wf + (kk * 32 + chunk * 8 + nb) * 32 + lane);
                    mma_f16(acc[nb], a[kk], b);
                }
#pragma unroll
            for (int nb = 0; nb < 8; nb++) {
                int c = chunk * 64 + nb * 8 + 2 * t;
                if (n0 + row0 < N)
                    gOut[(size_t)(n0 + row0) * 128 + (c >> 1)] = pack_h2(acc[nb][0], acc[nb][1]);
                if (n0 + row1 < N)
                    gOut[(size_t)(n0 + row1) * 128 + (c >> 1)] = pack_h2(acc[nb][2], acc[nb][3]);
            }
        }
    }
}

// ---------------- edge kernel: 3 CTAs/SM, fused softmax + numerator agg -----
#define EDGE_SMEM 67584

__global__ void __launch_bounds__(256, 3)
edge_kernel(const float* __restrict__ ef_,
            const int* __restrict__ src, const int* __restrict__ dst,
            const float* __restrict__ be1, const float* __restrict__ be2,
            const float* __restrict__ ba1, const float* __restrict__ Wa2,
            const float* __restrict__ ba2,
            float* __restrict__ uh_e, int E)
{
    extern __shared__ __align__(16) char dyn[];
    __shared__ int sSrc[128], sDst[128];
    __shared__ float sEx[128];

    const int tid = threadIdx.x;
    const int lane = tid & 31, wid = tid >> 5;
    const int g = lane >> 2, t = lane & 3;
    const int e0 = blockIdx.x * 128;

    if (tid < 128)      { int e = e0 + tid;       sSrc[tid]       = (e < E) ? src[e] : 0; }
    else                { int e = e0 + tid - 128; sDst[tid - 128] = (e < E) ? dst[e] : 0; }
    __syncthreads();

    // stage S = P[src] + Q[dst]
    for (int idx = tid; idx < 4096; idx += 256) {
        int le = idx >> 5, q = idx & 31;
        uint4 p = __ldg((const uint4*)g_P + (size_t)sSrc[le] * 32 + q);
        uint4 qv = __ldg((const uint4*)g_Q + (size_t)sDst[le] * 32 + q);
        uint4 s;
        s.x = addh2_f32(p.x, qv.x); s.y = addh2_f32(p.y, qv.y);
        s.z = addh2_f32(p.z, qv.z); s.w = addh2_f32(p.w, qv.w);
        *(uint4*)(dyn + le * 528 + q * 16) = s;
    }

    const int row0 = wid * 16 + g, row1 = row0 + 8;
    const int er0 = e0 + row0, er1 = e0 + row1;

    // ef A-fragments straight from global (warp-exclusive rows)
    unsigned aef[2][4];
#pragma unroll
    for (int kk = 0; kk < 2; kk++) {
        int c = kk * 16 + 2 * t;
        if (er0 < E) {
            float2 v0 = *(const float2*)(ef_ + (size_t)er0 * 32 + c);
            float2 v2 = *(const float2*)(ef_ + (size_t)er0 * 32 + c + 8);
            aef[kk][0] = pack_h2(v0.x, v0.y);
            aef[kk][2] = pack_h2(v2.x, v2.y);
        } else aef[kk][0] = aef[kk][2] = 0u;
        if (er1 < E) {
            float2 v1 = *(const float2*)(ef_ + (size_t)er1 * 32 + c);
            float2 v3 = *(const float2*)(ef_ + (size_t)er1 * 32 + c + 8);
            aef[kk][1] = pack_h2(v1.x, v1.y);
            aef[kk][3] = pack_h2(v3.x, v3.y);
        } else aef[kk][1] = aef[kk][3] = 0u;
    }
    __syncthreads();   // S ready

    // ---- Pass E: edge-hidden cols [0,128) in two 64-col halves ----
#pragma unroll
    for (int half = 0; half < 2; half++) {
        float acc[8][4];
#pragma unroll
        for (int nb = 0; nb < 8; nb++)
#pragma unroll
            for (int q = 0; q < 4; q++) acc[nb][q] = 0.f;
#pragma unroll
        for (int kk = 0; kk < 2; kk++)
#pragma unroll
            for (int nb = 0; nb < 8; nb++) {
                uint2 b = __ldg((const uint2*)g_Wcf + (kk * 32 + half * 8 + nb) * 32 + lane);
                mma_f16(acc[nb], aef[kk], b);
            }
#pragma unroll
        for (int nb = 0; nb < 8; nb++) {
            int c = half * 64 + nb * 8 + 2 * t;
            float b0 = __ldg(be1 + c), b1 = __ldg(be1 + c + 1);
            float2 s0 = __half22float2(*(const __half2*)(dyn + row0 * 528 + c * 2));
            float2 s1 = __half22float2(*(const __half2*)(dyn + row1 * 528 + c * 2));
            *(unsigned*)(dyn + row0 * 528 + c * 2) =
                pack_h2(fmaxf(acc[nb][0] + s0.x + b0, 0.f), fmaxf(acc[nb][1] + s0.y + b1, 0.f));
            *(unsigned*)(dyn + row1 * 528 + c * 2) =
                pack_h2(fmaxf(acc[nb][2] + s1.x + b0, 0.f), fmaxf(acc[nb][3] + s1.y + b1, 0.f));
        }
    }

    // ---- Pass A: attn cols [128,256); logits -> ex (no segment-max) ----
    float l0 = 0.f, l1 = 0.f;
#pragma unroll
    for (int half = 0; half < 2; half++) {
        float acc[8][4];
#pragma unroll
        for (int nb = 0; nb < 8; nb++)
#pragma unroll
            for (int q = 0; q < 4; q++) acc[nb][q] = 0.f;
#pragma unroll
        for (int kk = 0; kk < 2; kk++)
#pragma unroll
            for (int nb = 0; nb < 8; nb++) {
                uint2 b = __ldg((const uint2*)g_Wcf + (kk * 32 + 16 + half * 8 + nb) * 32 + lane);
                mma_f16(acc[nb], aef[kk], b);
            }
#pragma unroll
        for (int nb = 0; nb < 8; nb++) {
            int c = half * 64 + nb * 8 + 2 * t;
            int off = (128 + c) * 2;
            float b0 = __ldg(ba1 + c), b1 = __ldg(ba1 + c + 1);
            float w0 = __ldg(Wa2 + c), w1 = __ldg(Wa2 + c + 1);
            float2 s0 = __half22float2(*(const __half2*)(dyn + row0 * 528 + off));
            float2 s1 = __half22float2(*(const __half2*)(dyn + row1 * 528 + off));
            l0 += fmaxf(acc[nb][0] + s0.x + b0, 0.f) * w0 + fmaxf(acc[nb][1] + s0.y + b1, 0.f) * w1;
            l1 += fmaxf(acc[nb][2] + s1.x + b0, 0.f) * w0 + fmaxf(acc[nb][3] + s1.y + b1, 0.f) * w1;
        }
    }
#pragma unroll
    for (int off = 1; off <= 2; off <<= 1) {
        l0 += __shfl_xor_sync(0xffffffffu, l0, off);
        l1 += __shfl_xor_sync(0xffffffffu, l1, off);
    }
    if (t == 0) {
        float b2 = __ldg(ba2);
        float ex0 = expf(l0 + b2), ex1 = expf(l1 + b2);
        sEx[row0] = ex0;
        sEx[row1] = ex1;
        if (er0 < E)
            asm volatile("red.global.add.f32 [%0], %1;" :: "l"(g_denom + sDst[row0]), "f"(ex0) : "memory");
        if (er1 < E)
            asm volatile("red.global.add.f32 [%0], %1;" :: "l"(g_denom + sDst[row1]), "f"(ex1) : "memory");
    }
    __syncthreads();   // hidden H (in S region) + sEx visible to all warps

    // ---- GEMM2: H[128x128] x W2[128x64] -> uh_e + numerator reds ----
    {
        const int warp_m = wid & 3, warp_n = wid >> 2;
        float accO[2][4][4];
#pragma unroll
        for (int mt = 0; mt < 2; mt++)
#pragma unroll
            for (int nb = 0; nb < 4; nb++)
#pragma unroll
                for (int q = 0; q < 4; q++) accO[mt][nb][q] = 0.f;
        unsigned a[2][4];
#pragma unroll
        for (int kk = 0; kk < 8; kk++) {
#pragma unroll
            for (int mt = 0; mt < 2; mt++) {
                int row = warp_m * 32 + mt * 16 + g;
                const char* base = dyn + row * 528 + kk * 32 + 4 * t;
                a[mt][0] = *(const unsigned*)(base);
                a[mt][1] = *(const unsigned*)(base + 8 * 528);
                a[mt][2] = *(const unsigned*)(base + 16);
                a[mt][3] = *(const unsigned*)(base + 8 * 528 + 16);
            }
#pragma unroll
            for (int nb = 0; nb < 4; nb++) {
                uint2 b = __ldg((const uint2*)g_W2f + (kk * 8 + warp_n * 4 + nb) * 32 + lane);
                mma_f16(accO[0][nb], a[0], b);
                mma_f16(accO[1][nb], a[1], b);
            }
        }
#pragma unroll
        for (int mt = 0; mt < 2; mt++) {
            int r0 = warp_m * 32 + mt * 16 + g;
            int r1 = r0 + 8;
            float ex0 = sEx[r0], ex1 = sEx[r1];
            int d0 = sDst[r0], d1 = sDst[r1];
#pragma unroll
            for (int nb = 0; nb < 4; nb++) {
                int c = warp_n * 32 + nb * 8 + 2 * t;
                float b0 = __ldg(be2 + c), b1 = __ldg(be2 + c + 1);
                int e = e0 + r0;
                float o0 = accO[mt][nb][0] + b0, o1 = accO[mt][nb][1] + b1;
                float o2 = accO[mt][nb][2] + b0, o3 = accO[mt][nb][3] + b1;
                if (e < E) {
                    *(float2*)(uh_e + (size_t)e * 64 + c) = make_float2(o0, o1);
                    asm volatile("red.global.add.v2.f32 [%0], {%1,%2};"
                                 :: "l"(g_agg + (size_t)d0 * 64 + c),
                                    "f"(o0 * ex0), "f"(o1 * ex0) : "memory");
                }
                if (e0 + r1 < E) {
                    *(float2*)(uh_e + (size_t)(e0 + r1) * 64 + c) = make_float2(o2, o3);
                    asm volatile("red.global.add.v2.f32 [%0], {%1,%2};"
                                 :: "l"(g_agg + (size_t)d1 * 64 + c),
                                    "f"(o2 * ex1), "f"(o3 * ex1) : "memory");
                }
            }
        }
    }
}

// ---------------- node kernel: fp16 HMMA, 2 CTAs/SM --------------------------
#define oNi  0          // in/hidden tile [128][136]h, stride 272 (34816 B)
#define oNW1 34816      // Wn1 frags 32 KB
#define oNW2 67584      // Wn2 frags 16 KB
#define NODE_SMEM 83968

__global__ void __launch_bounds__(256, 2)
node_kernel(const float* __restrict__ nf,
            const float* __restrict__ bn1, const float* __restrict__ bn2,
            float* __restrict__ uh_n, int N)
{
    extern __shared__ __align__(16) char dyn[];

    const int tid = threadIdx.x;
    const int lane = tid & 31, wid = tid >> 5;
    const int g = lane >> 2, t = lane & 3;
    const int warp_m = wid & 3, warp_n = wid >> 2;
    const int n0 = blockIdx.x * 128;

    for (int i = tid; i < 2048; i += 256) ((uint4*)(dyn + oNW1))[i] = ((const uint4*)g_Wn1f)[i];
    for (int i = tid; i < 1024; i += 256) ((uint4*)(dyn + oNW2))[i] = ((const uint4*)g_Wn2f)[i];
    // gather in = [agg_num/denom | nf] -> fp16
    for (int idx = tid; idx < 4096; idx += 256) {
        int le = idx >> 5, q = idx & 31;
        int n = n0 + le;
        float4 v = make_float4(0.f, 0.f, 0.f, 0.f);
        if (n < N) {
            if (q < 16) {
                v = __ldg((const float4*)(g_agg + (size_t)n * 64) + q);
                float inv = 1.f / fmaxf(g_denom[n], 1e-38f);
                v.x *= inv; v.y *= inv; v.z *= inv; v.w *= inv;
            } else {
                v = __ldg((const float4*)(nf + (size_t)n * 64) + (q - 16));
            }
        }
        *(uint2*)(dyn + oNi + le * 272 + q * 8) = make_uint2(pack_h2(v.x, v.y), pack_h2(v.z, v.w));
    }
    __syncthreads();

    float acc[2][8][4];
#pragma unroll
    for (int mt = 0; mt < 2; mt++)
#pragma unroll
        for (int nb = 0; nb < 8; nb++)
#pragma unroll
            for (int q = 0; q < 4; q++) acc[mt][nb][q] = 0.f;
    {
        unsigned a[2][4];
        const uint2* sWu = (const uint2*)(dyn + oNW1);
#pragma unroll
        for (int kk = 0; kk < 8; kk++) {
#pragma unroll
            for (int mt = 0; mt < 2; mt++) {
                int row = warp_m * 32 + mt * 16 + g;
                const char* base = dyn + oNi + row * 272 + kk * 32 + 4 * t;
                a[mt][0] = *(const unsigned*)(base);
                a[mt][1] = *(const unsigned*)(base + 8 * 272);
                a[mt][2] = *(const unsigned*)(base + 16);
                a[mt][3] = *(const unsigned*)(base + 8 * 272 + 16);
            }
#pragma unroll
            for (int nb = 0; nb < 8; nb++) {
                uint2 b = sWu[(kk * 16 + warp_n * 8 + nb) * 32 + lane];
                mma_f16(acc[0][nb], a[0], b);
                mma_f16(acc[1][nb], a[1], b);
            }
        }
    }
    __syncthreads();

#pragma unroll
    for (int mt = 0; mt < 2; mt++)
#pragma unroll
        for (int nb = 0; nb < 8; nb++) {
            int c = warp_n * 64 + nb * 8 + 2 * t;
            float b0 = __ldg(bn1 + c), b1 = __ldg(bn1 + c + 1);
            int r0 = warp_m * 32 + mt * 16 + g;
            *(unsigned*)(dyn + oNi + r0 * 272 + c * 2) =
                pack_h2(fmaxf(acc[mt][nb][0] + b0, 0.f), fmaxf(acc[mt][nb][1] + b1, 0.f));
            *(unsigned*)(dyn + oNi + (r0 + 8) * 272 + c * 2) =
                pack_h2(fmaxf(acc[mt][nb][2] + b0, 0.f), fmaxf(acc[mt][nb][3] + b1, 0.f));
        }
    __syncthreads();

    {
        float accO[2][4][4];
#pragma unroll
        for (int mt = 0; mt < 2; mt++)
#pragma unroll
            for (int nb = 0; nb < 4; nb++)
#pragma unroll
                for (int q = 0; q < 4; q++) accO[mt][nb][q] = 0.f;
        unsigned a[2][4];
        const uint2* sWu = (const uint2*)(dyn + oNW2);
#pragma unroll
        for (int kk = 0; kk < 8; kk++) {
#pragma unroll
            for (int mt = 0; mt < 2; mt++) {
                int row = warp_m * 32 + mt * 16 + g;
                const char* base = dyn + oNi + row * 272 + kk * 32 + 4 * t;
                a[mt][0] = *(const unsigned*)(base);
                a[mt][1] = *(const unsigned*)(base + 8 * 272);
                a[mt][2] = *(const unsigned*)(base + 16);
                a[mt][3] = *(const unsigned*)(base + 8 * 272 + 16);
            }
#pragma unroll
            for (int nb = 0; nb < 4; nb++) {
                uint2 b = sWu[(kk * 8 + warp_n * 4 + nb) * 32 + lane];
                mma_f16(accO[0][nb], a[0], b);
                mma_f16(accO[1][nb], a[1], b);
            }
        }
#pragma unroll
        for (int mt = 0; mt < 2; mt++)
#pragma unroll
            for (int nb = 0; nb < 4; nb++) {
                int c = warp_n * 32 + nb * 8 + 2 * t;
                float b0 = __ldg(bn2 + c), b1 = __ldg(bn2 + c + 1);
                int r0 = warp_m * 32 + mt * 16 + g;
                int n = n0 + r0;
                if (n < N)
                    *(float2*)(uh_n + (size_t)n * 64 + c) =
                        make_float2(accO[mt][nb][0] + b0, accO[mt][nb][1] + b1);
                if (n + 8 < N)
                    *(float2*)(uh_n + (size_t)(n + 8) * 64 + c) =
                        make_float2(accO[mt][nb][2] + b0, accO[mt][nb][3] + b1);
            }
    }
}

// ---------------- init ------------------------------------------------------
__global__ void init_kernel(int N) {
    int t = blockIdx.x * blockDim.x + threadIdx.x;
    if (t < N * 16) ((float4*)g_agg)[t] = make_float4(0.f, 0.f, 0.f, 0.f);
    if (t < N) g_denom[t] = 0.f;
}

// ---------------- launch -----------------------------------------------------
extern "C" void kernel_launch(void* const* d_in, const int* in_sizes, int n_in,
                              void* d_out, int out_size)
{
    const float* nf  = (const float*)d_in[0];
    const float* ef  = (const float*)d_in[1];
    const int*   src = (const int*)d_in[2];
    const int*   dst = (const int*)d_in[3];
    const float* We1 = (const float*)d_in[4];
    const float* be1 = (const float*)d_in[5];
    const float* We2 = (const float*)d_in[6];
    const float* be2 = (const float*)d_in[7];
    const float* Wa1 = (const float*)d_in[8];
    const float* ba1 = (const float*)d_in[9];
    const float* Wa2 = (const float*)d_in[10];
    const float* ba2 = (const float*)d_in[11];
    const float* Wn1 = (const float*)d_in[12];
    const float* bn1 = (const float*)d_in[13];
    const float* Wn2 = (const float*)d_in[14];
    const float* bn2 = (const float*)d_in[15];

    const int N = in_sizes[0] / 64;
    const int E = in_sizes[2];

    float* uh_n = (float*)d_out;
    float* uh_e = uh_n + (size_t)N * 64;

    cudaFuncSetAttribute(pq_kernel,   cudaFuncAttributeMaxDynamicSharedMemorySize, PQ_SMEM);
    cudaFuncSetAttribute(edge_kernel, cudaFuncAttributeMaxDynamicSharedMemorySize, EDGE_SMEM);
    cudaFuncSetAttribute(node_kernel, cudaFuncAttributeMaxDynamicSharedMemorySize, NODE_SMEM);

    prep_kernel<<<(28672 + 255) / 256, 256>>>(We1, Wa1, We2, Wn1, Wn2);
    init_kernel<<<(N * 16 + 255) / 256, 256>>>(N);
    pq_kernel<<<(N + 127) / 128, 256, PQ_SMEM>>>(nf, N);
    edge_kernel<<<(E + 127) / 128, 256, EDGE_SMEM>>>(
        ef, src, dst, be1, be2, ba1, Wa2, ba2, uh_e, E);
    node_kernel<<<(N + 127) / 128, 256, NODE_SMEM>>>(nf, bn1, bn2, uh_n, N);
}

// round 15
// speedup vs baseline: 3.0217x; 1.0289x over previous
#include <cuda_runtime.h>
#include <cuda_fp16.h>
#include <math.h>
#include <stdint.h>

#define NN 50000
#define NE 800000

// ---------------- scratch (static device globals; no allocation) -----------
__device__ float    g_denom[NN];
__device__ float    g_agg[NN * 64];    // numerator: sum ex*uh_e

// P/Q tables: [node][256] fp16. P = nf@[We1s|Wa1s], Q = nf@[We1d|Wa1d]
__device__ unsigned g_P[50048 * 128];
__device__ unsigned g_Q[50048 * 128];

// fp16 fragment images
__device__ unsigned g_WPf[8192];    // [K=64][N=256]
__device__ unsigned g_WQf[8192];    // [K=64][N=256]
__device__ unsigned g_Wcf[4096];    // [K=32][N=256]  (ef rows of We1|Wa1)
__device__ unsigned g_W2f[4096];    // [K=128][N=64]
__device__ unsigned g_Wn1f[8192];   // [K=128][N=128]
__device__ unsigned g_Wn2f[4096];   // [K=128][N=64]

__device__ __forceinline__ unsigned pack_h2(float a, float b) {
    __half2 h = __floats2half2_rn(a, b);
    return *(unsigned*)&h;
}
__device__ __forceinline__ unsigned addh2_f32(unsigned a, unsigned b) {
    float2 fa = __half22float2(*(__half2*)&a);
    float2 fb = __half22float2(*(__half2*)&b);
    return pack_h2(fa.x + fb.x, fa.y + fb.y);
}

__device__ __forceinline__ void mma_f16(float c[4], const unsigned a[4], uint2 b) {
    asm volatile(
        "mma.sync.aligned.m16n8k16.row.col.f32.f16.f16.f32 "
        "{%0,%1,%2,%3},{%4,%5,%6,%7},{%8,%9},{%0,%1,%2,%3};\n"
        : "+f"(c[0]), "+f"(c[1]), "+f"(c[2]), "+f"(c[3])
        : "r"(a[0]), "r"(a[1]), "r"(a[2]), "r"(a[3]), "r"(b.x), "r"(b.y));
}

// ---------------- weight prep -----------------------------------------------
__global__ void prep_kernel(const float* __restrict__ We1,
                            const float* __restrict__ Wa1,
                            const float* __restrict__ We2,
                            const float* __restrict__ Wn1,
                            const float* __restrict__ Wn2) {
    int idx = blockIdx.x * blockDim.x + threadIdx.x;
    if (idx < 8192) {                       // WP/WQ: K=64, N=256 (NBT=32)
        int reg = idx & 1, lane = (idx >> 1) & 31, nbt = (idx >> 6) & 31, kk = idx >> 11;
        int g = lane >> 2, t = lane & 3;
        int n = nbt * 8 + g;
        int k0 = kk * 16 + 2 * t + reg * 8;
        const float* W = (n < 128) ? We1 : Wa1;
        int nc = n & 127;
        g_WPf[idx] = pack_h2(W[k0 * 128 + nc], W[(k0 + 1) * 128 + nc]);
        g_WQf[idx] = pack_h2(W[(k0 + 64) * 128 + nc], W[(k0 + 65) * 128 + nc]);
    } else if (idx < 12288) {               // Wc: K=32, N=256 (rows 128..159)
        int i = idx - 8192;
        int reg = i & 1, lane = (i >> 1) & 31, nbt = (i >> 6) & 31, kk = i >> 11;
        int g = lane >> 2, t = lane & 3;
        int n = nbt * 8 + g;
        int k0 = 128 + kk * 16 + 2 * t + reg * 8;
        const float* W = (n < 128) ? We1 : Wa1;
        int nc = n & 127;
        g_Wcf[i] = pack_h2(W[k0 * 128 + nc], W[(k0 + 1) * 128 + nc]);
    } else if (idx < 16384) {               // W2e: K=128, N=64
        int i = idx - 12288;
        int reg = i & 1, lane = (i >> 1) & 31, nbt = (i >> 6) & 7, kk = i >> 9;
        int g = lane >> 2, t = lane & 3;
        int n = nbt * 8 + g;
        int k0 = kk * 16 + 2 * t + reg * 8;
        g_W2f[i] = pack_h2(We2[k0 * 64 + n], We2[(k0 + 1) * 64 + n]);
    } else if (idx < 24576) {               // Wn1: K=128, N=128 (NBT=16)
        int i = idx - 16384;
        int reg = i & 1, lane = (i >> 1) & 31, nbt = (i >> 6) & 15, kk = i >> 10;
        int g = lane >> 2, t = lane & 3;
        int n = nbt * 8 + g;
        int k0 = kk * 16 + 2 * t + reg * 8;
        g_Wn1f[i] = pack_h2(Wn1[k0 * 128 + n], Wn1[(k0 + 1) * 128 + n]);
    } else if (idx < 28672) {               // Wn2: K=128, N=64
        int i = idx - 24576;
        int reg = i & 1, lane = (i >> 1) & 31, nbt = (i >> 6) & 7, kk = i >> 9;
        int g = lane >> 2, t = lane & 3;
        int n = nbt * 8 + g;
        int k0 = kk * 16 + 2 * t + reg * 8;
        g_Wn2f[i] = pack_h2(Wn2[k0 * 64 + n], Wn2[(k0 + 1) * 64 + n]);
    }
}

// ---------------- per-node precompute: P = nf@WP, Q = nf@WQ -----------------
#define PQ_SMEM 18432

__global__ void __launch_bounds__(256, 3)
pq_kernel(const float* __restrict__ nf, int N)
{
    extern __shared__ __align__(16) char dyn[];
    char* sNf = dyn;                              // [128][72] fp16 (stride 144B)

    const int tid = threadIdx.x;
    const int lane = tid & 31, wid = tid >> 5;
    const int g = lane >> 2, t = lane & 3;
    const int n0 = blockIdx.x * 128;

    for (int idx = tid; idx < 128 * 16; idx += 256) {
        int le = idx >> 4, q = idx & 15;
        int n = n0 + le;
        float4 v = make_float4(0.f, 0.f, 0.f, 0.f);
        if (n < N) v = __ldg((const float4*)(nf + (size_t)n * 64) + q);
        *(uint2*)(sNf + le * 144 + q * 8) = make_uint2(pack_h2(v.x, v.y), pack_h2(v.z, v.w));
    }
    __syncthreads();

    const int row0 = wid * 16 + g, row1 = row0 + 8;

    unsigned a[4][4];
#pragma unroll
    for (int kk = 0; kk < 4; kk++) {
        const char* base = sNf + row0 * 144 + kk * 32 + 4 * t;
        a[kk][0] = *(const unsigned*)(base);
        a[kk][1] = *(const unsigned*)(base + 8 * 144);
        a[kk][2] = *(const unsigned*)(base + 16);
        a[kk][3] = *(const unsigned*)(base + 8 * 144 + 16);
    }

#pragma unroll
    for (int tab = 0; tab < 2; tab++) {
        const uint2* Wf = (const uint2*)(tab ? g_WQf : g_WPf);
        unsigned* gOut = tab ? g_Q : g_P;
#pragma unroll
        for (int chunk = 0; chunk < 4; chunk++) {
            float acc[8][4];
#pragma unroll
            for (int nb = 0; nb < 8; nb++)
#pragma unroll
                for (int q = 0; q < 4; q++) acc[nb][q] = 0.f;
#pragma unroll
            for (int kk = 0; kk < 4; kk++)
#pragma unroll
                for (int nb = 0; nb < 8; nb++) {
                    uint2 b = __ldg(Wf + (kk * 32 + chunk * 8 + nb) * 32 + lane);
                    mma_f16(acc[nb], a[kk], b);
                }
#pragma unroll
            for (int nb = 0; nb < 8; nb++) {
                int c = chunk * 64 + nb * 8 + 2 * t;
                if (n0 + row0 < N)
                    gOut[(size_t)(n0 + row0) * 128 + (c >> 1)] = pack_h2(acc[nb][0], acc[nb][1]);
                if (n0 + row1 < N)
                    gOut[(size_t)(n0 + row1) * 128 + (c >> 1)] = pack_h2(acc[nb][2], acc[nb][3]);
            }
        }
    }
}

// ---------------- edge kernel: warp-local gather, 3 CTAs/SM ------------------
#define EDGE_SMEM 67584

__global__ void __launch_bounds__(256, 3)
edge_kernel(const float* __restrict__ ef_,
            const int* __restrict__ src, const int* __restrict__ dst,
            const float* __restrict__ be1, const float* __restrict__ be2,
            const float* __restrict__ ba1, const float* __restrict__ Wa2,
            const float* __restrict__ ba2,
            float* __restrict__ uh_e, int E)
{
    extern __shared__ __align__(16) char dyn[];
    __shared__ int sSrc[128], sDst[128];
    __shared__ float sEx[128];

    const int tid = threadIdx.x;
    const int lane = tid & 31, wid = tid >> 5;
    const int g = lane >> 2, t = lane & 3;
    const int e0 = blockIdx.x * 128;
    const int R = wid * 16;                 // this warp's 16 rows

    const int row0 = R + g, row1 = row0 + 8;
    const int er0 = e0 + row0, er1 = e0 + row1;

    // ef A-fragments first (LDG latency hides under gather issue)
    unsigned aef[2][4];
#pragma unroll
    for (int kk = 0; kk < 2; kk++) {
        int c = kk * 16 + 2 * t;
        if (er0 < E) {
            float2 v0 = *(const float2*)(ef_ + (size_t)er0 * 32 + c);
            float2 v2 = *(const float2*)(ef_ + (size_t)er0 * 32 + c + 8);
            aef[kk][0] = pack_h2(v0.x, v0.y);
            aef[kk][2] = pack_h2(v2.x, v2.y);
        } else aef[kk][0] = aef[kk][2] = 0u;
        if (er1 < E) {
            float2 v1 = *(const float2*)(ef_ + (size_t)er1 * 32 + c);
            float2 v3 = *(const float2*)(ef_ + (size_t)er1 * 32 + c + 8);
            aef[kk][1] = pack_h2(v1.x, v1.y);
            aef[kk][3] = pack_h2(v3.x, v3.y);
        } else aef[kk][1] = aef[kk][3] = 0u;
    }

    // warp-local src/dst indices for rows [R, R+16)
    {
        int e = e0 + R + (lane & 15);
        int v = 0;
        if (lane < 16) { if (e < E) v = src[e]; sSrc[R + lane] = v; }
        else           { if (e < E) v = dst[e]; sDst[R + (lane - 16)] = v; }
    }
    __syncwarp();

    // warp-local S gather: 16 rows x 32 uint4 each
#pragma unroll 4
    for (int i = lane; i < 512; i += 32) {
        int r = R + (i >> 5), q = i & 31;
        uint4 p  = __ldg((const uint4*)g_P + (size_t)sSrc[r] * 32 + q);
        uint4 qv = __ldg((const uint4*)g_Q + (size_t)sDst[r] * 32 + q);
        uint4 s;
        s.x = addh2_f32(p.x, qv.x); s.y = addh2_f32(p.y, qv.y);
        s.z = addh2_f32(p.z, qv.z); s.w = addh2_f32(p.w, qv.w);
        *(uint4*)(dyn + r * 528 + q * 16) = s;
    }
    __syncwarp();   // S rows [R, R+16) ready for this warp

    // ---- Pass E: edge-hidden cols [0,128) in two 64-col halves ----
#pragma unroll
    for (int half = 0; half < 2; half++) {
        float acc[8][4];
#pragma unroll
        for (int nb = 0; nb < 8; nb++)
#pragma unroll
            for (int q = 0; q < 4; q++) acc[nb][q] = 0.f;
#pragma unroll
        for (int kk = 0; kk < 2; kk++)
#pragma unroll
            for (int nb = 0; nb < 8; nb++) {
                uint2 b = __ldg((const uint2*)g_Wcf + (kk * 32 + half * 8 + nb) * 32 + lane);
                mma_f16(acc[nb], aef[kk], b);
            }
#pragma unroll
        for (int nb = 0; nb < 8; nb++) {
            int c = half * 64 + nb * 8 + 2 * t;
            float b0 = __ldg(be1 + c), b1 = __ldg(be1 + c + 1);
            float2 s0 = __half22float2(*(const __half2*)(dyn + row0 * 528 + c * 2));
            float2 s1 = __half22float2(*(const __half2*)(dyn + row1 * 528 + c * 2));
            *(unsigned*)(dyn + row0 * 528 + c * 2) =
                pack_h2(fmaxf(acc[nb][0] + s0.x + b0, 0.f), fmaxf(acc[nb][1] + s0.y + b1, 0.f));
            *(unsigned*)(dyn + row1 * 528 + c * 2) =
                pack_h2(fmaxf(acc[nb][2] + s1.x + b0, 0.f), fmaxf(acc[nb][3] + s1.y + b1, 0.f));
        }
    }

    // ---- Pass A: attn cols [128,256); logits -> ex (no segment-max) ----
    float l0 = 0.f, l1 = 0.f;
#pragma unroll
    for (int half = 0; half < 2; half++) {
        float acc[8][4];
#pragma unroll
        for (int nb = 0; nb < 8; nb++)
#pragma unroll
            for (int q = 0; q < 4; q++) acc[nb][q] = 0.f;
#pragma unroll
        for (int kk = 0; kk < 2; kk++)
#pragma unroll
            for (int nb = 0; nb < 8; nb++) {
                uint2 b = __ldg((const uint2*)g_Wcf + (kk * 32 + 16 + half * 8 + nb) * 32 + lane);
                mma_f16(acc[nb], aef[kk], b);
            }
#pragma unroll
        for (int nb = 0; nb < 8; nb++) {
            int c = half * 64 + nb * 8 + 2 * t;
            int off = (128 + c) * 2;
            float b0 = __ldg(ba1 + c), b1 = __ldg(ba1 + c + 1);
            float w0 = __ldg(Wa2 + c), w1 = __ldg(Wa2 + c + 1);
            float2 s0 = __half22float2(*(const __half2*)(dyn + row0 * 528 + off));
            float2 s1 = __half22float2(*(const __half2*)(dyn + row1 * 528 + off));
            l0 += fmaxf(acc[nb][0] + s0.x + b0, 0.f) * w0 + fmaxf(acc[nb][1] + s0.y + b1, 0.f) * w1;
            l1 += fmaxf(acc[nb][2] + s1.x + b0, 0.f) * w0 + fmaxf(acc[nb][3] + s1.y + b1, 0.f) * w1;
        }
    }
#pragma unroll
    for (int off = 1; off <= 2; off <<= 1) {
        l0 += __shfl_xor_sync(0xffffffffu, l0, off);
        l1 += __shfl_xor_sync(0xffffffffu, l1, off);
    }
    if (t == 0) {
        float b2 = __ldg(ba2);
        float ex0 = expf(l0 + b2), ex1 = expf(l1 + b2);
        sEx[row0] = ex0;
        sEx[row1] = ex1;
        if (er0 < E)
            asm volatile("red.global.add.f32 [%0], %1;" :: "l"(g_denom + sDst[row0]), "f"(ex0) : "memory");
        if (er1 < E)
            asm volatile("red.global.add.f32 [%0], %1;" :: "l"(g_denom + sDst[row1]), "f"(ex1) : "memory");
    }
    __syncthreads();   // hidden + sEx + sSrc/sDst visible across warps

    // ---- GEMM2: H[128x128] x W2[128x64] -> uh_e + numerator reds ----
    {
        const int warp_m = wid & 3, warp_n = wid >> 2;
        float accO[2][4][4];
#pragma unroll
        for (int mt = 0; mt < 2; mt++)
#pragma unroll
            for (int nb = 0; nb < 4; nb++)
#pragma unroll
                for (int q = 0; q < 4; q++) accO[mt][nb][q] = 0.f;
        unsigned a[2][4];
#pragma unroll
        for (int kk = 0; kk < 8; kk++) {
#pragma unroll
            for (int mt = 0; mt < 2; mt++) {
                int row = warp_m * 32 + mt * 16 + g;
                const char* base = dyn + row * 528 + kk * 32 + 4 * t;
                a[mt][0] = *(const unsigned*)(base);
                a[mt][1] = *(const unsigned*)(base + 8 * 528);
                a[mt][2] = *(const unsigned*)(base + 16);
                a[mt][3] = *(const unsigned*)(base + 8 * 528 + 16);
            }
#pragma unroll
            for (int nb = 0; nb < 4; nb++) {
                uint2 b = __ldg((const uint2*)g_W2f + (kk * 8 + warp_n * 4 + nb) * 32 + lane);
                mma_f16(accO[0][nb], a[0], b);
                mma_f16(accO[1][nb], a[1], b);
            }
        }
#pragma unroll
        for (int mt = 0; mt < 2; mt++) {
            int r0 = warp_m * 32 + mt * 16 + g;
            int r1 = r0 + 8;
            float ex0 = sEx[r0], ex1 = sEx[r1];
            int d0 = sDst[r0], d1 = sDst[r1];
#pragma unroll
            for (int nb = 0; nb < 4; nb++) {
                int c = warp_n * 32 + nb * 8 + 2 * t;
                float b0 = __ldg(be2 + c), b1 = __ldg(be2 + c + 1);
                int e = e0 + r0;
                float o0 = accO[mt][nb][0] + b0, o1 = accO[mt][nb][1] + b1;
                float o2 = accO[mt][nb][2] + b0, o3 = accO[mt][nb][3] + b1;
                if (e < E) {
                    *(float2*)(uh_e + (size_t)e * 64 + c) = make_float2(o0, o1);
                    asm volatile("red.global.add.v2.f32 [%0], {%1,%2};"
                                 :: "l"(g_agg + (size_t)d0 * 64 + c),
                                    "f"(o0 * ex0), "f"(o1 * ex0) : "memory");
                }
                if (e0 + r1 < E) {
                    *(float2*)(uh_e + (size_t)(e0 + r1) * 64 + c) = make_float2(o2, o3);
                    asm volatile("red.global.add.v2.f32 [%0], {%1,%2};"
                                 :: "l"(g_agg + (size_t)d1 * 64 + c),
                                    "f"(o2 * ex1), "f"(o3 * ex1) : "memory");
                }
            }
        }
    }
}

// ---------------- node kernel: fp16 HMMA, 2 CTAs/SM --------------------------
#define oNi  0          // in/hidden tile [128][136]h, stride 272 (34816 B)
#define oNW1 34816      // Wn1 frags 32 KB
#define oNW2 67584      // Wn2 frags 16 KB
#define NODE_SMEM 83968

__global__ void __launch_bounds__(256, 2)
node_kernel(const float* __restrict__ nf,
            const float* __restrict__ bn1, const float* __restrict__ bn2,
            float* __restrict__ uh_n, int N)
{
    extern __shared__ __align__(16) char dyn[];

    const int tid = threadIdx.x;
    const int lane = tid & 31, wid = tid >> 5;
    const int g = lane >> 2, t = lane & 3;
    const int warp_m = wid & 3, warp_n = wid >> 2;
    const int n0 = blockIdx.x * 128;

    for (int i = tid; i < 2048; i += 256) ((uint4*)(dyn + oNW1))[i] = ((const uint4*)g_Wn1f)[i];
    for (int i = tid; i < 1024; i += 256) ((uint4*)(dyn + oNW2))[i] = ((const uint4*)g_Wn2f)[i];
    // gather in = [agg_num/denom | nf] -> fp16
    for (int idx = tid; idx < 4096; idx += 256) {
        int le = idx >> 5, q = idx & 31;
        int n = n0 + le;
        float4 v = make_float4(0.f, 0.f, 0.f, 0.f);
        if (n < N) {
            if (q < 16) {
                v = __ldg((const float4*)(g_agg + (size_t)n * 64) + q);
                float inv = 1.f / fmaxf(g_denom[n], 1e-38f);
                v.x *= inv; v.y *= inv; v.z *= inv; v.w *= inv;
            } else {
                v = __ldg((const float4*)(nf + (size_t)n * 64) + (q - 16));
            }
        }
        *(uint2*)(dyn + oNi + le * 272 + q * 8) = make_uint2(pack_h2(v.x, v.y), pack_h2(v.z, v.w));
    }
    __syncthreads();

    float acc[2][8][4];
#pragma unroll
    for (int mt = 0; mt < 2; mt++)
#pragma unroll
        for (int nb = 0; nb < 8; nb++)
#pragma unroll
            for (int q = 0; q < 4; q++) acc[mt][nb][q] = 0.f;
    {
        unsigned a[2][4];
        const uint2* sWu = (const uint2*)(dyn + oNW1);
#pragma unroll
        for (int kk = 0; kk < 8; kk++) {
#pragma unroll
            for (int mt = 0; mt < 2; mt++) {
                int row = warp_m * 32 + mt * 16 + g;
                const char* base = dyn + oNi + row * 272 + kk * 32 + 4 * t;
                a[mt][0] = *(const unsigned*)(base);
                a[mt][1] = *(const unsigned*)(base + 8 * 272);
                a[mt][2] = *(const unsigned*)(base + 16);
                a[mt][3] = *(const unsigned*)(base + 8 * 272 + 16);
            }
#pragma unroll
            for (int nb = 0; nb < 8; nb++) {
                uint2 b = sWu[(kk * 16 + warp_n * 8 + nb) * 32 + lane];
                mma_f16(acc[0][nb], a[0], b);
                mma_f16(acc[1][nb], a[1], b);
            }
        }
    }
    __syncthreads();

#pragma unroll
    for (int mt = 0; mt < 2; mt++)
#pragma unroll
        for (int nb = 0; nb < 8; nb++) {
            int c = warp_n * 64 + nb * 8 + 2 * t;
            float b0 = __ldg(bn1 + c), b1 = __ldg(bn1 + c + 1);
            int r0 = warp_m * 32 + mt * 16 + g;
            *(unsigned*)(dyn + oNi + r0 * 272 + c * 2) =
                pack_h2(fmaxf(acc[mt][nb][0] + b0, 0.f), fmaxf(acc[mt][nb][1] + b1, 0.f));
            *(unsigned*)(dyn + oNi + (r0 + 8) * 272 + c * 2) =
                pack_h2(fmaxf(acc[mt][nb][2] + b0, 0.f), fmaxf(acc[mt][nb][3] + b1, 0.f));
        }
    __syncthreads();

    {
        float accO[2][4][4];
#pragma unroll
        for (int mt = 0; mt < 2; mt++)
#pragma unroll
            for (int nb = 0; nb < 4; nb++)
#pragma unroll
                for (int q = 0; q < 4; q++) accO[mt][nb][q] = 0.f;
        unsigned a[2][4];
        const uint2* sWu = (const uint2*)(dyn + oNW2);
#pragma unroll
        for (int kk = 0; kk < 8; kk++) {
#pragma unroll
            for (int mt = 0; mt < 2; mt++) {
                int row = warp_m * 32 + mt * 16 + g;
                const char* base = dyn + oNi + row * 272 + kk * 32 + 4 * t;
                a[mt][0] = *(const unsigned*)(base);
                a[mt][1] = *(const unsigned*)(base + 8 * 272);
                a[mt][2] = *(const unsigned*)(base + 16);
                a[mt][3] = *(const unsigned*)(base + 8 * 272 + 16);
            }
#pragma unroll
            for (int nb = 0; nb < 4; nb++) {
                uint2 b = sWu[(kk * 8 + warp_n * 4 + nb) * 32 + lane];
                mma_f16(accO[0][nb], a[0], b);
                mma_f16(accO[1][nb], a[1], b);
            }
        }
#pragma unroll
        for (int mt = 0; mt < 2; mt++)
#pragma unroll
            for (int nb = 0; nb < 4; nb++) {
                int c = warp_n * 32 + nb * 8 + 2 * t;
                float b0 = __ldg(bn2 + c), b1 = __ldg(bn2 + c + 1);
                int r0 = warp_m * 32 + mt * 16 + g;
                int n = n0 + r0;
                if (n < N)
                    *(float2*)(uh_n + (size_t)n * 64 + c) =
                        make_float2(accO[mt][nb][0] + b0, accO[mt][nb][1] + b1);
                if (n + 8 < N)
                    *(float2*)(uh_n + (size_t)(n + 8) * 64 + c) =
                        make_float2(accO[mt][nb][2] + b0, accO[mt][nb][3] + b1);
            }
    }
}

// ---------------- init ------------------------------------------------------
__global__ void init_kernel(int N) {
    int t = blockIdx.x * blockDim.x + threadIdx.x;
    if (t < N * 16) ((float4*)g_agg)[t] = make_float4(0.f, 0.f, 0.f, 0.f);
    if (t < N) g_denom[t] = 0.f;
}

// ---------------- launch -----------------------------------------------------
extern "C" void kernel_launch(void* const* d_in, const int* in_sizes, int n_in,
                              void* d_out, int out_size)
{
    const float* nf  = (const float*)d_in[0];
    const float* ef  = (const float*)d_in[1];
    const int*   src = (const int*)d_in[2];
    const int*   dst = (const int*)d_in[3];
    const float* We1 = (const float*)d_in[4];
    const float* be1 = (const float*)d_in[5];
    const float* We2 = (const float*)d_in[6];
    const float* be2 = (const float*)d_in[7];
    const float* Wa1 = (const float*)d_in[8];
    const float* ba1 = (const float*)d_in[9];
    const float* Wa2 = (const float*)d_in[10];
    const float* ba2 = (const float*)d_in[11];
    const float* Wn1 = (const float*)d_in[12];
    const float* bn1 = (const float*)d_in[13];
    const float* Wn2 = (const float*)d_in[14];
    const float* bn2 = (const float*)d_in[15];

    const int N = in_sizes[0] / 64;
    const int E = in_sizes[2];

    float* uh_n = (float*)d_out;
    float* uh_e = uh_n + (size_t)N * 64;

    cudaFuncSetAttribute(pq_kernel,   cudaFuncAttributeMaxDynamicSharedMemorySize, PQ_SMEM);
    cudaFuncSetAttribute(edge_kernel, cudaFuncAttributeMaxDynamicSharedMemorySize, EDGE_SMEM);
    cudaFuncSetAttribute(node_kernel, cudaFuncAttributeMaxDynamicSharedMemorySize, NODE_SMEM);

    prep_kernel<<<(28672 + 255) / 256, 256>>>(We1, Wa1, We2, Wn1, Wn2);
    init_kernel<<<(N * 16 + 255) / 256, 256>>>(N);
    pq_kernel<<<(N + 127) / 128, 256, PQ_SMEM>>>(nf, N);
    edge_kernel<<<(E + 127) / 128, 256, EDGE_SMEM>>>(
        ef, src, dst, be1, be2, ba1, Wa2, ba2, uh_e, E);
    node_kernel<<<(N + 127) / 128, 256, NODE_SMEM>>>(nf, bn1, bn2, uh_n, N);
}